// round 9
// baseline (speedup 1.0000x reference)
#include <cuda_runtime.h>
#include <math.h>
#include <stdint.h>

#define BB   8
#define NCELL 1024
#define SLEN 1025
#define D    256
#define NH   8
#define HD   32
#define DFF  1024
#define NL   4
#define MTOK (BB*SLEN)   // 8200

// ---------------- scratch (static device globals; no allocs) ----------------
__device__ float g_x[MTOK*D];
__device__ float g_q[MTOK*D];
__device__ float g_k[MTOK*D];
__device__ float g_v[MTOK*D];
__device__ float g_a[MTOK*D];
__device__ float g_t[MTOK*D];
__device__ float g_h[(size_t)MTOK*DFF];

// cp.async helper: 16B global->shared, zero-fill when sz==0
#define CPA16(dst, src, sz) \
    asm volatile("cp.async.cg.shared.global [%0], [%1], 16, %2;" \
        :: "r"((uint32_t)__cvta_generic_to_shared(dst)), "l"(src), "r"(sz))

// ---------------- embedding: emb + cell-type MLP + positional + cls ----------
__global__ void embed_kernel(const float* __restrict__ cf,
                             const int* __restrict__ xc,
                             const int* __restrict__ yc,
                             const float* __restrict__ Wemb,
                             const float* __restrict__ bemb,
                             const float* __restrict__ Wct1,
                             const float* __restrict__ bct1,
                             const float* __restrict__ Wct2,
                             const float* __restrict__ bct2,
                             const float* __restrict__ cls)
{
    int blk = blockIdx.x;          // 0..8199
    int b = blk / SLEN;
    int s = blk % SLEN;
    int d = threadIdx.x;           // 0..255
    float* out = g_x + (size_t)blk * D;

    if (s == 0) { out[d] = cls[d]; return; }
    int n = s - 1;

    __shared__ float cfs[64];
    __shared__ float hs[128];
    const float* cfp = cf + ((size_t)b*NCELL + n)*64;
    if (d < 64) cfs[d] = cfp[d];
    __syncthreads();

    if (d < 128) {
        float acc = bct1[d];
        #pragma unroll
        for (int k = 0; k < 64; k++) acc = fmaf(cfs[k], Wct1[k*128 + d], acc);
        hs[d] = fmaxf(acc, 0.f);
    }
    __syncthreads();

    float e = bemb[d];
    #pragma unroll
    for (int k = 0; k < 64; k++) e = fmaf(cfs[k], Wemb[k*256 + d], e);
    float c2 = bct2[d];
    #pragma unroll
    for (int j = 0; j < 128; j++) c2 = fmaf(hs[j], Wct2[j*256 + d], c2);

    // positional encoding (match jax: div = exp(2m * (-ln(10000)/128)))
    int dd    = (d < 128) ? d : d - 128;
    int coord = (d < 128) ? xc[b*NCELL + n] : yc[b*NCELL + n];
    coord = min(max(coord, 0), 999);
    int m = dd >> 1;
    const float c1 = -0.07195578739046225f;  // float(-ln(10000)/128)
    float dv  = expf((float)(2*m) * c1);
    float ang = (float)coord * dv;
    float p   = (dd & 1) ? cosf(ang) : sinf(ang);

    out[d] = e + c2 + p;
}

// ---- SGEMM body: C = A(MxK) @ W(KxN) + bias [ReLU]; BM=128 BN=64 BK=16 ------
// 256 threads, 8x4 microtile (32 accs -> ~76 regs -> 2 CTAs/SM), double buffer.
__device__ __forceinline__
void gemm_body(const float* __restrict__ A,
               const float* __restrict__ W,
               const float* __restrict__ bias,
               float* __restrict__ C,
               int M, int N, int K, int relu,
               int bx, int by)
{
    __shared__ float As[2][16][132];   // [buf][k][m] transposed, padded
    __shared__ float Bs[2][16][64];    // [buf][k][n]

    int tid = threadIdx.x;
    int m0 = bx * 128;
    int n0 = by * 64;
    int ar = (tid >> 4) << 3;      // 0..120
    int bc = (tid & 15) << 2;      // 0..60

    // load mapping: A 128x16 = 512 float4, 2 per thread
    int arow = tid >> 2;           // 0..63 (and +64)
    int akc  = (tid & 3) << 2;     // 0,4,8,12
    // B 16x64 = 256 float4, 1 per thread
    int bkr = tid >> 4;            // 0..15
    int bnc = (tid & 15) << 2;     // 0..60

    bool av0 = (m0 + arow)      < M;
    bool av1 = (m0 + arow + 64) < M;
    const float* Ap0 = A + (size_t)(m0 + arow)      * K + akc;
    const float* Ap1 = A + (size_t)(m0 + arow + 64) * K + akc;
    const float* Bp  = W + (size_t)bkr * N + n0 + bnc;

    float acc[8][4] = {};

    // prologue: tile 0 -> buffer 0
    {
        float4 a0 = av0 ? *(const float4*)Ap0 : make_float4(0.f,0.f,0.f,0.f);
        float4 a1 = av1 ? *(const float4*)Ap1 : make_float4(0.f,0.f,0.f,0.f);
        float4 b0 = *(const float4*)Bp;
        As[0][akc+0][arow] = a0.x; As[0][akc+1][arow] = a0.y;
        As[0][akc+2][arow] = a0.z; As[0][akc+3][arow] = a0.w;
        As[0][akc+0][arow+64] = a1.x; As[0][akc+1][arow+64] = a1.y;
        As[0][akc+2][arow+64] = a1.z; As[0][akc+3][arow+64] = a1.w;
        *(float4*)&Bs[0][bkr][bnc] = b0;
    }
    __syncthreads();

    int KT = K >> 4;
    for (int kt = 0; kt < KT; kt++) {
        int cur = kt & 1;
        float4 pa0, pa1, pb0;
        bool more = (kt + 1 < KT);
        if (more) {
            int k0 = (kt + 1) << 4;
            pa0 = av0 ? *(const float4*)(Ap0 + k0) : make_float4(0.f,0.f,0.f,0.f);
            pa1 = av1 ? *(const float4*)(Ap1 + k0) : make_float4(0.f,0.f,0.f,0.f);
            pb0 = *(const float4*)(Bp + (size_t)k0 * N);
        }

        #pragma unroll
        for (int kk = 0; kk < 16; kk++) {
            float a[8], b[4];
            *(float4*)&a[0] = *(float4*)&As[cur][kk][ar];
            *(float4*)&a[4] = *(float4*)&As[cur][kk][ar+4];
            *(float4*)&b[0] = *(float4*)&Bs[cur][kk][bc];
            #pragma unroll
            for (int r = 0; r < 8; r++) {
                #pragma unroll
                for (int c = 0; c < 4; c++)
                    acc[r][c] = fmaf(a[r], b[c], acc[r][c]);
            }
        }

        if (more) {
            int nxt = cur ^ 1;
            As[nxt][akc+0][arow] = pa0.x; As[nxt][akc+1][arow] = pa0.y;
            As[nxt][akc+2][arow] = pa0.z; As[nxt][akc+3][arow] = pa0.w;
            As[nxt][akc+0][arow+64] = pa1.x; As[nxt][akc+1][arow+64] = pa1.y;
            As[nxt][akc+2][arow+64] = pa1.z; As[nxt][akc+3][arow+64] = pa1.w;
            *(float4*)&Bs[nxt][bkr][bnc] = pb0;
            __syncthreads();
        }
    }

    float4 bb4 = *(const float4*)(bias + n0 + bc);
    float bb[4] = {bb4.x, bb4.y, bb4.z, bb4.w};
    #pragma unroll
    for (int r = 0; r < 8; r++) {
        int gr = m0 + ar + r;
        if (gr < M) {
            float4 o;
            o.x = acc[r][0] + bb[0]; o.y = acc[r][1] + bb[1];
            o.z = acc[r][2] + bb[2]; o.w = acc[r][3] + bb[3];
            if (relu) {
                o.x = fmaxf(o.x, 0.f); o.y = fmaxf(o.y, 0.f);
                o.z = fmaxf(o.z, 0.f); o.w = fmaxf(o.w, 0.f);
            }
            *(float4*)(C + (size_t)gr*N + n0 + bc) = o;
        }
    }
}

__global__ __launch_bounds__(256, 2)
void gemm_kernel(const float* __restrict__ A,
                 const float* __restrict__ W,
                 const float* __restrict__ bias,
                 float* __restrict__ C,
                 int M, int N, int K, int relu)
{
    gemm_body(A, W, bias, C, M, N, K, relu, blockIdx.x, blockIdx.y);
}

// fused QKV: grid.z in {0,1,2} selects weights/bias/output
__global__ __launch_bounds__(256, 2)
void qkv_kernel(const float* __restrict__ A,
                const float* __restrict__ Wq,
                const float* __restrict__ Wk,
                const float* __restrict__ Wv,
                const float* __restrict__ bq,
                const float* __restrict__ bk,
                const float* __restrict__ bv,
                float* __restrict__ Q,
                float* __restrict__ Ko,
                float* __restrict__ V)
{
    int z = blockIdx.z;
    const float* W = (z == 0) ? Wq : (z == 1) ? Wk : Wv;
    const float* b = (z == 0) ? bq : (z == 1) ? bk : bv;
    float* C       = (z == 0) ? Q  : (z == 1) ? Ko : V;
    gemm_body(A, W, b, C, MTOK, D, D, 0, blockIdx.x, blockIdx.y);
}

// ------- flash attention: 512 threads, 1 q-row/thread, cp.async dbuf ---------
__device__ __forceinline__ void attn_issue_tile(
    const float* kbase, const float* vbase,
    float (*ks)[64][36], float (*vs)[64][36],
    int buf, int t, int row0, int c4)
{
    int gk = t * 64 + row0;
    int sz = (gk < SLEN) ? 16 : 0;
    int ck = min(gk, SLEN-1);
    CPA16(&ks[buf][row0][c4], kbase + (size_t)ck*D + c4, sz);
    CPA16(&vs[buf][row0][c4], vbase + (size_t)ck*D + c4, sz);
    asm volatile("cp.async.commit_group;");
}

__global__ __launch_bounds__(512, 1) void attn_kernel()
{
    __shared__ float ks[2][64][36];
    __shared__ float vs[2][64][36];

    int qt = blockIdx.x;           // 0..8
    int h  = blockIdx.y;
    int b  = blockIdx.z;
    int tid = threadIdx.x;         // 0..511
    int rl  = tid >> 2;            // 0..127
    int sub = tid & 3;
    int qrow = qt*128 + rl;
    bool valid = qrow < SLEN;

    int row0 = tid >> 3;           // 0..63 (load mapping, 1 float4/thread)
    int c4   = (tid & 7) << 2;

    const float scale = 0.17677669529663687f;   // 1/sqrt(32)
    const float* qbase = g_q + (size_t)b*SLEN*D + h*HD;
    const float* kbase = g_k + (size_t)b*SLEN*D + h*HD;
    const float* vbase = g_v + (size_t)b*SLEN*D + h*HD;

    float q[HD];
    #pragma unroll
    for (int d4 = 0; d4 < 8; d4++) {
        float4 t0 = make_float4(0.f,0.f,0.f,0.f);
        if (valid) t0 = *(const float4*)(qbase + (size_t)qrow*D + d4*4);
        q[d4*4+0] = t0.x*scale; q[d4*4+1] = t0.y*scale;
        q[d4*4+2] = t0.z*scale; q[d4*4+3] = t0.w*scale;
    }

    float m = -INFINITY, l = 0.f;
    float acc[HD];
    #pragma unroll
    for (int d = 0; d < HD; d++) acc[d] = 0.f;

    const int ntiles = (SLEN + 63) / 64;   // 17

    attn_issue_tile(kbase, vbase, ks, vs, 0, 0, row0, c4);

    for (int t = 0; t < ntiles; t++) {
        int cur = t & 1;
        int k0 = t*64;
        if (t + 1 < ntiles) {
            attn_issue_tile(kbase, vbase, ks, vs, cur ^ 1, t + 1, row0, c4);
            asm volatile("cp.async.wait_group 1;");
        } else {
            asm volatile("cp.async.wait_group 0;");
        }
        __syncthreads();

        float p[16];
        float tmax = -INFINITY;
        #pragma unroll
        for (int j = 0; j < 16; j++) {
            int cl = 4*j + sub;            // interleaved column assignment
            float s;
            if (k0 + cl < SLEN) {
                s = 0.f;
                #pragma unroll
                for (int d4 = 0; d4 < 8; d4++) {
                    float4 kv = *(const float4*)&ks[cur][cl][d4*4];
                    s = fmaf(q[d4*4+0], kv.x, s);
                    s = fmaf(q[d4*4+1], kv.y, s);
                    s = fmaf(q[d4*4+2], kv.z, s);
                    s = fmaf(q[d4*4+3], kv.w, s);
                }
            } else s = -INFINITY;
            p[j] = s;
            tmax = fmaxf(tmax, s);
        }
        tmax = fmaxf(tmax, __shfl_xor_sync(0xffffffffu, tmax, 1));
        tmax = fmaxf(tmax, __shfl_xor_sync(0xffffffffu, tmax, 2));

        float mn = fmaxf(m, tmax);
        float cr = __expf(m - mn);
        l *= cr;
        #pragma unroll
        for (int d = 0; d < HD; d++) acc[d] *= cr;

        float ls = 0.f;
        #pragma unroll
        for (int j = 0; j < 16; j++) {
            p[j] = __expf(p[j] - mn); ls += p[j];
        }
        l += ls;

        #pragma unroll
        for (int j = 0; j < 16; j++) {
            int cl = 4*j + sub;
            float pj = p[j];
            #pragma unroll
            for (int d4 = 0; d4 < 8; d4++) {
                float4 vv = *(const float4*)&vs[cur][cl][d4*4];
                acc[d4*4+0] = fmaf(pj, vv.x, acc[d4*4+0]);
                acc[d4*4+1] = fmaf(pj, vv.y, acc[d4*4+1]);
                acc[d4*4+2] = fmaf(pj, vv.z, acc[d4*4+2]);
                acc[d4*4+3] = fmaf(pj, vv.w, acc[d4*4+3]);
            }
        }
        m = mn;
        __syncthreads();   // all reads of 'cur' done before t+1 re-issues into it
    }

    // reduce across the 4 sub-threads of each row
    l += __shfl_xor_sync(0xffffffffu, l, 1);
    l += __shfl_xor_sync(0xffffffffu, l, 2);
    #pragma unroll
    for (int d = 0; d < HD; d++) {
        acc[d] += __shfl_xor_sync(0xffffffffu, acc[d], 1);
        acc[d] += __shfl_xor_sync(0xffffffffu, acc[d], 2);
    }

    if (sub == 0 && valid) {
        float inv = 1.f / l;
        float* op = g_a + ((size_t)b*SLEN + qrow)*D + h*HD;
        #pragma unroll
        for (int d4 = 0; d4 < 8; d4++) {
            float4 o;
            o.x = acc[d4*4+0]*inv; o.y = acc[d4*4+1]*inv;
            o.z = acc[d4*4+2]*inv; o.w = acc[d4*4+3]*inv;
            *(float4*)(op + d4*4) = o;
        }
    }
}

// ---------- fused residual + LayerNorm, warp-per-row (8 rows/block) ----------
__global__ void ln_kernel(const float* __restrict__ A,
                          const float* __restrict__ Bsrc,
                          const float* __restrict__ g,
                          const float* __restrict__ bta,
                          float* __restrict__ out)
{
    int warp = threadIdx.x >> 5;
    int lane = threadIdx.x & 31;
    int row = blockIdx.x * 8 + warp;
    size_t base = (size_t)row * D;

    const float4* ap = (const float4*)(A + base);
    const float4* bp = (const float4*)(Bsrc + base);
    float4 a0 = ap[lane], a1 = ap[lane + 32];
    float4 b0 = bp[lane], b1 = bp[lane + 32];
    float v[8];
    v[0]=a0.x+b0.x; v[1]=a0.y+b0.y; v[2]=a0.z+b0.z; v[3]=a0.w+b0.w;
    v[4]=a1.x+b1.x; v[5]=a1.y+b1.y; v[6]=a1.z+b1.z; v[7]=a1.w+b1.w;

    float s = 0.f, s2 = 0.f;
    #pragma unroll
    for (int i = 0; i < 8; i++) { s += v[i]; s2 = fmaf(v[i], v[i], s2); }
    #pragma unroll
    for (int o = 16; o > 0; o >>= 1) {
        s  += __shfl_xor_sync(0xffffffffu, s,  o);
        s2 += __shfl_xor_sync(0xffffffffu, s2, o);
    }
    float mu = s * (1.f/256.f);
    float var = s2 * (1.f/256.f) - mu*mu;
    float rstd = rsqrtf(var + 1e-5f);

    const float4* gp = (const float4*)g;
    const float4* tp = (const float4*)bta;
    float4 g0 = gp[lane], g1 = gp[lane+32];
    float4 t0 = tp[lane], t1 = tp[lane+32];
    float4 o0, o1;
    o0.x = (v[0]-mu)*rstd*g0.x + t0.x;
    o0.y = (v[1]-mu)*rstd*g0.y + t0.y;
    o0.z = (v[2]-mu)*rstd*g0.z + t0.z;
    o0.w = (v[3]-mu)*rstd*g0.w + t0.w;
    o1.x = (v[4]-mu)*rstd*g1.x + t1.x;
    o1.y = (v[5]-mu)*rstd*g1.y + t1.y;
    o1.z = (v[6]-mu)*rstd*g1.z + t1.z;
    o1.w = (v[7]-mu)*rstd*g1.w + t1.w;
    float4* op = (float4*)(out + base);
    op[lane]      = o0;
    op[lane + 32] = o1;
}

// ---------------- final: LN cls row only + 2-layer head ----------------------
__global__ void head_kernel(const float* __restrict__ g,
                            const float* __restrict__ bta,
                            const float* __restrict__ Wh1,
                            const float* __restrict__ bh1,
                            const float* __restrict__ Wh2,
                            const float* __restrict__ bh2,
                            float* __restrict__ out)
{
    int b = blockIdx.x;
    int d = threadIdx.x;
    float v = g_x[(size_t)b*SLEN*D + d];

    float s = v, s2 = v*v;
    #pragma unroll
    for (int o = 16; o > 0; o >>= 1) {
        s  += __shfl_xor_sync(0xffffffffu, s,  o);
        s2 += __shfl_xor_sync(0xffffffffu, s2, o);
    }
    __shared__ float ws[8], ws2[8];
    __shared__ float mu_s, rstd_s;
    int w = d >> 5;
    if ((d & 31) == 0) { ws[w] = s; ws2[w] = s2; }
    __syncthreads();
    if (d == 0) {
        float S1 = 0.f, S2 = 0.f;
        #pragma unroll
        for (int i = 0; i < 8; i++) { S1 += ws[i]; S2 += ws2[i]; }
        float mu = S1 * (1.f/256.f);
        float var = S2 * (1.f/256.f) - mu*mu;
        mu_s = mu;
        rstd_s = rsqrtf(var + 1e-5f);
    }
    __syncthreads();

    __shared__ float clsr[256];
    __shared__ float hid[256];
    float c = (v - mu_s) * rstd_s * g[d] + bta[d];
    clsr[d] = c;
    out[b*D + d] = c;                       // cls_out
    __syncthreads();

    float hsum = bh1[d];
    #pragma unroll 8
    for (int k = 0; k < 256; k++) hsum = fmaf(clsr[k], Wh1[k*256 + d], hsum);
    hid[d] = fmaxf(hsum, 0.f);
    __syncthreads();

    if (d < 2) {
        float lg = bh2[d];
        for (int k = 0; k < 256; k++) lg = fmaf(hid[k], Wh2[k*2 + d], lg);
        out[BB*D + b*2 + d] = lg;           // logits after cls_out block
    }
}

// ---------------- launcher ---------------------------------------------------
extern "C" void kernel_launch(void* const* d_in, const int* in_sizes, int n_in,
                              void* d_out, int out_size)
{
    (void)in_sizes; (void)n_in; (void)out_size;

    const float* cf   = (const float*)d_in[0];
    const int*   xc   = (const int*)  d_in[1];
    const int*   yc   = (const int*)  d_in[2];
    const float* Wemb = (const float*)d_in[3];
    const float* bemb = (const float*)d_in[4];
    const float* Wct1 = (const float*)d_in[5];
    const float* bct1 = (const float*)d_in[6];
    const float* Wct2 = (const float*)d_in[7];
    const float* bct2 = (const float*)d_in[8];
    const float* cls  = (const float*)d_in[9];
    const float* Wq = (const float*)d_in[10]; const float* bq = (const float*)d_in[11];
    const float* Wk = (const float*)d_in[12]; const float* bk = (const float*)d_in[13];
    const float* Wv = (const float*)d_in[14]; const float* bv = (const float*)d_in[15];
    const float* Wo = (const float*)d_in[16]; const float* bo = (const float*)d_in[17];
    const float* ln1g = (const float*)d_in[18]; const float* ln1b = (const float*)d_in[19];
    const float* ln2g = (const float*)d_in[20]; const float* ln2b = (const float*)d_in[21];
    const float* Wf1 = (const float*)d_in[22]; const float* bf1 = (const float*)d_in[23];
    const float* Wf2 = (const float*)d_in[24]; const float* bf2 = (const float*)d_in[25];
    const float* lnfg = (const float*)d_in[26]; const float* lnfb = (const float*)d_in[27];
    const float* Wh1 = (const float*)d_in[28]; const float* bh1 = (const float*)d_in[29];
    const float* Wh2 = (const float*)d_in[30]; const float* bh2 = (const float*)d_in[31];
    float* out = (float*)d_out;

    void* p;
    cudaGetSymbolAddress(&p, g_x); float* xb = (float*)p;
    cudaGetSymbolAddress(&p, g_q); float* qb = (float*)p;
    cudaGetSymbolAddress(&p, g_k); float* kb = (float*)p;
    cudaGetSymbolAddress(&p, g_v); float* vb = (float*)p;
    cudaGetSymbolAddress(&p, g_a); float* ab = (float*)p;
    cudaGetSymbolAddress(&p, g_t); float* tb = (float*)p;
    cudaGetSymbolAddress(&p, g_h); float* hb = (float*)p;

    embed_kernel<<<MTOK, 256>>>(cf, xc, yc, Wemb, bemb, Wct1, bct1, Wct2, bct2, cls);

    dim3 gqkv((MTOK + 127)/128, D/64, 3);  // 65 x 4 x 3
    dim3 g256((MTOK + 127)/128, D/64);     // 65 x 4
    dim3 gff ((MTOK + 127)/128, DFF/64);   // 65 x 16
    dim3 gattn((SLEN + 127)/128, NH, BB);  // 9 x 8 x 8
    int lngrid = MTOK / 8;                 // 1025

    for (int l = 0; l < NL; l++) {
        size_t wo = (size_t)l*D*D;
        qkv_kernel<<<gqkv, 256>>>(xb, Wq + wo, Wk + wo, Wv + wo,
                                  bq + l*D, bk + l*D, bv + l*D, qb, kb, vb);
        attn_kernel<<<gattn, 512>>>();
        gemm_kernel<<<g256, 256>>>(ab, Wo + wo, bo + l*D, tb, MTOK, D, D, 0);
        ln_kernel<<<lngrid, 256>>>(xb, tb, ln1g + l*D, ln1b + l*D, xb);
        gemm_kernel<<<gff, 256>>>(xb, Wf1 + (size_t)l*D*DFF, bf1 + l*DFF, hb, MTOK, DFF, D, 1);
        gemm_kernel<<<g256, 256>>>(hb, Wf2 + (size_t)l*DFF*D, bf2 + l*D, tb, MTOK, D, DFF, 0);
        ln_kernel<<<lngrid, 256>>>(xb, tb, ln2g + l*D, ln2b + l*D, xb);
    }

    head_kernel<<<BB, 256>>>(lnfg, lnfb, Wh1, bh1, Wh2, bh2, out);
}

// round 10
// speedup vs baseline: 1.4065x; 1.4065x over previous
#include <cuda_runtime.h>
#include <math.h>
#include <stdint.h>

#define BB   8
#define NCELL 1024
#define SLEN 1025
#define D    256
#define NH   8
#define HD   32
#define DFF  1024
#define NL   4
#define MTOK (BB*SLEN)   // 8200

// ---------------- scratch (static device globals; no allocs) ----------------
__device__ float g_x[MTOK*D];
__device__ float g_q[MTOK*D];
__device__ float g_k[MTOK*D];
__device__ float g_v[MTOK*D];
__device__ float g_a[MTOK*D];
__device__ float g_t[MTOK*D];
__device__ float g_h[(size_t)MTOK*DFF];

// cp.async helper: 16B global->shared, zero-fill when sz==0
#define CPA16(dst, src, sz) \
    asm volatile("cp.async.cg.shared.global [%0], [%1], 16, %2;" \
        :: "r"((uint32_t)__cvta_generic_to_shared(dst)), "l"(src), "r"(sz))

// ---------------- embedding: emb + cell-type MLP + positional + cls ----------
__global__ void embed_kernel(const float* __restrict__ cf,
                             const int* __restrict__ xc,
                             const int* __restrict__ yc,
                             const float* __restrict__ Wemb,
                             const float* __restrict__ bemb,
                             const float* __restrict__ Wct1,
                             const float* __restrict__ bct1,
                             const float* __restrict__ Wct2,
                             const float* __restrict__ bct2,
                             const float* __restrict__ cls)
{
    int blk = blockIdx.x;          // 0..8199
    int b = blk / SLEN;
    int s = blk % SLEN;
    int d = threadIdx.x;           // 0..255
    float* out = g_x + (size_t)blk * D;

    if (s == 0) { out[d] = cls[d]; return; }
    int n = s - 1;

    __shared__ float cfs[64];
    __shared__ float hs[128];
    const float* cfp = cf + ((size_t)b*NCELL + n)*64;
    if (d < 64) cfs[d] = cfp[d];
    __syncthreads();

    if (d < 128) {
        float acc = bct1[d];
        #pragma unroll
        for (int k = 0; k < 64; k++) acc = fmaf(cfs[k], Wct1[k*128 + d], acc);
        hs[d] = fmaxf(acc, 0.f);
    }
    __syncthreads();

    float e = bemb[d];
    #pragma unroll
    for (int k = 0; k < 64; k++) e = fmaf(cfs[k], Wemb[k*256 + d], e);
    float c2 = bct2[d];
    #pragma unroll
    for (int j = 0; j < 128; j++) c2 = fmaf(hs[j], Wct2[j*256 + d], c2);

    // positional encoding (match jax: div = exp(2m * (-ln(10000)/128)))
    int dd    = (d < 128) ? d : d - 128;
    int coord = (d < 128) ? xc[b*NCELL + n] : yc[b*NCELL + n];
    coord = min(max(coord, 0), 999);
    int m = dd >> 1;
    const float c1 = -0.07195578739046225f;  // float(-ln(10000)/128)
    float dv  = expf((float)(2*m) * c1);
    float ang = (float)coord * dv;
    float p   = (dd & 1) ? cosf(ang) : sinf(ang);

    out[d] = e + c2 + p;
}

// ---- SGEMM body: C = A(MxK) @ W(KxN) + bias [ReLU]; BM=64 BN=64 BK=16 -------
// 128 threads, 8x4 microtile (~75 regs -> 4 CTAs/SM, 16 warps), double buffer.
__device__ __forceinline__
void gemm_body(const float* __restrict__ A,
               const float* __restrict__ W,
               const float* __restrict__ bias,
               float* __restrict__ C,
               int M, int N, int K, int relu,
               int bx, int by)
{
    __shared__ float As[2][16][68];    // [buf][k][m] transposed, padded (16B-mult)
    __shared__ float Bs[2][16][64];    // [buf][k][n]

    int tid = threadIdx.x;             // 0..127
    int m0 = bx * 64;
    int n0 = by * 64;
    int ar = (tid >> 4) << 3;          // 0..56 (8 rows)
    int bc = (tid & 15) << 2;          // 0..60 (4 cols)

    // A tile 64x16 = 256 float4; 2/thread: rows arow, arow+32
    int arow = tid >> 2;               // 0..31
    int akc  = (tid & 3) << 2;         // 0,4,8,12
    // B tile 16x64 = 256 float4; 2/thread: k rows bkr, bkr+8
    int bkr = tid >> 4;                // 0..7
    int bnc = (tid & 15) << 2;         // 0..60

    bool av0 = (m0 + arow)      < M;
    bool av1 = (m0 + arow + 32) < M;
    const float* Ap0 = A + (size_t)(m0 + arow)      * K + akc;
    const float* Ap1 = A + (size_t)(m0 + arow + 32) * K + akc;
    const float* Bp0 = W + (size_t)bkr       * N + n0 + bnc;
    const float* Bp1 = W + (size_t)(bkr + 8) * N + n0 + bnc;

    float acc[8][4] = {};

    // prologue: tile 0 -> buffer 0
    {
        float4 a0 = av0 ? *(const float4*)Ap0 : make_float4(0.f,0.f,0.f,0.f);
        float4 a1 = av1 ? *(const float4*)Ap1 : make_float4(0.f,0.f,0.f,0.f);
        float4 b0 = *(const float4*)Bp0;
        float4 b1 = *(const float4*)Bp1;
        As[0][akc+0][arow] = a0.x; As[0][akc+1][arow] = a0.y;
        As[0][akc+2][arow] = a0.z; As[0][akc+3][arow] = a0.w;
        As[0][akc+0][arow+32] = a1.x; As[0][akc+1][arow+32] = a1.y;
        As[0][akc+2][arow+32] = a1.z; As[0][akc+3][arow+32] = a1.w;
        *(float4*)&Bs[0][bkr  ][bnc] = b0;
        *(float4*)&Bs[0][bkr+8][bnc] = b1;
    }
    __syncthreads();

    int KT = K >> 4;
    for (int kt = 0; kt < KT; kt++) {
        int cur = kt & 1;
        float4 pa0, pa1, pb0, pb1;
        bool more = (kt + 1 < KT);
        if (more) {
            int k0 = (kt + 1) << 4;
            pa0 = av0 ? *(const float4*)(Ap0 + k0) : make_float4(0.f,0.f,0.f,0.f);
            pa1 = av1 ? *(const float4*)(Ap1 + k0) : make_float4(0.f,0.f,0.f,0.f);
            pb0 = *(const float4*)(Bp0 + (size_t)k0 * N);
            pb1 = *(const float4*)(Bp1 + (size_t)k0 * N);
        }

        #pragma unroll
        for (int kk = 0; kk < 16; kk++) {
            float a[8], b[4];
            *(float4*)&a[0] = *(float4*)&As[cur][kk][ar];
            *(float4*)&a[4] = *(float4*)&As[cur][kk][ar+4];
            *(float4*)&b[0] = *(float4*)&Bs[cur][kk][bc];
            #pragma unroll
            for (int r = 0; r < 8; r++) {
                #pragma unroll
                for (int c = 0; c < 4; c++)
                    acc[r][c] = fmaf(a[r], b[c], acc[r][c]);
            }
        }

        if (more) {
            int nxt = cur ^ 1;
            As[nxt][akc+0][arow] = pa0.x; As[nxt][akc+1][arow] = pa0.y;
            As[nxt][akc+2][arow] = pa0.z; As[nxt][akc+3][arow] = pa0.w;
            As[nxt][akc+0][arow+32] = pa1.x; As[nxt][akc+1][arow+32] = pa1.y;
            As[nxt][akc+2][arow+32] = pa1.z; As[nxt][akc+3][arow+32] = pa1.w;
            *(float4*)&Bs[nxt][bkr  ][bnc] = pb0;
            *(float4*)&Bs[nxt][bkr+8][bnc] = pb1;
            __syncthreads();
        }
    }

    float4 bb4 = *(const float4*)(bias + n0 + bc);
    float bb[4] = {bb4.x, bb4.y, bb4.z, bb4.w};
    #pragma unroll
    for (int r = 0; r < 8; r++) {
        int gr = m0 + ar + r;
        if (gr < M) {
            float4 o;
            o.x = acc[r][0] + bb[0]; o.y = acc[r][1] + bb[1];
            o.z = acc[r][2] + bb[2]; o.w = acc[r][3] + bb[3];
            if (relu) {
                o.x = fmaxf(o.x, 0.f); o.y = fmaxf(o.y, 0.f);
                o.z = fmaxf(o.z, 0.f); o.w = fmaxf(o.w, 0.f);
            }
            *(float4*)(C + (size_t)gr*N + n0 + bc) = o;
        }
    }
}

__global__ __launch_bounds__(128, 4)
void gemm_kernel(const float* __restrict__ A,
                 const float* __restrict__ W,
                 const float* __restrict__ bias,
                 float* __restrict__ C,
                 int M, int N, int K, int relu)
{
    gemm_body(A, W, bias, C, M, N, K, relu, blockIdx.x, blockIdx.y);
}

// fused QKV: grid.z in {0,1,2} selects weights/bias/output
__global__ __launch_bounds__(128, 4)
void qkv_kernel(const float* __restrict__ A,
                const float* __restrict__ Wq,
                const float* __restrict__ Wk,
                const float* __restrict__ Wv,
                const float* __restrict__ bq,
                const float* __restrict__ bk,
                const float* __restrict__ bv,
                float* __restrict__ Q,
                float* __restrict__ Ko,
                float* __restrict__ V)
{
    int z = blockIdx.z;
    const float* W = (z == 0) ? Wq : (z == 1) ? Wk : Wv;
    const float* b = (z == 0) ? bq : (z == 1) ? bk : bv;
    float* C       = (z == 0) ? Q  : (z == 1) ? Ko : V;
    gemm_body(A, W, b, C, MTOK, D, D, 0, blockIdx.x, blockIdx.y);
}

// ---------------- flash attention: q-tile 128, cp.async double buffering -----
// 256 threads: rl = tid>>2 owns rows (qt*128+rl) and (+64); sub = tid&3 owns
// k-columns {4j+sub} (interleaved -> conflict-free smem broadcast).
__device__ __forceinline__ void attn_issue_tile(
    const float* kbase, const float* vbase,
    float (*ks)[64][36], float (*vs)[64][36],
    int buf, int t, int row0, int c4)
{
    int k0  = t * 64;
    int gk0 = k0 + row0;
    int gk1 = gk0 + 32;
    int s0 = (gk0 < SLEN) ? 16 : 0;
    int s1 = (gk1 < SLEN) ? 16 : 0;
    int ck0 = min(gk0, SLEN-1);
    int ck1 = min(gk1, SLEN-1);
    CPA16(&ks[buf][row0   ][c4], kbase + (size_t)ck0*D + c4, s0);
    CPA16(&ks[buf][row0+32][c4], kbase + (size_t)ck1*D + c4, s1);
    CPA16(&vs[buf][row0   ][c4], vbase + (size_t)ck0*D + c4, s0);
    CPA16(&vs[buf][row0+32][c4], vbase + (size_t)ck1*D + c4, s1);
    asm volatile("cp.async.commit_group;");
}

__global__ void attn_kernel()
{
    __shared__ float ks[2][64][36];
    __shared__ float vs[2][64][36];

    int qt = blockIdx.x;           // 0..8
    int h  = blockIdx.y;
    int b  = blockIdx.z;
    int tid = threadIdx.x;
    int rl  = tid >> 2;            // 0..63
    int sub = tid & 3;
    int q0r = qt*128 + rl;
    int q1r = q0r + 64;
    bool v0 = q0r < SLEN;
    bool v1 = q1r < SLEN;

    int row0 = tid >> 3;           // 0..31 (load mapping)
    int c4   = (tid & 7) << 2;

    const float scale = 0.17677669529663687f;   // 1/sqrt(32)
    const float* qbase = g_q + (size_t)b*SLEN*D + h*HD;
    const float* kbase = g_k + (size_t)b*SLEN*D + h*HD;
    const float* vbase = g_v + (size_t)b*SLEN*D + h*HD;

    float q0[HD], q1[HD];
    #pragma unroll
    for (int d4 = 0; d4 < 8; d4++) {
        float4 t0 = make_float4(0.f,0.f,0.f,0.f);
        float4 t1 = make_float4(0.f,0.f,0.f,0.f);
        if (v0) t0 = *(const float4*)(qbase + (size_t)q0r*D + d4*4);
        if (v1) t1 = *(const float4*)(qbase + (size_t)q1r*D + d4*4);
        q0[d4*4+0] = t0.x*scale; q0[d4*4+1] = t0.y*scale;
        q0[d4*4+2] = t0.z*scale; q0[d4*4+3] = t0.w*scale;
        q1[d4*4+0] = t1.x*scale; q1[d4*4+1] = t1.y*scale;
        q1[d4*4+2] = t1.z*scale; q1[d4*4+3] = t1.w*scale;
    }

    float m0 = -INFINITY, m1 = -INFINITY, l0 = 0.f, l1 = 0.f;
    float acc0[HD], acc1[HD];
    #pragma unroll
    for (int d = 0; d < HD; d++) { acc0[d] = 0.f; acc1[d] = 0.f; }

    const int ntiles = (SLEN + 63) / 64;   // 17

    attn_issue_tile(kbase, vbase, ks, vs, 0, 0, row0, c4);

    for (int t = 0; t < ntiles; t++) {
        int cur = t & 1;
        int k0 = t*64;
        if (t + 1 < ntiles) {
            attn_issue_tile(kbase, vbase, ks, vs, cur ^ 1, t + 1, row0, c4);
            asm volatile("cp.async.wait_group 1;");
        } else {
            asm volatile("cp.async.wait_group 0;");
        }
        __syncthreads();

        float p0[16], p1[16];
        float t0 = -INFINITY, t1 = -INFINITY;
        #pragma unroll
        for (int j = 0; j < 16; j++) {
            int cl = 4*j + sub;            // interleaved column assignment
            float s0, s1;
            if (k0 + cl < SLEN) {
                s0 = 0.f; s1 = 0.f;
                #pragma unroll
                for (int d4 = 0; d4 < 8; d4++) {
                    float4 kv = *(const float4*)&ks[cur][cl][d4*4];
                    s0 = fmaf(q0[d4*4+0], kv.x, s0);
                    s0 = fmaf(q0[d4*4+1], kv.y, s0);
                    s0 = fmaf(q0[d4*4+2], kv.z, s0);
                    s0 = fmaf(q0[d4*4+3], kv.w, s0);
                    s1 = fmaf(q1[d4*4+0], kv.x, s1);
                    s1 = fmaf(q1[d4*4+1], kv.y, s1);
                    s1 = fmaf(q1[d4*4+2], kv.z, s1);
                    s1 = fmaf(q1[d4*4+3], kv.w, s1);
                }
            } else { s0 = -INFINITY; s1 = -INFINITY; }
            p0[j] = s0; p1[j] = s1;
            t0 = fmaxf(t0, s0); t1 = fmaxf(t1, s1);
        }
        t0 = fmaxf(t0, __shfl_xor_sync(0xffffffffu, t0, 1));
        t0 = fmaxf(t0, __shfl_xor_sync(0xffffffffu, t0, 2));
        t1 = fmaxf(t1, __shfl_xor_sync(0xffffffffu, t1, 1));
        t1 = fmaxf(t1, __shfl_xor_sync(0xffffffffu, t1, 2));

        float mn0 = fmaxf(m0, t0), mn1 = fmaxf(m1, t1);
        float cr0 = __expf(m0 - mn0), cr1 = __expf(m1 - mn1);
        l0 *= cr0; l1 *= cr1;
        #pragma unroll
        for (int d = 0; d < HD; d++) { acc0[d] *= cr0; acc1[d] *= cr1; }

        float ls0 = 0.f, ls1 = 0.f;
        #pragma unroll
        for (int j = 0; j < 16; j++) {
            p0[j] = __expf(p0[j] - mn0); ls0 += p0[j];
            p1[j] = __expf(p1[j] - mn1); ls1 += p1[j];
        }
        l0 += ls0; l1 += ls1;

        #pragma unroll
        for (int j = 0; j < 16; j++) {
            int cl = 4*j + sub;
            float pj0 = p0[j], pj1 = p1[j];
            #pragma unroll
            for (int d4 = 0; d4 < 8; d4++) {
                float4 vv = *(const float4*)&vs[cur][cl][d4*4];
                acc0[d4*4+0] = fmaf(pj0, vv.x, acc0[d4*4+0]);
                acc0[d4*4+1] = fmaf(pj0, vv.y, acc0[d4*4+1]);
                acc0[d4*4+2] = fmaf(pj0, vv.z, acc0[d4*4+2]);
                acc0[d4*4+3] = fmaf(pj0, vv.w, acc0[d4*4+3]);
                acc1[d4*4+0] = fmaf(pj1, vv.x, acc1[d4*4+0]);
                acc1[d4*4+1] = fmaf(pj1, vv.y, acc1[d4*4+1]);
                acc1[d4*4+2] = fmaf(pj1, vv.z, acc1[d4*4+2]);
                acc1[d4*4+3] = fmaf(pj1, vv.w, acc1[d4*4+3]);
            }
        }
        m0 = mn0; m1 = mn1;
        __syncthreads();   // all reads of 'cur' done before t+1 re-issues into it
    }

    // reduce across the 4 sub-threads of each row
    l0 += __shfl_xor_sync(0xffffffffu, l0, 1);
    l0 += __shfl_xor_sync(0xffffffffu, l0, 2);
    l1 += __shfl_xor_sync(0xffffffffu, l1, 1);
    l1 += __shfl_xor_sync(0xffffffffu, l1, 2);
    #pragma unroll
    for (int d = 0; d < HD; d++) {
        acc0[d] += __shfl_xor_sync(0xffffffffu, acc0[d], 1);
        acc0[d] += __shfl_xor_sync(0xffffffffu, acc0[d], 2);
        acc1[d] += __shfl_xor_sync(0xffffffffu, acc1[d], 1);
        acc1[d] += __shfl_xor_sync(0xffffffffu, acc1[d], 2);
    }

    if (sub == 0) {
        if (v0) {
            float inv = 1.f / l0;
            float* op = g_a + ((size_t)b*SLEN + q0r)*D + h*HD;
            #pragma unroll
            for (int d4 = 0; d4 < 8; d4++) {
                float4 o;
                o.x = acc0[d4*4+0]*inv; o.y = acc0[d4*4+1]*inv;
                o.z = acc0[d4*4+2]*inv; o.w = acc0[d4*4+3]*inv;
                *(float4*)(op + d4*4) = o;
            }
        }
        if (v1) {
            float inv = 1.f / l1;
            float* op = g_a + ((size_t)b*SLEN + q1r)*D + h*HD;
            #pragma unroll
            for (int d4 = 0; d4 < 8; d4++) {
                float4 o;
                o.x = acc1[d4*4+0]*inv; o.y = acc1[d4*4+1]*inv;
                o.z = acc1[d4*4+2]*inv; o.w = acc1[d4*4+3]*inv;
                *(float4*)(op + d4*4) = o;
            }
        }
    }
}

// ---------- fused residual + LayerNorm, warp-per-row (8 rows/block) ----------
__global__ void ln_kernel(const float* __restrict__ A,
                          const float* __restrict__ Bsrc,
                          const float* __restrict__ g,
                          const float* __restrict__ bta,
                          float* __restrict__ out)
{
    int warp = threadIdx.x >> 5;
    int lane = threadIdx.x & 31;
    int row = blockIdx.x * 8 + warp;
    size_t base = (size_t)row * D;

    const float4* ap = (const float4*)(A + base);
    const float4* bp = (const float4*)(Bsrc + base);
    float4 a0 = ap[lane], a1 = ap[lane + 32];
    float4 b0 = bp[lane], b1 = bp[lane + 32];
    float v[8];
    v[0]=a0.x+b0.x; v[1]=a0.y+b0.y; v[2]=a0.z+b0.z; v[3]=a0.w+b0.w;
    v[4]=a1.x+b1.x; v[5]=a1.y+b1.y; v[6]=a1.z+b1.z; v[7]=a1.w+b1.w;

    float s = 0.f, s2 = 0.f;
    #pragma unroll
    for (int i = 0; i < 8; i++) { s += v[i]; s2 = fmaf(v[i], v[i], s2); }
    #pragma unroll
    for (int o = 16; o > 0; o >>= 1) {
        s  += __shfl_xor_sync(0xffffffffu, s,  o);
        s2 += __shfl_xor_sync(0xffffffffu, s2, o);
    }
    float mu = s * (1.f/256.f);
    float var = s2 * (1.f/256.f) - mu*mu;
    float rstd = rsqrtf(var + 1e-5f);

    const float4* gp = (const float4*)g;
    const float4* tp = (const float4*)bta;
    float4 g0 = gp[lane], g1 = gp[lane+32];
    float4 t0 = tp[lane], t1 = tp[lane+32];
    float4 o0, o1;
    o0.x = (v[0]-mu)*rstd*g0.x + t0.x;
    o0.y = (v[1]-mu)*rstd*g0.y + t0.y;
    o0.z = (v[2]-mu)*rstd*g0.z + t0.z;
    o0.w = (v[3]-mu)*rstd*g0.w + t0.w;
    o1.x = (v[4]-mu)*rstd*g1.x + t1.x;
    o1.y = (v[5]-mu)*rstd*g1.y + t1.y;
    o1.z = (v[6]-mu)*rstd*g1.z + t1.z;
    o1.w = (v[7]-mu)*rstd*g1.w + t1.w;
    float4* op = (float4*)(out + base);
    op[lane]      = o0;
    op[lane + 32] = o1;
}

// ---------------- final: LN cls row only + 2-layer head ----------------------
__global__ void head_kernel(const float* __restrict__ g,
                            const float* __restrict__ bta,
                            const float* __restrict__ Wh1,
                            const float* __restrict__ bh1,
                            const float* __restrict__ Wh2,
                            const float* __restrict__ bh2,
                            float* __restrict__ out)
{
    int b = blockIdx.x;
    int d = threadIdx.x;
    float v = g_x[(size_t)b*SLEN*D + d];

    float s = v, s2 = v*v;
    #pragma unroll
    for (int o = 16; o > 0; o >>= 1) {
        s  += __shfl_xor_sync(0xffffffffu, s,  o);
        s2 += __shfl_xor_sync(0xffffffffu, s2, o);
    }
    __shared__ float ws[8], ws2[8];
    __shared__ float mu_s, rstd_s;
    int w = d >> 5;
    if ((d & 31) == 0) { ws[w] = s; ws2[w] = s2; }
    __syncthreads();
    if (d == 0) {
        float S1 = 0.f, S2 = 0.f;
        #pragma unroll
        for (int i = 0; i < 8; i++) { S1 += ws[i]; S2 += ws2[i]; }
        float mu = S1 * (1.f/256.f);
        float var = S2 * (1.f/256.f) - mu*mu;
        mu_s = mu;
        rstd_s = rsqrtf(var + 1e-5f);
    }
    __syncthreads();

    __shared__ float clsr[256];
    __shared__ float hid[256];
    float c = (v - mu_s) * rstd_s * g[d] + bta[d];
    clsr[d] = c;
    out[b*D + d] = c;                       // cls_out
    __syncthreads();

    float hsum = bh1[d];
    #pragma unroll 8
    for (int k = 0; k < 256; k++) hsum = fmaf(clsr[k], Wh1[k*256 + d], hsum);
    hid[d] = fmaxf(hsum, 0.f);
    __syncthreads();

    if (d < 2) {
        float lg = bh2[d];
        for (int k = 0; k < 256; k++) lg = fmaf(hid[k], Wh2[k*2 + d], lg);
        out[BB*D + b*2 + d] = lg;           // logits after cls_out block
    }
}

// ---------------- launcher ---------------------------------------------------
extern "C" void kernel_launch(void* const* d_in, const int* in_sizes, int n_in,
                              void* d_out, int out_size)
{
    (void)in_sizes; (void)n_in; (void)out_size;

    const float* cf   = (const float*)d_in[0];
    const int*   xc   = (const int*)  d_in[1];
    const int*   yc   = (const int*)  d_in[2];
    const float* Wemb = (const float*)d_in[3];
    const float* bemb = (const float*)d_in[4];
    const float* Wct1 = (const float*)d_in[5];
    const float* bct1 = (const float*)d_in[6];
    const float* Wct2 = (const float*)d_in[7];
    const float* bct2 = (const float*)d_in[8];
    const float* cls  = (const float*)d_in[9];
    const float* Wq = (const float*)d_in[10]; const float* bq = (const float*)d_in[11];
    const float* Wk = (const float*)d_in[12]; const float* bk = (const float*)d_in[13];
    const float* Wv = (const float*)d_in[14]; const float* bv = (const float*)d_in[15];
    const float* Wo = (const float*)d_in[16]; const float* bo = (const float*)d_in[17];
    const float* ln1g = (const float*)d_in[18]; const float* ln1b = (const float*)d_in[19];
    const float* ln2g = (const float*)d_in[20]; const float* ln2b = (const float*)d_in[21];
    const float* Wf1 = (const float*)d_in[22]; const float* bf1 = (const float*)d_in[23];
    const float* Wf2 = (const float*)d_in[24]; const float* bf2 = (const float*)d_in[25];
    const float* lnfg = (const float*)d_in[26]; const float* lnfb = (const float*)d_in[27];
    const float* Wh1 = (const float*)d_in[28]; const float* bh1 = (const float*)d_in[29];
    const float* Wh2 = (const float*)d_in[30]; const float* bh2 = (const float*)d_in[31];
    float* out = (float*)d_out;

    void* p;
    cudaGetSymbolAddress(&p, g_x); float* xb = (float*)p;
    cudaGetSymbolAddress(&p, g_q); float* qb = (float*)p;
    cudaGetSymbolAddress(&p, g_k); float* kb = (float*)p;
    cudaGetSymbolAddress(&p, g_v); float* vb = (float*)p;
    cudaGetSymbolAddress(&p, g_a); float* ab = (float*)p;
    cudaGetSymbolAddress(&p, g_t); float* tb = (float*)p;
    cudaGetSymbolAddress(&p, g_h); float* hb = (float*)p;

    embed_kernel<<<MTOK, 256>>>(cf, xc, yc, Wemb, bemb, Wct1, bct1, Wct2, bct2, cls);

    dim3 gqkv((MTOK + 63)/64, D/64, 3);    // 129 x 4 x 3
    dim3 g256((MTOK + 63)/64, D/64);       // 129 x 4
    dim3 gff ((MTOK + 63)/64, DFF/64);     // 129 x 16
    dim3 gattn((SLEN + 127)/128, NH, BB);  // 9 x 8 x 8
    int lngrid = MTOK / 8;                 // 1025

    for (int l = 0; l < NL; l++) {
        size_t wo = (size_t)l*D*D;
        qkv_kernel<<<gqkv, 128>>>(xb, Wq + wo, Wk + wo, Wv + wo,
                                  bq + l*D, bk + l*D, bv + l*D, qb, kb, vb);
        attn_kernel<<<gattn, 256>>>();
        gemm_kernel<<<g256, 128>>>(ab, Wo + wo, bo + l*D, tb, MTOK, D, D, 0);
        ln_kernel<<<lngrid, 256>>>(xb, tb, ln1g + l*D, ln1b + l*D, xb);
        gemm_kernel<<<gff, 128>>>(xb, Wf1 + (size_t)l*D*DFF, bf1 + l*DFF, hb, MTOK, DFF, D, 1);
        gemm_kernel<<<g256, 128>>>(hb, Wf2 + (size_t)l*DFF*D, bf2 + l*D, tb, MTOK, D, DFF, 0);
        ln_kernel<<<lngrid, 256>>>(xb, tb, ln2g + l*D, ln2b + l*D, xb);
    }

    head_kernel<<<BB, 256>>>(lnfg, lnfb, Wh1, bh1, Wh2, bh2, out);
}

// round 11
// speedup vs baseline: 1.4095x; 1.0022x over previous
#include <cuda_runtime.h>
#include <math.h>
#include <stdint.h>

#define BB   8
#define NCELL 1024
#define SLEN 1025
#define D    256
#define NH   8
#define HD   32
#define DFF  1024
#define NL   4
#define MTOK (BB*SLEN)   // 8200

typedef unsigned long long u64;

// packed f32x2 helpers (Blackwell sm_100+)
#define FMA2(acc, a, b) \
    asm("fma.rn.f32x2 %0, %1, %2, %0;" : "+l"(acc) : "l"(a), "l"(b))
#define MUL2(d, a, b) \
    asm("mul.rn.f32x2 %0, %1, %2;" : "=l"(d) : "l"(a), "l"(b))
#define PACK2(d, lo, hi) \
    asm("mov.b64 %0, {%1, %2};" : "=l"(d) : "f"(lo), "f"(hi))
#define UNPACK2(lo, hi, s) \
    asm("mov.b64 {%0, %1}, %2;" : "=f"(lo), "=f"(hi) : "l"(s))

// ---------------- scratch (static device globals; no allocs) ----------------
__device__ float g_x[MTOK*D];
__device__ float g_q[MTOK*D];
__device__ float g_k[MTOK*D];
__device__ float g_v[MTOK*D];
__device__ float g_a[MTOK*D];
__device__ float g_t[MTOK*D];
__device__ float g_h[(size_t)MTOK*DFF];

// cp.async helper: 16B global->shared, zero-fill when sz==0
#define CPA16(dst, src, sz) \
    asm volatile("cp.async.cg.shared.global [%0], [%1], 16, %2;" \
        :: "r"((uint32_t)__cvta_generic_to_shared(dst)), "l"(src), "r"(sz))

// ---------------- embedding: emb + cell-type MLP + positional + cls ----------
__global__ void embed_kernel(const float* __restrict__ cf,
                             const int* __restrict__ xc,
                             const int* __restrict__ yc,
                             const float* __restrict__ Wemb,
                             const float* __restrict__ bemb,
                             const float* __restrict__ Wct1,
                             const float* __restrict__ bct1,
                             const float* __restrict__ Wct2,
                             const float* __restrict__ bct2,
                             const float* __restrict__ cls)
{
    int blk = blockIdx.x;          // 0..8199
    int b = blk / SLEN;
    int s = blk % SLEN;
    int d = threadIdx.x;           // 0..255
    float* out = g_x + (size_t)blk * D;

    if (s == 0) { out[d] = cls[d]; return; }
    int n = s - 1;

    __shared__ float cfs[64];
    __shared__ float hs[128];
    const float* cfp = cf + ((size_t)b*NCELL + n)*64;
    if (d < 64) cfs[d] = cfp[d];
    __syncthreads();

    if (d < 128) {
        float acc = bct1[d];
        #pragma unroll
        for (int k = 0; k < 64; k++) acc = fmaf(cfs[k], Wct1[k*128 + d], acc);
        hs[d] = fmaxf(acc, 0.f);
    }
    __syncthreads();

    float e = bemb[d];
    #pragma unroll
    for (int k = 0; k < 64; k++) e = fmaf(cfs[k], Wemb[k*256 + d], e);
    float c2 = bct2[d];
    #pragma unroll
    for (int j = 0; j < 128; j++) c2 = fmaf(hs[j], Wct2[j*256 + d], c2);

    // positional encoding (match jax: div = exp(2m * (-ln(10000)/128)))
    int dd    = (d < 128) ? d : d - 128;
    int coord = (d < 128) ? xc[b*NCELL + n] : yc[b*NCELL + n];
    coord = min(max(coord, 0), 999);
    int m = dd >> 1;
    const float c1 = -0.07195578739046225f;  // float(-ln(10000)/128)
    float dv  = expf((float)(2*m) * c1);
    float ang = (float)coord * dv;
    float p   = (dd & 1) ? cosf(ang) : sinf(ang);

    out[d] = e + c2 + p;
}

// ---- SGEMM body: C = A(MxK) @ W(KxN) + bias [ReLU]; BM=64 BN=64 BK=16 -------
// 128 threads, 8x4 microtile via packed f32x2 FMA (16 FFMA2/kk), double buffer.
__device__ __forceinline__
void gemm_body(const float* __restrict__ A,
               const float* __restrict__ W,
               const float* __restrict__ bias,
               float* __restrict__ C,
               int M, int N, int K, int relu,
               int bx, int by)
{
    __shared__ float As[2][16][68];    // [buf][k][m] transposed, padded
    __shared__ float Bs[2][16][64];    // [buf][k][n]

    int tid = threadIdx.x;             // 0..127
    int m0 = bx * 64;
    int n0 = by * 64;
    int ar = (tid >> 4) << 3;          // 0..56 (8 rows)
    int bc = (tid & 15) << 2;          // 0..60 (4 cols)

    // A tile 64x16 = 256 float4; 2/thread: rows arow, arow+32
    int arow = tid >> 2;               // 0..31
    int akc  = (tid & 3) << 2;         // 0,4,8,12
    // B tile 16x64 = 256 float4; 2/thread: k rows bkr, bkr+8
    int bkr = tid >> 4;                // 0..7
    int bnc = (tid & 15) << 2;         // 0..60

    bool av0 = (m0 + arow)      < M;
    bool av1 = (m0 + arow + 32) < M;
    const float* Ap0 = A + (size_t)(m0 + arow)      * K + akc;
    const float* Ap1 = A + (size_t)(m0 + arow + 32) * K + akc;
    const float* Bp0 = W + (size_t)bkr       * N + n0 + bnc;
    const float* Bp1 = W + (size_t)(bkr + 8) * N + n0 + bnc;

    u64 acc2[4][4];                    // [row-pair][col], packed (row2rp, row2rp+1)
    #pragma unroll
    for (int i = 0; i < 4; i++)
        #pragma unroll
        for (int j = 0; j < 4; j++) acc2[i][j] = 0ull;

    // prologue: tile 0 -> buffer 0
    {
        float4 a0 = av0 ? *(const float4*)Ap0 : make_float4(0.f,0.f,0.f,0.f);
        float4 a1 = av1 ? *(const float4*)Ap1 : make_float4(0.f,0.f,0.f,0.f);
        float4 b0 = *(const float4*)Bp0;
        float4 b1 = *(const float4*)Bp1;
        As[0][akc+0][arow] = a0.x; As[0][akc+1][arow] = a0.y;
        As[0][akc+2][arow] = a0.z; As[0][akc+3][arow] = a0.w;
        As[0][akc+0][arow+32] = a1.x; As[0][akc+1][arow+32] = a1.y;
        As[0][akc+2][arow+32] = a1.z; As[0][akc+3][arow+32] = a1.w;
        *(float4*)&Bs[0][bkr  ][bnc] = b0;
        *(float4*)&Bs[0][bkr+8][bnc] = b1;
    }
    __syncthreads();

    int KT = K >> 4;
    for (int kt = 0; kt < KT; kt++) {
        int cur = kt & 1;
        float4 pa0, pa1, pb0, pb1;
        bool more = (kt + 1 < KT);
        if (more) {
            int k0 = (kt + 1) << 4;
            pa0 = av0 ? *(const float4*)(Ap0 + k0) : make_float4(0.f,0.f,0.f,0.f);
            pa1 = av1 ? *(const float4*)(Ap1 + k0) : make_float4(0.f,0.f,0.f,0.f);
            pb0 = *(const float4*)(Bp0 + (size_t)k0 * N);
            pb1 = *(const float4*)(Bp1 + (size_t)k0 * N);
        }

        #pragma unroll
        for (int kk = 0; kk < 16; kk++) {
            union { float4 f; u64 u[2]; } a0u, a1u, bu;
            a0u.f = *(float4*)&As[cur][kk][ar];      // rows ar..ar+3 -> pairs
            a1u.f = *(float4*)&As[cur][kk][ar+4];    // rows ar+4..ar+7
            bu.f  = *(float4*)&Bs[cur][kk][bc];
            float bf[4] = {bu.f.x, bu.f.y, bu.f.z, bu.f.w};
            u64 bb[4];
            #pragma unroll
            for (int c = 0; c < 4; c++) PACK2(bb[c], bf[c], bf[c]);
            u64 aa[4] = {a0u.u[0], a0u.u[1], a1u.u[0], a1u.u[1]};
            #pragma unroll
            for (int rp = 0; rp < 4; rp++) {
                #pragma unroll
                for (int c = 0; c < 4; c++)
                    FMA2(acc2[rp][c], aa[rp], bb[c]);
            }
        }

        if (more) {
            int nxt = cur ^ 1;
            As[nxt][akc+0][arow] = pa0.x; As[nxt][akc+1][arow] = pa0.y;
            As[nxt][akc+2][arow] = pa0.z; As[nxt][akc+3][arow] = pa0.w;
            As[nxt][akc+0][arow+32] = pa1.x; As[nxt][akc+1][arow+32] = pa1.y;
            As[nxt][akc+2][arow+32] = pa1.z; As[nxt][akc+3][arow+32] = pa1.w;
            *(float4*)&Bs[nxt][bkr  ][bnc] = pb0;
            *(float4*)&Bs[nxt][bkr+8][bnc] = pb1;
            __syncthreads();
        }
    }

    float4 bb4 = *(const float4*)(bias + n0 + bc);
    float bbf[4] = {bb4.x, bb4.y, bb4.z, bb4.w};
    #pragma unroll
    for (int rp = 0; rp < 4; rp++) {
        float lo[4], hi[4];
        #pragma unroll
        for (int c = 0; c < 4; c++) UNPACK2(lo[c], hi[c], acc2[rp][c]);
        #pragma unroll
        for (int h = 0; h < 2; h++) {
            int gr = m0 + ar + 2*rp + h;
            if (gr < M) {
                float* src = h ? hi : lo;
                float4 o;
                o.x = src[0] + bbf[0]; o.y = src[1] + bbf[1];
                o.z = src[2] + bbf[2]; o.w = src[3] + bbf[3];
                if (relu) {
                    o.x = fmaxf(o.x, 0.f); o.y = fmaxf(o.y, 0.f);
                    o.z = fmaxf(o.z, 0.f); o.w = fmaxf(o.w, 0.f);
                }
                *(float4*)(C + (size_t)gr*N + n0 + bc) = o;
            }
        }
    }
}

__global__ __launch_bounds__(128, 4)
void gemm_kernel(const float* __restrict__ A,
                 const float* __restrict__ W,
                 const float* __restrict__ bias,
                 float* __restrict__ C,
                 int M, int N, int K, int relu)
{
    gemm_body(A, W, bias, C, M, N, K, relu, blockIdx.x, blockIdx.y);
}

// fused QKV: grid.z in {0,1,2} selects weights/bias/output
__global__ __launch_bounds__(128, 4)
void qkv_kernel(const float* __restrict__ A,
                const float* __restrict__ Wq,
                const float* __restrict__ Wk,
                const float* __restrict__ Wv,
                const float* __restrict__ bq,
                const float* __restrict__ bk,
                const float* __restrict__ bv,
                float* __restrict__ Q,
                float* __restrict__ Ko,
                float* __restrict__ V)
{
    int z = blockIdx.z;
    const float* W = (z == 0) ? Wq : (z == 1) ? Wk : Wv;
    const float* b = (z == 0) ? bq : (z == 1) ? bk : bv;
    float* C       = (z == 0) ? Q  : (z == 1) ? Ko : V;
    gemm_body(A, W, b, C, MTOK, D, D, 0, blockIdx.x, blockIdx.y);
}

// ---------------- flash attention: q-tile 128, cp.async dbuf, f32x2 math -----
__device__ __forceinline__ void attn_issue_tile(
    const float* kbase, const float* vbase,
    float (*ks)[64][36], float (*vs)[64][36],
    int buf, int t, int row0, int c4)
{
    int k0  = t * 64;
    int gk0 = k0 + row0;
    int gk1 = gk0 + 32;
    int s0 = (gk0 < SLEN) ? 16 : 0;
    int s1 = (gk1 < SLEN) ? 16 : 0;
    int ck0 = min(gk0, SLEN-1);
    int ck1 = min(gk1, SLEN-1);
    CPA16(&ks[buf][row0   ][c4], kbase + (size_t)ck0*D + c4, s0);
    CPA16(&ks[buf][row0+32][c4], kbase + (size_t)ck1*D + c4, s1);
    CPA16(&vs[buf][row0   ][c4], vbase + (size_t)ck0*D + c4, s0);
    CPA16(&vs[buf][row0+32][c4], vbase + (size_t)ck1*D + c4, s1);
    asm volatile("cp.async.commit_group;");
}

__global__ void attn_kernel()
{
    __shared__ float ks[2][64][36];
    __shared__ float vs[2][64][36];

    int qt = blockIdx.x;           // 0..8
    int h  = blockIdx.y;
    int b  = blockIdx.z;
    int tid = threadIdx.x;
    int rl  = tid >> 2;            // 0..63
    int sub = tid & 3;
    int q0r = qt*128 + rl;
    int q1r = q0r + 64;
    bool v0 = q0r < SLEN;
    bool v1 = q1r < SLEN;

    int row0 = tid >> 3;           // 0..31 (load mapping)
    int c4   = (tid & 7) << 2;

    const float scale = 0.17677669529663687f;   // 1/sqrt(32)
    const float* qbase = g_q + (size_t)b*SLEN*D + h*HD;
    const float* kbase = g_k + (size_t)b*SLEN*D + h*HD;
    const float* vbase = g_v + (size_t)b*SLEN*D + h*HD;

    // q packed along d: qp[i] = (q[2i], q[2i+1])
    u64 qp0[16], qp1[16];
    #pragma unroll
    for (int d4 = 0; d4 < 8; d4++) {
        float4 t0 = make_float4(0.f,0.f,0.f,0.f);
        float4 t1 = make_float4(0.f,0.f,0.f,0.f);
        if (v0) t0 = *(const float4*)(qbase + (size_t)q0r*D + d4*4);
        if (v1) t1 = *(const float4*)(qbase + (size_t)q1r*D + d4*4);
        PACK2(qp0[2*d4+0], t0.x*scale, t0.y*scale);
        PACK2(qp0[2*d4+1], t0.z*scale, t0.w*scale);
        PACK2(qp1[2*d4+0], t1.x*scale, t1.y*scale);
        PACK2(qp1[2*d4+1], t1.z*scale, t1.w*scale);
    }

    float m0 = -INFINITY, m1 = -INFINITY, l0 = 0.f, l1 = 0.f;
    u64 accp0[16], accp1[16];      // packed along d
    #pragma unroll
    for (int i = 0; i < 16; i++) { accp0[i] = 0ull; accp1[i] = 0ull; }

    const int ntiles = (SLEN + 63) / 64;   // 17

    attn_issue_tile(kbase, vbase, ks, vs, 0, 0, row0, c4);

    for (int t = 0; t < ntiles; t++) {
        int cur = t & 1;
        int k0 = t*64;
        if (t + 1 < ntiles) {
            attn_issue_tile(kbase, vbase, ks, vs, cur ^ 1, t + 1, row0, c4);
            asm volatile("cp.async.wait_group 1;");
        } else {
            asm volatile("cp.async.wait_group 0;");
        }
        __syncthreads();

        float p0[16], p1[16];
        float t0 = -INFINITY, t1 = -INFINITY;
        #pragma unroll
        for (int j = 0; j < 16; j++) {
            int cl = 4*j + sub;            // interleaved column assignment
            float s0, s1;
            if (k0 + cl < SLEN) {
                u64 s0a = 0ull, s1a = 0ull;
                #pragma unroll
                for (int d4 = 0; d4 < 8; d4++) {
                    union { float4 f; u64 u[2]; } kv;
                    kv.f = *(const float4*)&ks[cur][cl][d4*4];
                    FMA2(s0a, qp0[2*d4+0], kv.u[0]);
                    FMA2(s0a, qp0[2*d4+1], kv.u[1]);
                    FMA2(s1a, qp1[2*d4+0], kv.u[0]);
                    FMA2(s1a, qp1[2*d4+1], kv.u[1]);
                }
                float lo, hi;
                UNPACK2(lo, hi, s0a); s0 = lo + hi;
                UNPACK2(lo, hi, s1a); s1 = lo + hi;
            } else { s0 = -INFINITY; s1 = -INFINITY; }
            p0[j] = s0; p1[j] = s1;
            t0 = fmaxf(t0, s0); t1 = fmaxf(t1, s1);
        }
        t0 = fmaxf(t0, __shfl_xor_sync(0xffffffffu, t0, 1));
        t0 = fmaxf(t0, __shfl_xor_sync(0xffffffffu, t0, 2));
        t1 = fmaxf(t1, __shfl_xor_sync(0xffffffffu, t1, 1));
        t1 = fmaxf(t1, __shfl_xor_sync(0xffffffffu, t1, 2));

        float mn0 = fmaxf(m0, t0), mn1 = fmaxf(m1, t1);
        float cr0 = __expf(m0 - mn0), cr1 = __expf(m1 - mn1);
        l0 *= cr0; l1 *= cr1;
        u64 ccr0, ccr1;
        PACK2(ccr0, cr0, cr0);
        PACK2(ccr1, cr1, cr1);
        #pragma unroll
        for (int i = 0; i < 16; i++) {
            MUL2(accp0[i], accp0[i], ccr0);
            MUL2(accp1[i], accp1[i], ccr1);
        }

        float ls0 = 0.f, ls1 = 0.f;
        #pragma unroll
        for (int j = 0; j < 16; j++) {
            p0[j] = __expf(p0[j] - mn0); ls0 += p0[j];
            p1[j] = __expf(p1[j] - mn1); ls1 += p1[j];
        }
        l0 += ls0; l1 += ls1;

        #pragma unroll
        for (int j = 0; j < 16; j++) {
            int cl = 4*j + sub;
            u64 pp0, pp1;
            PACK2(pp0, p0[j], p0[j]);
            PACK2(pp1, p1[j], p1[j]);
            #pragma unroll
            for (int d4 = 0; d4 < 8; d4++) {
                union { float4 f; u64 u[2]; } vv;
                vv.f = *(const float4*)&vs[cur][cl][d4*4];
                FMA2(accp0[2*d4+0], pp0, vv.u[0]);
                FMA2(accp0[2*d4+1], pp0, vv.u[1]);
                FMA2(accp1[2*d4+0], pp1, vv.u[0]);
                FMA2(accp1[2*d4+1], pp1, vv.u[1]);
            }
        }
        m0 = mn0; m1 = mn1;
        __syncthreads();   // all reads of 'cur' done before t+1 re-issues into it
    }

    // unpack accumulators
    float acc0[HD], acc1[HD];
    #pragma unroll
    for (int i = 0; i < 16; i++) {
        UNPACK2(acc0[2*i], acc0[2*i+1], accp0[i]);
        UNPACK2(acc1[2*i], acc1[2*i+1], accp1[i]);
    }

    // reduce across the 4 sub-threads of each row
    l0 += __shfl_xor_sync(0xffffffffu, l0, 1);
    l0 += __shfl_xor_sync(0xffffffffu, l0, 2);
    l1 += __shfl_xor_sync(0xffffffffu, l1, 1);
    l1 += __shfl_xor_sync(0xffffffffu, l1, 2);
    #pragma unroll
    for (int d = 0; d < HD; d++) {
        acc0[d] += __shfl_xor_sync(0xffffffffu, acc0[d], 1);
        acc0[d] += __shfl_xor_sync(0xffffffffu, acc0[d], 2);
        acc1[d] += __shfl_xor_sync(0xffffffffu, acc1[d], 1);
        acc1[d] += __shfl_xor_sync(0xffffffffu, acc1[d], 2);
    }

    if (sub == 0) {
        if (v0) {
            float inv = 1.f / l0;
            float* op = g_a + ((size_t)b*SLEN + q0r)*D + h*HD;
            #pragma unroll
            for (int d4 = 0; d4 < 8; d4++) {
                float4 o;
                o.x = acc0[d4*4+0]*inv; o.y = acc0[d4*4+1]*inv;
                o.z = acc0[d4*4+2]*inv; o.w = acc0[d4*4+3]*inv;
                *(float4*)(op + d4*4) = o;
            }
        }
        if (v1) {
            float inv = 1.f / l1;
            float* op = g_a + ((size_t)b*SLEN + q1r)*D + h*HD;
            #pragma unroll
            for (int d4 = 0; d4 < 8; d4++) {
                float4 o;
                o.x = acc1[d4*4+0]*inv; o.y = acc1[d4*4+1]*inv;
                o.z = acc1[d4*4+2]*inv; o.w = acc1[d4*4+3]*inv;
                *(float4*)(op + d4*4) = o;
            }
        }
    }
}

// ---------- fused residual + LayerNorm, warp-per-row (8 rows/block) ----------
__global__ void ln_kernel(const float* __restrict__ A,
                          const float* __restrict__ Bsrc,
                          const float* __restrict__ g,
                          const float* __restrict__ bta,
                          float* __restrict__ out)
{
    int warp = threadIdx.x >> 5;
    int lane = threadIdx.x & 31;
    int row = blockIdx.x * 8 + warp;
    size_t base = (size_t)row * D;

    const float4* ap = (const float4*)(A + base);
    const float4* bp = (const float4*)(Bsrc + base);
    float4 a0 = ap[lane], a1 = ap[lane + 32];
    float4 b0 = bp[lane], b1 = bp[lane + 32];
    float v[8];
    v[0]=a0.x+b0.x; v[1]=a0.y+b0.y; v[2]=a0.z+b0.z; v[3]=a0.w+b0.w;
    v[4]=a1.x+b1.x; v[5]=a1.y+b1.y; v[6]=a1.z+b1.z; v[7]=a1.w+b1.w;

    float s = 0.f, s2 = 0.f;
    #pragma unroll
    for (int i = 0; i < 8; i++) { s += v[i]; s2 = fmaf(v[i], v[i], s2); }
    #pragma unroll
    for (int o = 16; o > 0; o >>= 1) {
        s  += __shfl_xor_sync(0xffffffffu, s,  o);
        s2 += __shfl_xor_sync(0xffffffffu, s2, o);
    }
    float mu = s * (1.f/256.f);
    float var = s2 * (1.f/256.f) - mu*mu;
    float rstd = rsqrtf(var + 1e-5f);

    const float4* gp = (const float4*)g;
    const float4* tp = (const float4*)bta;
    float4 g0 = gp[lane], g1 = gp[lane+32];
    float4 t0 = tp[lane], t1 = tp[lane+32];
    float4 o0, o1;
    o0.x = (v[0]-mu)*rstd*g0.x + t0.x;
    o0.y = (v[1]-mu)*rstd*g0.y + t0.y;
    o0.z = (v[2]-mu)*rstd*g0.z + t0.z;
    o0.w = (v[3]-mu)*rstd*g0.w + t0.w;
    o1.x = (v[4]-mu)*rstd*g1.x + t1.x;
    o1.y = (v[5]-mu)*rstd*g1.y + t1.y;
    o1.z = (v[6]-mu)*rstd*g1.z + t1.z;
    o1.w = (v[7]-mu)*rstd*g1.w + t1.w;
    float4* op = (float4*)(out + base);
    op[lane]      = o0;
    op[lane + 32] = o1;
}

// ---------------- final: LN cls row only + 2-layer head ----------------------
__global__ void head_kernel(const float* __restrict__ g,
                            const float* __restrict__ bta,
                            const float* __restrict__ Wh1,
                            const float* __restrict__ bh1,
                            const float* __restrict__ Wh2,
                            const float* __restrict__ bh2,
                            float* __restrict__ out)
{
    int b = blockIdx.x;
    int d = threadIdx.x;
    float v = g_x[(size_t)b*SLEN*D + d];

    float s = v, s2 = v*v;
    #pragma unroll
    for (int o = 16; o > 0; o >>= 1) {
        s  += __shfl_xor_sync(0xffffffffu, s,  o);
        s2 += __shfl_xor_sync(0xffffffffu, s2, o);
    }
    __shared__ float ws[8], ws2[8];
    __shared__ float mu_s, rstd_s;
    int w = d >> 5;
    if ((d & 31) == 0) { ws[w] = s; ws2[w] = s2; }
    __syncthreads();
    if (d == 0) {
        float S1 = 0.f, S2 = 0.f;
        #pragma unroll
        for (int i = 0; i < 8; i++) { S1 += ws[i]; S2 += ws2[i]; }
        float mu = S1 * (1.f/256.f);
        float var = S2 * (1.f/256.f) - mu*mu;
        mu_s = mu;
        rstd_s = rsqrtf(var + 1e-5f);
    }
    __syncthreads();

    __shared__ float clsr[256];
    __shared__ float hid[256];
    float c = (v - mu_s) * rstd_s * g[d] + bta[d];
    clsr[d] = c;
    out[b*D + d] = c;                       // cls_out
    __syncthreads();

    float hsum = bh1[d];
    #pragma unroll 8
    for (int k = 0; k < 256; k++) hsum = fmaf(clsr[k], Wh1[k*256 + d], hsum);
    hid[d] = fmaxf(hsum, 0.f);
    __syncthreads();

    if (d < 2) {
        float lg = bh2[d];
        for (int k = 0; k < 256; k++) lg = fmaf(hid[k], Wh2[k*2 + d], lg);
        out[BB*D + b*2 + d] = lg;           // logits after cls_out block
    }
}

// ---------------- launcher ---------------------------------------------------
extern "C" void kernel_launch(void* const* d_in, const int* in_sizes, int n_in,
                              void* d_out, int out_size)
{
    (void)in_sizes; (void)n_in; (void)out_size;

    const float* cf   = (const float*)d_in[0];
    const int*   xc   = (const int*)  d_in[1];
    const int*   yc   = (const int*)  d_in[2];
    const float* Wemb = (const float*)d_in[3];
    const float* bemb = (const float*)d_in[4];
    const float* Wct1 = (const float*)d_in[5];
    const float* bct1 = (const float*)d_in[6];
    const float* Wct2 = (const float*)d_in[7];
    const float* bct2 = (const float*)d_in[8];
    const float* cls  = (const float*)d_in[9];
    const float* Wq = (const float*)d_in[10]; const float* bq = (const float*)d_in[11];
    const float* Wk = (const float*)d_in[12]; const float* bk = (const float*)d_in[13];
    const float* Wv = (const float*)d_in[14]; const float* bv = (const float*)d_in[15];
    const float* Wo = (const float*)d_in[16]; const float* bo = (const float*)d_in[17];
    const float* ln1g = (const float*)d_in[18]; const float* ln1b = (const float*)d_in[19];
    const float* ln2g = (const float*)d_in[20]; const float* ln2b = (const float*)d_in[21];
    const float* Wf1 = (const float*)d_in[22]; const float* bf1 = (const float*)d_in[23];
    const float* Wf2 = (const float*)d_in[24]; const float* bf2 = (const float*)d_in[25];
    const float* lnfg = (const float*)d_in[26]; const float* lnfb = (const float*)d_in[27];
    const float* Wh1 = (const float*)d_in[28]; const float* bh1 = (const float*)d_in[29];
    const float* Wh2 = (const float*)d_in[30]; const float* bh2 = (const float*)d_in[31];
    float* out = (float*)d_out;

    void* p;
    cudaGetSymbolAddress(&p, g_x); float* xb = (float*)p;
    cudaGetSymbolAddress(&p, g_q); float* qb = (float*)p;
    cudaGetSymbolAddress(&p, g_k); float* kb = (float*)p;
    cudaGetSymbolAddress(&p, g_v); float* vb = (float*)p;
    cudaGetSymbolAddress(&p, g_a); float* ab = (float*)p;
    cudaGetSymbolAddress(&p, g_t); float* tb = (float*)p;
    cudaGetSymbolAddress(&p, g_h); float* hb = (float*)p;

    embed_kernel<<<MTOK, 256>>>(cf, xc, yc, Wemb, bemb, Wct1, bct1, Wct2, bct2, cls);

    dim3 gqkv((MTOK + 63)/64, D/64, 3);    // 129 x 4 x 3
    dim3 g256((MTOK + 63)/64, D/64);       // 129 x 4
    dim3 gff ((MTOK + 63)/64, DFF/64);     // 129 x 16
    dim3 gattn((SLEN + 127)/128, NH, BB);  // 9 x 8 x 8
    int lngrid = MTOK / 8;                 // 1025

    for (int l = 0; l < NL; l++) {
        size_t wo = (size_t)l*D*D;
        qkv_kernel<<<gqkv, 128>>>(xb, Wq + wo, Wk + wo, Wv + wo,
                                  bq + l*D, bk + l*D, bv + l*D, qb, kb, vb);
        attn_kernel<<<gattn, 256>>>();
        gemm_kernel<<<g256, 128>>>(ab, Wo + wo, bo + l*D, tb, MTOK, D, D, 0);
        ln_kernel<<<lngrid, 256>>>(xb, tb, ln1g + l*D, ln1b + l*D, xb);
        gemm_kernel<<<gff, 128>>>(xb, Wf1 + (size_t)l*D*DFF, bf1 + l*DFF, hb, MTOK, DFF, D, 1);
        gemm_kernel<<<g256, 128>>>(hb, Wf2 + (size_t)l*DFF*D, bf2 + l*D, tb, MTOK, D, DFF, 0);
        ln_kernel<<<lngrid, 256>>>(xb, tb, ln2g + l*D, ln2b + l*D, xb);
    }

    head_kernel<<<BB, 256>>>(lnfg, lnfb, Wh1, bh1, Wh2, bh2, out);
}

// round 12
// speedup vs baseline: 1.6065x; 1.1397x over previous
#include <cuda_runtime.h>
#include <cuda_bf16.h>
#include <math.h>
#include <stdint.h>

#define BB   8
#define NCELL 1024
#define SLEN 1025
#define D    256
#define NH   8
#define HD   32
#define DFF  1024
#define NL   4
#define MTOK (BB*SLEN)   // 8200

typedef unsigned long long u64;

// packed f32x2 helpers (attention kernel)
#define FMA2(acc, a, b) \
    asm("fma.rn.f32x2 %0, %1, %2, %0;" : "+l"(acc) : "l"(a), "l"(b))
#define MUL2(d, a, b) \
    asm("mul.rn.f32x2 %0, %1, %2;" : "=l"(d) : "l"(a), "l"(b))
#define PACK2(d, lo, hi) \
    asm("mov.b64 %0, {%1, %2};" : "=l"(d) : "f"(lo), "f"(hi))
#define UNPACK2(lo, hi, s) \
    asm("mov.b64 {%0, %1}, %2;" : "=f"(lo), "=f"(hi) : "l"(s))

// cp.async helper: 16B global->shared, zero-fill when sz==0
#define CPA16(dst, src, sz) \
    asm volatile("cp.async.cg.shared.global [%0], [%1], 16, %2;" \
        :: "r"((uint32_t)__cvta_generic_to_shared(dst)), "l"(src), "r"(sz))

// bf16 tensor-core mma: D(f32) += A(bf16) * B(bf16)
#define MMA_BF16(c, a, b) \
    asm volatile("mma.sync.aligned.m16n8k16.row.col.f32.bf16.bf16.f32 " \
        "{%0,%1,%2,%3}, {%4,%5,%6,%7}, {%8,%9}, {%0,%1,%2,%3};" \
        : "+f"((c)[0]), "+f"((c)[1]), "+f"((c)[2]), "+f"((c)[3]) \
        : "r"((a)[0]), "r"((a)[1]), "r"((a)[2]), "r"((a)[3]), \
          "r"((b)[0]), "r"((b)[1]))

// ---------------- scratch (static device globals; no allocs) ----------------
__device__ float g_x[MTOK*D];
__device__ float g_q[MTOK*D];
__device__ float g_k[MTOK*D];
__device__ float g_v[MTOK*D];
__device__ float g_t[MTOK*D];

// bf16 hi/lo split activations
__device__ __nv_bfloat16 g_xh[MTOK*D],  g_xl[MTOK*D];
__device__ __nv_bfloat16 g_ah[MTOK*D],  g_al[MTOK*D];
__device__ __nv_bfloat16 g_hh[(size_t)MTOK*DFF], g_hl[(size_t)MTOK*DFF];

// bf16 hi/lo split transposed weights [N][K]
// layout: qkv (NL*3*D*D), wo (NL*D*D), f1 (NL*D*DFF), f2 (NL*D*DFF)
#define WOFF_WO  (12*D*D)
#define WOFF_F1  (16*D*D)
#define WOFF_F2  (WOFF_F1 + 4*D*DFF)
#define WT_TOTAL (WOFF_F2 + 4*D*DFF)
__device__ __nv_bfloat16 g_wth[WT_TOTAL], g_wtl[WT_TOTAL];

__device__ __forceinline__ __nv_bfloat162 bsplit2(float a, float b, __nv_bfloat162* lo)
{
    __nv_bfloat16 ha = __float2bfloat16_rn(a);
    __nv_bfloat16 hb = __float2bfloat16_rn(b);
    lo->x = __float2bfloat16_rn(a - __bfloat162float(ha));
    lo->y = __float2bfloat16_rn(b - __bfloat162float(hb));
    __nv_bfloat162 hi; hi.x = ha; hi.y = hb;
    return hi;
}

// ---------------- embedding: emb + cell-type MLP + positional + cls ----------
__global__ void embed_kernel(const float* __restrict__ cf,
                             const int* __restrict__ xc,
                             const int* __restrict__ yc,
                             const float* __restrict__ Wemb,
                             const float* __restrict__ bemb,
                             const float* __restrict__ Wct1,
                             const float* __restrict__ bct1,
                             const float* __restrict__ Wct2,
                             const float* __restrict__ bct2,
                             const float* __restrict__ cls)
{
    int blk = blockIdx.x;          // 0..8199
    int b = blk / SLEN;
    int s = blk % SLEN;
    int d = threadIdx.x;           // 0..255
    float* out = g_x + (size_t)blk * D;

    float val;
    if (s == 0) {
        val = cls[d];
    } else {
        int n = s - 1;
        __shared__ float cfs[64];
        __shared__ float hs[128];
        const float* cfp = cf + ((size_t)b*NCELL + n)*64;
        if (d < 64) cfs[d] = cfp[d];
        __syncthreads();

        if (d < 128) {
            float acc = bct1[d];
            #pragma unroll
            for (int k = 0; k < 64; k++) acc = fmaf(cfs[k], Wct1[k*128 + d], acc);
            hs[d] = fmaxf(acc, 0.f);
        }
        __syncthreads();

        float e = bemb[d];
        #pragma unroll
        for (int k = 0; k < 64; k++) e = fmaf(cfs[k], Wemb[k*256 + d], e);
        float c2 = bct2[d];
        #pragma unroll
        for (int j = 0; j < 128; j++) c2 = fmaf(hs[j], Wct2[j*256 + d], c2);

        int dd    = (d < 128) ? d : d - 128;
        int coord = (d < 128) ? xc[b*NCELL + n] : yc[b*NCELL + n];
        coord = min(max(coord, 0), 999);
        int m = dd >> 1;
        const float c1 = -0.07195578739046225f;  // float(-ln(10000)/128)
        float dv  = expf((float)(2*m) * c1);
        float ang = (float)coord * dv;
        float p   = (dd & 1) ? cosf(ang) : sinf(ang);
        val = e + c2 + p;
    }

    out[d] = val;
    __nv_bfloat16 hh = __float2bfloat16_rn(val);
    g_xh[(size_t)blk*D + d] = hh;
    g_xl[(size_t)blk*D + d] = __float2bfloat16_rn(val - __bfloat162float(hh));
}

// ---------------- weight convert: W[K][N] f32 -> Wt[N][K] bf16 hi/lo ---------
__global__ void wconv_kernel(const float* __restrict__ src,
                             __nv_bfloat16* __restrict__ dh,
                             __nv_bfloat16* __restrict__ dl,
                             int K, int N, int srcStride, int dstStride)
{
    int l = blockIdx.y;
    int idx = blockIdx.x*256 + threadIdx.x;
    int n = idx / K;
    int k = idx - n*K;
    float v = src[(size_t)l*srcStride + (size_t)k*N + n];
    __nv_bfloat16 h = __float2bfloat16_rn(v);
    dh[(size_t)l*dstStride + idx] = h;
    dl[(size_t)l*dstStride + idx] = __float2bfloat16_rn(v - __bfloat162float(h));
}

// ---- bf16x3 tensor-core GEMM: C = A@W + bias; BM=BN=64 BK=32, 128 thr -------
// A: [M][K] bf16 hi/lo, W: [N][K] bf16 hi/lo (transposed).
// Out: f32 Cf OR bf16-split (Ch, Cl). relu applied before split.
__device__ __forceinline__
void mma_body(const __nv_bfloat16* __restrict__ Agh,
              const __nv_bfloat16* __restrict__ Agl,
              const __nv_bfloat16* __restrict__ Bgh,
              const __nv_bfloat16* __restrict__ Bgl,
              const float* __restrict__ bias,
              float* __restrict__ Cf,
              __nv_bfloat16* __restrict__ Ch,
              __nv_bfloat16* __restrict__ Cl,
              int M, int N, int K, int relu, int bx, int by)
{
    __shared__ __nv_bfloat16 Ahs[2][64][40], Als[2][64][40];
    __shared__ __nv_bfloat16 Bhs[2][64][40], Bls[2][64][40];

    int tid  = threadIdx.x;        // 0..127
    int lane = tid & 31;
    int wid  = tid >> 5;
    int m0 = bx * 64, n0 = by * 64;
    int g = lane >> 2, t = lane & 3;
    int mw = (wid & 1) * 32;
    int nw = (wid >> 1) * 32;

    // tile-load mapping: 1 row (32 bf16) per 2 threads, 2 16B chunks each
    int lr = tid >> 1;             // 0..63
    int lc = (tid & 1) * 16;       // 0 or 16 (bf16 offset)

    int gr = m0 + lr;
    int szA = (gr < M) ? 16 : 0;
    int cr  = min(gr, M-1);
    const __nv_bfloat16* pAh = Agh + (size_t)cr*K + lc;
    const __nv_bfloat16* pAl = Agl + (size_t)cr*K + lc;
    const __nv_bfloat16* pBh = Bgh + (size_t)(n0 + lr)*K + lc;
    const __nv_bfloat16* pBl = Bgl + (size_t)(n0 + lr)*K + lc;

    float acc[2][4][4];
    #pragma unroll
    for (int mt = 0; mt < 2; mt++)
        #pragma unroll
        for (int nt = 0; nt < 4; nt++)
            #pragma unroll
            for (int i = 0; i < 4; i++) acc[mt][nt][i] = 0.f;

#define ISSUE_TILE(buf, kt) do { \
    int _k0 = (kt)*32; \
    CPA16(&Ahs[buf][lr][lc],   pAh + _k0,     szA); \
    CPA16(&Ahs[buf][lr][lc+8], pAh + _k0 + 8, szA); \
    CPA16(&Als[buf][lr][lc],   pAl + _k0,     szA); \
    CPA16(&Als[buf][lr][lc+8], pAl + _k0 + 8, szA); \
    CPA16(&Bhs[buf][lr][lc],   pBh + _k0,     16); \
    CPA16(&Bhs[buf][lr][lc+8], pBh + _k0 + 8, 16); \
    CPA16(&Bls[buf][lr][lc],   pBl + _k0,     16); \
    CPA16(&Bls[buf][lr][lc+8], pBl + _k0 + 8, 16); \
    asm volatile("cp.async.commit_group;"); \
} while (0)

    ISSUE_TILE(0, 0);

    int KT = K >> 5;
    for (int kt = 0; kt < KT; kt++) {
        int cur = kt & 1;
        if (kt + 1 < KT) {
            ISSUE_TILE(cur ^ 1, kt + 1);
            asm volatile("cp.async.wait_group 1;");
        } else {
            asm volatile("cp.async.wait_group 0;");
        }
        __syncthreads();

        #pragma unroll
        for (int ks8 = 0; ks8 < 2; ks8++) {
            int ks = ks8 * 16;
            uint32_t ah[2][4], al[2][4], bh[4][2], bl[4][2];
            #pragma unroll
            for (int mt = 0; mt < 2; mt++) {
                int rb = mw + mt*16;
                ah[mt][0] = *(const uint32_t*)&Ahs[cur][rb+g  ][ks+2*t];
                ah[mt][1] = *(const uint32_t*)&Ahs[cur][rb+g+8][ks+2*t];
                ah[mt][2] = *(const uint32_t*)&Ahs[cur][rb+g  ][ks+2*t+8];
                ah[mt][3] = *(const uint32_t*)&Ahs[cur][rb+g+8][ks+2*t+8];
                al[mt][0] = *(const uint32_t*)&Als[cur][rb+g  ][ks+2*t];
                al[mt][1] = *(const uint32_t*)&Als[cur][rb+g+8][ks+2*t];
                al[mt][2] = *(const uint32_t*)&Als[cur][rb+g  ][ks+2*t+8];
                al[mt][3] = *(const uint32_t*)&Als[cur][rb+g+8][ks+2*t+8];
            }
            #pragma unroll
            for (int nt = 0; nt < 4; nt++) {
                int nb = nw + nt*8;
                bh[nt][0] = *(const uint32_t*)&Bhs[cur][nb+g][ks+2*t];
                bh[nt][1] = *(const uint32_t*)&Bhs[cur][nb+g][ks+2*t+8];
                bl[nt][0] = *(const uint32_t*)&Bls[cur][nb+g][ks+2*t];
                bl[nt][1] = *(const uint32_t*)&Bls[cur][nb+g][ks+2*t+8];
            }
            #pragma unroll
            for (int mt = 0; mt < 2; mt++) {
                #pragma unroll
                for (int nt = 0; nt < 4; nt++) {
                    MMA_BF16(acc[mt][nt], ah[mt], bh[nt]);
                    MMA_BF16(acc[mt][nt], ah[mt], bl[nt]);
                    MMA_BF16(acc[mt][nt], al[mt], bh[nt]);
                }
            }
        }
        __syncthreads();
    }
#undef ISSUE_TILE

    // epilogue
    #pragma unroll
    for (int mt = 0; mt < 2; mt++) {
        #pragma unroll
        for (int nt = 0; nt < 4; nt++) {
            int col = n0 + nw + nt*8 + 2*t;
            float b0v = bias[col], b1v = bias[col+1];
            int r0 = m0 + mw + mt*16 + g;
            int r1 = r0 + 8;
            float v00 = acc[mt][nt][0] + b0v, v01 = acc[mt][nt][1] + b1v;
            float v10 = acc[mt][nt][2] + b0v, v11 = acc[mt][nt][3] + b1v;
            if (relu) {
                v00 = fmaxf(v00, 0.f); v01 = fmaxf(v01, 0.f);
                v10 = fmaxf(v10, 0.f); v11 = fmaxf(v11, 0.f);
            }
            if (Cf) {
                if (r0 < M) { float2 o = {v00, v01}; *(float2*)(Cf + (size_t)r0*N + col) = o; }
                if (r1 < M) { float2 o = {v10, v11}; *(float2*)(Cf + (size_t)r1*N + col) = o; }
            } else {
                if (r0 < M) {
                    __nv_bfloat162 lo; __nv_bfloat162 hi = bsplit2(v00, v01, &lo);
                    *(__nv_bfloat162*)(Ch + (size_t)r0*N + col) = hi;
                    *(__nv_bfloat162*)(Cl + (size_t)r0*N + col) = lo;
                }
                if (r1 < M) {
                    __nv_bfloat162 lo; __nv_bfloat162 hi = bsplit2(v10, v11, &lo);
                    *(__nv_bfloat162*)(Ch + (size_t)r1*N + col) = hi;
                    *(__nv_bfloat162*)(Cl + (size_t)r1*N + col) = lo;
                }
            }
        }
    }
}

__global__ __launch_bounds__(128, 4)
void mma_gemm(const __nv_bfloat16* __restrict__ Agh,
              const __nv_bfloat16* __restrict__ Agl,
              const __nv_bfloat16* __restrict__ Bgh,
              const __nv_bfloat16* __restrict__ Bgl,
              const float* __restrict__ bias,
              float* __restrict__ Cf,
              __nv_bfloat16* __restrict__ Ch,
              __nv_bfloat16* __restrict__ Cl,
              int M, int N, int K, int relu)
{
    mma_body(Agh, Agl, Bgh, Bgl, bias, Cf, Ch, Cl, M, N, K, relu,
             blockIdx.x, blockIdx.y);
}

// fused QKV: grid.z selects weight slot / bias / output
__global__ __launch_bounds__(128, 4)
void qkv_mma(const __nv_bfloat16* __restrict__ xh,
             const __nv_bfloat16* __restrict__ xl,
             const __nv_bfloat16* __restrict__ wth,   // + l*3*D*D already
             const __nv_bfloat16* __restrict__ wtl,
             const float* __restrict__ bq,
             const float* __restrict__ bk,
             const float* __restrict__ bv,
             float* __restrict__ Q,
             float* __restrict__ Ko,
             float* __restrict__ V)
{
    int z = blockIdx.z;
    const __nv_bfloat16* bh = wth + (size_t)z*D*D;
    const __nv_bfloat16* bl = wtl + (size_t)z*D*D;
    const float* bias = (z == 0) ? bq : (z == 1) ? bk : bv;
    float* C          = (z == 0) ? Q  : (z == 1) ? Ko : V;
    mma_body(xh, xl, bh, bl, bias, C, nullptr, nullptr, MTOK, D, D, 0,
             blockIdx.x, blockIdx.y);
}

// ---------------- flash attention: q-tile 128, cp.async dbuf, f32x2 math -----
__device__ __forceinline__ void attn_issue_tile(
    const float* kbase, const float* vbase,
    float (*ks)[64][36], float (*vs)[64][36],
    int buf, int t, int row0, int c4)
{
    int k0  = t * 64;
    int gk0 = k0 + row0;
    int gk1 = gk0 + 32;
    int s0 = (gk0 < SLEN) ? 16 : 0;
    int s1 = (gk1 < SLEN) ? 16 : 0;
    int ck0 = min(gk0, SLEN-1);
    int ck1 = min(gk1, SLEN-1);
    CPA16(&ks[buf][row0   ][c4], kbase + (size_t)ck0*D + c4, s0);
    CPA16(&ks[buf][row0+32][c4], kbase + (size_t)ck1*D + c4, s1);
    CPA16(&vs[buf][row0   ][c4], vbase + (size_t)ck0*D + c4, s0);
    CPA16(&vs[buf][row0+32][c4], vbase + (size_t)ck1*D + c4, s1);
    asm volatile("cp.async.commit_group;");
}

__global__ void attn_kernel()
{
    __shared__ float ks[2][64][36];
    __shared__ float vs[2][64][36];

    int qt = blockIdx.x;           // 0..8
    int h  = blockIdx.y;
    int b  = blockIdx.z;
    int tid = threadIdx.x;
    int rl  = tid >> 2;            // 0..63
    int sub = tid & 3;
    int q0r = qt*128 + rl;
    int q1r = q0r + 64;
    bool v0 = q0r < SLEN;
    bool v1 = q1r < SLEN;

    int row0 = tid >> 3;           // 0..31 (load mapping)
    int c4   = (tid & 7) << 2;

    const float scale = 0.17677669529663687f;   // 1/sqrt(32)
    const float* qbase = g_q + (size_t)b*SLEN*D + h*HD;
    const float* kbase = g_k + (size_t)b*SLEN*D + h*HD;
    const float* vbase = g_v + (size_t)b*SLEN*D + h*HD;

    u64 qp0[16], qp1[16];
    #pragma unroll
    for (int d4 = 0; d4 < 8; d4++) {
        float4 t0 = make_float4(0.f,0.f,0.f,0.f);
        float4 t1 = make_float4(0.f,0.f,0.f,0.f);
        if (v0) t0 = *(const float4*)(qbase + (size_t)q0r*D + d4*4);
        if (v1) t1 = *(const float4*)(qbase + (size_t)q1r*D + d4*4);
        PACK2(qp0[2*d4+0], t0.x*scale, t0.y*scale);
        PACK2(qp0[2*d4+1], t0.z*scale, t0.w*scale);
        PACK2(qp1[2*d4+0], t1.x*scale, t1.y*scale);
        PACK2(qp1[2*d4+1], t1.z*scale, t1.w*scale);
    }

    float m0 = -INFINITY, m1 = -INFINITY, l0 = 0.f, l1 = 0.f;
    u64 accp0[16], accp1[16];
    #pragma unroll
    for (int i = 0; i < 16; i++) { accp0[i] = 0ull; accp1[i] = 0ull; }

    const int ntiles = (SLEN + 63) / 64;   // 17

    attn_issue_tile(kbase, vbase, ks, vs, 0, 0, row0, c4);

    for (int t = 0; t < ntiles; t++) {
        int cur = t & 1;
        int k0 = t*64;
        if (t + 1 < ntiles) {
            attn_issue_tile(kbase, vbase, ks, vs, cur ^ 1, t + 1, row0, c4);
            asm volatile("cp.async.wait_group 1;");
        } else {
            asm volatile("cp.async.wait_group 0;");
        }
        __syncthreads();

        float p0[16], p1[16];
        float t0 = -INFINITY, t1 = -INFINITY;
        #pragma unroll
        for (int j = 0; j < 16; j++) {
            int cl = 4*j + sub;
            float s0, s1;
            if (k0 + cl < SLEN) {
                u64 s0a = 0ull, s1a = 0ull;
                #pragma unroll
                for (int d4 = 0; d4 < 8; d4++) {
                    union { float4 f; u64 u[2]; } kv;
                    kv.f = *(const float4*)&ks[cur][cl][d4*4];
                    FMA2(s0a, qp0[2*d4+0], kv.u[0]);
                    FMA2(s0a, qp0[2*d4+1], kv.u[1]);
                    FMA2(s1a, qp1[2*d4+0], kv.u[0]);
                    FMA2(s1a, qp1[2*d4+1], kv.u[1]);
                }
                float lo, hi;
                UNPACK2(lo, hi, s0a); s0 = lo + hi;
                UNPACK2(lo, hi, s1a); s1 = lo + hi;
            } else { s0 = -INFINITY; s1 = -INFINITY; }
            p0[j] = s0; p1[j] = s1;
            t0 = fmaxf(t0, s0); t1 = fmaxf(t1, s1);
        }
        t0 = fmaxf(t0, __shfl_xor_sync(0xffffffffu, t0, 1));
        t0 = fmaxf(t0, __shfl_xor_sync(0xffffffffu, t0, 2));
        t1 = fmaxf(t1, __shfl_xor_sync(0xffffffffu, t1, 1));
        t1 = fmaxf(t1, __shfl_xor_sync(0xffffffffu, t1, 2));

        float mn0 = fmaxf(m0, t0), mn1 = fmaxf(m1, t1);
        float cr0 = __expf(m0 - mn0), cr1 = __expf(m1 - mn1);
        l0 *= cr0; l1 *= cr1;
        u64 ccr0, ccr1;
        PACK2(ccr0, cr0, cr0);
        PACK2(ccr1, cr1, cr1);
        #pragma unroll
        for (int i = 0; i < 16; i++) {
            MUL2(accp0[i], accp0[i], ccr0);
            MUL2(accp1[i], accp1[i], ccr1);
        }

        float ls0 = 0.f, ls1 = 0.f;
        #pragma unroll
        for (int j = 0; j < 16; j++) {
            p0[j] = __expf(p0[j] - mn0); ls0 += p0[j];
            p1[j] = __expf(p1[j] - mn1); ls1 += p1[j];
        }
        l0 += ls0; l1 += ls1;

        #pragma unroll
        for (int j = 0; j < 16; j++) {
            int cl = 4*j + sub;
            u64 pp0, pp1;
            PACK2(pp0, p0[j], p0[j]);
            PACK2(pp1, p1[j], p1[j]);
            #pragma unroll
            for (int d4 = 0; d4 < 8; d4++) {
                union { float4 f; u64 u[2]; } vv;
                vv.f = *(const float4*)&vs[cur][cl][d4*4];
                FMA2(accp0[2*d4+0], pp0, vv.u[0]);
                FMA2(accp0[2*d4+1], pp0, vv.u[1]);
                FMA2(accp1[2*d4+0], pp1, vv.u[0]);
                FMA2(accp1[2*d4+1], pp1, vv.u[1]);
            }
        }
        m0 = mn0; m1 = mn1;
        __syncthreads();
    }

    float acc0[HD], acc1[HD];
    #pragma unroll
    for (int i = 0; i < 16; i++) {
        UNPACK2(acc0[2*i], acc0[2*i+1], accp0[i]);
        UNPACK2(acc1[2*i], acc1[2*i+1], accp1[i]);
    }

    l0 += __shfl_xor_sync(0xffffffffu, l0, 1);
    l0 += __shfl_xor_sync(0xffffffffu, l0, 2);
    l1 += __shfl_xor_sync(0xffffffffu, l1, 1);
    l1 += __shfl_xor_sync(0xffffffffu, l1, 2);
    #pragma unroll
    for (int d = 0; d < HD; d++) {
        acc0[d] += __shfl_xor_sync(0xffffffffu, acc0[d], 1);
        acc0[d] += __shfl_xor_sync(0xffffffffu, acc0[d], 2);
        acc1[d] += __shfl_xor_sync(0xffffffffu, acc1[d], 1);
        acc1[d] += __shfl_xor_sync(0xffffffffu, acc1[d], 2);
    }

    // epilogue: write bf16 hi/lo split (consumed only by Wo mma GEMM)
    if (sub == 0) {
        if (v0) {
            float inv = 1.f / l0;
            size_t base = ((size_t)b*SLEN + q0r)*D + h*HD;
            #pragma unroll
            for (int d2 = 0; d2 < 16; d2++) {
                __nv_bfloat162 lo;
                __nv_bfloat162 hi = bsplit2(acc0[2*d2]*inv, acc0[2*d2+1]*inv, &lo);
                *(__nv_bfloat162*)(g_ah + base + 2*d2) = hi;
                *(__nv_bfloat162*)(g_al + base + 2*d2) = lo;
            }
        }
        if (v1) {
            float inv = 1.f / l1;
            size_t base = ((size_t)b*SLEN + q1r)*D + h*HD;
            #pragma unroll
            for (int d2 = 0; d2 < 16; d2++) {
                __nv_bfloat162 lo;
                __nv_bfloat162 hi = bsplit2(acc1[2*d2]*inv, acc1[2*d2+1]*inv, &lo);
                *(__nv_bfloat162*)(g_ah + base + 2*d2) = hi;
                *(__nv_bfloat162*)(g_al + base + 2*d2) = lo;
            }
        }
    }
}

// ---------- fused residual + LayerNorm, warp-per-row; f32 + bf16-split out ---
__global__ void ln_kernel(const float* __restrict__ A,
                          const float* __restrict__ Bsrc,
                          const float* __restrict__ g,
                          const float* __restrict__ bta,
                          float* __restrict__ out,
                          __nv_bfloat16* __restrict__ oh,
                          __nv_bfloat16* __restrict__ ol)
{
    int warp = threadIdx.x >> 5;
    int lane = threadIdx.x & 31;
    int row = blockIdx.x * 8 + warp;
    size_t base = (size_t)row * D;

    const float4* ap = (const float4*)(A + base);
    const float4* bp = (const float4*)(Bsrc + base);
    float4 a0 = ap[lane], a1 = ap[lane + 32];
    float4 b0 = bp[lane], b1 = bp[lane + 32];
    float v[8];
    v[0]=a0.x+b0.x; v[1]=a0.y+b0.y; v[2]=a0.z+b0.z; v[3]=a0.w+b0.w;
    v[4]=a1.x+b1.x; v[5]=a1.y+b1.y; v[6]=a1.z+b1.z; v[7]=a1.w+b1.w;

    float s = 0.f, s2 = 0.f;
    #pragma unroll
    for (int i = 0; i < 8; i++) { s += v[i]; s2 = fmaf(v[i], v[i], s2); }
    #pragma unroll
    for (int o = 16; o > 0; o >>= 1) {
        s  += __shfl_xor_sync(0xffffffffu, s,  o);
        s2 += __shfl_xor_sync(0xffffffffu, s2, o);
    }
    float mu = s * (1.f/256.f);
    float var = s2 * (1.f/256.f) - mu*mu;
    float rstd = rsqrtf(var + 1e-5f);

    const float4* gp = (const float4*)g;
    const float4* tp = (const float4*)bta;
    float4 g0 = gp[lane], g1 = gp[lane+32];
    float4 t0 = tp[lane], t1 = tp[lane+32];
    float4 o0, o1;
    o0.x = (v[0]-mu)*rstd*g0.x + t0.x;
    o0.y = (v[1]-mu)*rstd*g0.y + t0.y;
    o0.z = (v[2]-mu)*rstd*g0.z + t0.z;
    o0.w = (v[3]-mu)*rstd*g0.w + t0.w;
    o1.x = (v[4]-mu)*rstd*g1.x + t1.x;
    o1.y = (v[5]-mu)*rstd*g1.y + t1.y;
    o1.z = (v[6]-mu)*rstd*g1.z + t1.z;
    o1.w = (v[7]-mu)*rstd*g1.w + t1.w;
    float4* op = (float4*)(out + base);
    op[lane]      = o0;
    op[lane + 32] = o1;

    size_t e0 = base + (size_t)lane*4;
    size_t e1 = base + (size_t)(lane+32)*4;
    __nv_bfloat162 lo, hi;
    hi = bsplit2(o0.x, o0.y, &lo);
    *(__nv_bfloat162*)(oh + e0)     = hi; *(__nv_bfloat162*)(ol + e0)     = lo;
    hi = bsplit2(o0.z, o0.w, &lo);
    *(__nv_bfloat162*)(oh + e0 + 2) = hi; *(__nv_bfloat162*)(ol + e0 + 2) = lo;
    hi = bsplit2(o1.x, o1.y, &lo);
    *(__nv_bfloat162*)(oh + e1)     = hi; *(__nv_bfloat162*)(ol + e1)     = lo;
    hi = bsplit2(o1.z, o1.w, &lo);
    *(__nv_bfloat162*)(oh + e1 + 2) = hi; *(__nv_bfloat162*)(ol + e1 + 2) = lo;
}

// ---------------- final: LN cls row only + 2-layer head ----------------------
__global__ void head_kernel(const float* __restrict__ g,
                            const float* __restrict__ bta,
                            const float* __restrict__ Wh1,
                            const float* __restrict__ bh1,
                            const float* __restrict__ Wh2,
                            const float* __restrict__ bh2,
                            float* __restrict__ out)
{
    int b = blockIdx.x;
    int d = threadIdx.x;
    float v = g_x[(size_t)b*SLEN*D + d];

    float s = v, s2 = v*v;
    #pragma unroll
    for (int o = 16; o > 0; o >>= 1) {
        s  += __shfl_xor_sync(0xffffffffu, s,  o);
        s2 += __shfl_xor_sync(0xffffffffu, s2, o);
    }
    __shared__ float ws[8], ws2[8];
    __shared__ float mu_s, rstd_s;
    int w = d >> 5;
    if ((d & 31) == 0) { ws[w] = s; ws2[w] = s2; }
    __syncthreads();
    if (d == 0) {
        float S1 = 0.f, S2 = 0.f;
        #pragma unroll
        for (int i = 0; i < 8; i++) { S1 += ws[i]; S2 += ws2[i]; }
        float mu = S1 * (1.f/256.f);
        float var = S2 * (1.f/256.f) - mu*mu;
        mu_s = mu;
        rstd_s = rsqrtf(var + 1e-5f);
    }
    __syncthreads();

    __shared__ float clsr[256];
    __shared__ float hid[256];
    float c = (v - mu_s) * rstd_s * g[d] + bta[d];
    clsr[d] = c;
    out[b*D + d] = c;                       // cls_out
    __syncthreads();

    float hsum = bh1[d];
    #pragma unroll 8
    for (int k = 0; k < 256; k++) hsum = fmaf(clsr[k], Wh1[k*256 + d], hsum);
    hid[d] = fmaxf(hsum, 0.f);
    __syncthreads();

    if (d < 2) {
        float lg = bh2[d];
        for (int k = 0; k < 256; k++) lg = fmaf(hid[k], Wh2[k*2 + d], lg);
        out[BB*D + b*2 + d] = lg;           // logits after cls_out block
    }
}

// ---------------- launcher ---------------------------------------------------
extern "C" void kernel_launch(void* const* d_in, const int* in_sizes, int n_in,
                              void* d_out, int out_size)
{
    (void)in_sizes; (void)n_in; (void)out_size;

    const float* cf   = (const float*)d_in[0];
    const int*   xc   = (const int*)  d_in[1];
    const int*   yc   = (const int*)  d_in[2];
    const float* Wemb = (const float*)d_in[3];
    const float* bemb = (const float*)d_in[4];
    const float* Wct1 = (const float*)d_in[5];
    const float* bct1 = (const float*)d_in[6];
    const float* Wct2 = (const float*)d_in[7];
    const float* bct2 = (const float*)d_in[8];
    const float* cls  = (const float*)d_in[9];
    const float* Wq = (const float*)d_in[10]; const float* bq = (const float*)d_in[11];
    const float* Wk = (const float*)d_in[12]; const float* bk = (const float*)d_in[13];
    const float* Wv = (const float*)d_in[14]; const float* bv = (const float*)d_in[15];
    const float* Wo = (const float*)d_in[16]; const float* bo = (const float*)d_in[17];
    const float* ln1g = (const float*)d_in[18]; const float* ln1b = (const float*)d_in[19];
    const float* ln2g = (const float*)d_in[20]; const float* ln2b = (const float*)d_in[21];
    const float* Wf1 = (const float*)d_in[22]; const float* bf1 = (const float*)d_in[23];
    const float* Wf2 = (const float*)d_in[24]; const float* bf2 = (const float*)d_in[25];
    const float* lnfg = (const float*)d_in[26]; const float* lnfb = (const float*)d_in[27];
    const float* Wh1 = (const float*)d_in[28]; const float* bh1 = (const float*)d_in[29];
    const float* Wh2 = (const float*)d_in[30]; const float* bh2 = (const float*)d_in[31];
    float* out = (float*)d_out;

    void* p;
    cudaGetSymbolAddress(&p, g_x);  float* xb = (float*)p;
    cudaGetSymbolAddress(&p, g_q);  float* qb = (float*)p;
    cudaGetSymbolAddress(&p, g_k);  float* kb = (float*)p;
    cudaGetSymbolAddress(&p, g_v);  float* vb = (float*)p;
    cudaGetSymbolAddress(&p, g_t);  float* tb = (float*)p;
    cudaGetSymbolAddress(&p, g_xh); __nv_bfloat16* xh = (__nv_bfloat16*)p;
    cudaGetSymbolAddress(&p, g_xl); __nv_bfloat16* xl = (__nv_bfloat16*)p;
    cudaGetSymbolAddress(&p, g_ah); __nv_bfloat16* ah = (__nv_bfloat16*)p;
    cudaGetSymbolAddress(&p, g_al); __nv_bfloat16* al = (__nv_bfloat16*)p;
    cudaGetSymbolAddress(&p, g_hh); __nv_bfloat16* hh = (__nv_bfloat16*)p;
    cudaGetSymbolAddress(&p, g_hl); __nv_bfloat16* hl = (__nv_bfloat16*)p;
    cudaGetSymbolAddress(&p, g_wth); __nv_bfloat16* wth = (__nv_bfloat16*)p;
    cudaGetSymbolAddress(&p, g_wtl); __nv_bfloat16* wtl = (__nv_bfloat16*)p;

    // upfront: weight split + transpose (all layers)
    {
        dim3 gdd((D*D)/256, NL);
        wconv_kernel<<<gdd, 256>>>(Wq, wth + 0,       wtl + 0,       D, D, D*D, 3*D*D);
        wconv_kernel<<<gdd, 256>>>(Wk, wth + D*D,     wtl + D*D,     D, D, D*D, 3*D*D);
        wconv_kernel<<<gdd, 256>>>(Wv, wth + 2*D*D,   wtl + 2*D*D,   D, D, D*D, 3*D*D);
        wconv_kernel<<<gdd, 256>>>(Wo, wth + WOFF_WO, wtl + WOFF_WO, D, D, D*D, D*D);
        dim3 gdf((D*DFF)/256, NL);
        wconv_kernel<<<gdf, 256>>>(Wf1, wth + WOFF_F1, wtl + WOFF_F1, D, DFF, D*DFF, D*DFF);
        wconv_kernel<<<gdf, 256>>>(Wf2, wth + WOFF_F2, wtl + WOFF_F2, DFF, D, D*DFF, D*DFF);
    }

    embed_kernel<<<MTOK, 256>>>(cf, xc, yc, Wemb, bemb, Wct1, bct1, Wct2, bct2, cls);

    int MB = (MTOK + 63) / 64;             // 129
    dim3 gqkv(MB, D/64, 3);                // 129 x 4 x 3
    dim3 gdd2(MB, D/64);                   // 129 x 4
    dim3 gff (MB, DFF/64);                 // 129 x 16
    dim3 gattn((SLEN + 127)/128, NH, BB);  // 9 x 8 x 8
    int lngrid = MTOK / 8;                 // 1025

    for (int l = 0; l < NL; l++) {
        qkv_mma<<<gqkv, 128>>>(xh, xl,
                               wth + (size_t)l*3*D*D, wtl + (size_t)l*3*D*D,
                               bq + l*D, bk + l*D, bv + l*D, qb, kb, vb);
        attn_kernel<<<gattn, 256>>>();
        mma_gemm<<<gdd2, 128>>>(ah, al,
                                wth + WOFF_WO + (size_t)l*D*D,
                                wtl + WOFF_WO + (size_t)l*D*D,
                                bo + l*D, tb, nullptr, nullptr, MTOK, D, D, 0);
        ln_kernel<<<lngrid, 256>>>(xb, tb, ln1g + l*D, ln1b + l*D, xb, xh, xl);
        mma_gemm<<<gff, 128>>>(xh, xl,
                               wth + WOFF_F1 + (size_t)l*D*DFF,
                               wtl + WOFF_F1 + (size_t)l*D*DFF,
                               bf1 + l*DFF, nullptr, hh, hl, MTOK, DFF, D, 1);
        mma_gemm<<<gdd2, 128>>>(hh, hl,
                                wth + WOFF_F2 + (size_t)l*D*DFF,
                                wtl + WOFF_F2 + (size_t)l*D*DFF,
                                bf2 + l*D, tb, nullptr, nullptr, MTOK, D, DFF, 0);
        ln_kernel<<<lngrid, 256>>>(xb, tb, ln2g + l*D, ln2b + l*D, xb, xh, xl);
    }

    head_kernel<<<BB, 256>>>(lnfg, lnfb, Wh1, bh1, Wh2, bh2, out);
}

// round 13
// speedup vs baseline: 2.5533x; 1.5894x over previous
#include <cuda_runtime.h>
#include <cuda_bf16.h>
#include <math.h>
#include <stdint.h>

#define BB   8
#define NCELL 1024
#define SLEN 1025
#define D    256
#define NH   8
#define HD   32
#define DFF  1024
#define NL   4
#define MTOK (BB*SLEN)   // 8200

// cp.async helper: 16B global->shared, zero-fill when sz==0
#define CPA16(dst, src, sz) \
    asm volatile("cp.async.cg.shared.global [%0], [%1], 16, %2;" \
        :: "r"((uint32_t)__cvta_generic_to_shared(dst)), "l"(src), "r"(sz))

// bf16 tensor-core mma: C(f32) += A(bf16) * B(bf16), m16n8k16 row.col
#define MMA_BF16(c, a, b) \
    asm volatile("mma.sync.aligned.m16n8k16.row.col.f32.bf16.bf16.f32 " \
        "{%0,%1,%2,%3}, {%4,%5,%6,%7}, {%8,%9}, {%0,%1,%2,%3};" \
        : "+f"((c)[0]), "+f"((c)[1]), "+f"((c)[2]), "+f"((c)[3]) \
        : "r"((a)[0]), "r"((a)[1]), "r"((a)[2]), "r"((a)[3]), \
          "r"((b)[0]), "r"((b)[1]))

#define LDSM4(d0,d1,d2,d3,a) \
    asm volatile("ldmatrix.sync.aligned.m8n8.x4.shared.b16 {%0,%1,%2,%3}, [%4];" \
        : "=r"(d0),"=r"(d1),"=r"(d2),"=r"(d3) : "r"(a))
#define LDSM4T(d0,d1,d2,d3,a) \
    asm volatile("ldmatrix.sync.aligned.m8n8.x4.trans.shared.b16 {%0,%1,%2,%3}, [%4];" \
        : "=r"(d0),"=r"(d1),"=r"(d2),"=r"(d3) : "r"(a))

#define CVTPK(d, hi, lo) \
    asm("cvt.rn.bf16x2.f32 %0, %1, %2;" : "=r"(d) : "f"(hi), "f"(lo))

__device__ __forceinline__ uint32_t sptr(const void* p) {
    return (uint32_t)__cvta_generic_to_shared(p);
}

// pack (p0,p1) -> bf16x2 hi word + bf16x2 residual word
__device__ __forceinline__ void psplit(float p0, float p1, uint32_t& hi, uint32_t& lo)
{
    CVTPK(hi, p1, p0);
    float f0 = __uint_as_float(hi << 16);
    float f1 = __uint_as_float(hi & 0xffff0000u);
    CVTPK(lo, p1 - f1, p0 - f0);
}

// ---------------- scratch (static device globals; no allocs) ----------------
__device__ float g_x[MTOK*D];
__device__ float g_t[MTOK*D];

// bf16 hi/lo split activations
__device__ __nv_bfloat16 g_xh[MTOK*D],  g_xl[MTOK*D];
__device__ __nv_bfloat16 g_ah[MTOK*D],  g_al[MTOK*D];
__device__ __nv_bfloat16 g_hh[(size_t)MTOK*DFF], g_hl[(size_t)MTOK*DFF];
__device__ __nv_bfloat16 g_qh[MTOK*D],  g_ql[MTOK*D];
__device__ __nv_bfloat16 g_kh[MTOK*D],  g_kl[MTOK*D];
__device__ __nv_bfloat16 g_vh[MTOK*D],  g_vl[MTOK*D];

// bf16 hi/lo split transposed weights [N][K]
#define WOFF_WO  (12*D*D)
#define WOFF_F1  (16*D*D)
#define WOFF_F2  (WOFF_F1 + 4*D*DFF)
#define WT_TOTAL (WOFF_F2 + 4*D*DFF)
__device__ __nv_bfloat16 g_wth[WT_TOTAL], g_wtl[WT_TOTAL];

__device__ __forceinline__ __nv_bfloat162 bsplit2(float a, float b, __nv_bfloat162* lo)
{
    __nv_bfloat16 ha = __float2bfloat16_rn(a);
    __nv_bfloat16 hb = __float2bfloat16_rn(b);
    lo->x = __float2bfloat16_rn(a - __bfloat162float(ha));
    lo->y = __float2bfloat16_rn(b - __bfloat162float(hb));
    __nv_bfloat162 hi; hi.x = ha; hi.y = hb;
    return hi;
}

// ---------------- embedding: emb + cell-type MLP + positional + cls ----------
__global__ void embed_kernel(const float* __restrict__ cf,
                             const int* __restrict__ xc,
                             const int* __restrict__ yc,
                             const float* __restrict__ Wemb,
                             const float* __restrict__ bemb,
                             const float* __restrict__ Wct1,
                             const float* __restrict__ bct1,
                             const float* __restrict__ Wct2,
                             const float* __restrict__ bct2,
                             const float* __restrict__ cls)
{
    int blk = blockIdx.x;          // 0..8199
    int b = blk / SLEN;
    int s = blk % SLEN;
    int d = threadIdx.x;           // 0..255
    float* out = g_x + (size_t)blk * D;

    float val;
    if (s == 0) {
        val = cls[d];
    } else {
        int n = s - 1;
        __shared__ float cfs[64];
        __shared__ float hs[128];
        const float* cfp = cf + ((size_t)b*NCELL + n)*64;
        if (d < 64) cfs[d] = cfp[d];
        __syncthreads();

        if (d < 128) {
            float acc = bct1[d];
            #pragma unroll
            for (int k = 0; k < 64; k++) acc = fmaf(cfs[k], Wct1[k*128 + d], acc);
            hs[d] = fmaxf(acc, 0.f);
        }
        __syncthreads();

        float e = bemb[d];
        #pragma unroll
        for (int k = 0; k < 64; k++) e = fmaf(cfs[k], Wemb[k*256 + d], e);
        float c2 = bct2[d];
        #pragma unroll
        for (int j = 0; j < 128; j++) c2 = fmaf(hs[j], Wct2[j*256 + d], c2);

        int dd    = (d < 128) ? d : d - 128;
        int coord = (d < 128) ? xc[b*NCELL + n] : yc[b*NCELL + n];
        coord = min(max(coord, 0), 999);
        int m = dd >> 1;
        const float c1 = -0.07195578739046225f;  // float(-ln(10000)/128)
        float dv  = expf((float)(2*m) * c1);
        float ang = (float)coord * dv;
        float p   = (dd & 1) ? cosf(ang) : sinf(ang);
        val = e + c2 + p;
    }

    out[d] = val;
    __nv_bfloat16 hh = __float2bfloat16_rn(val);
    g_xh[(size_t)blk*D + d] = hh;
    g_xl[(size_t)blk*D + d] = __float2bfloat16_rn(val - __bfloat162float(hh));
}

// ---------------- weight convert: W[K][N] f32 -> Wt[N][K] bf16 hi/lo ---------
__global__ void wconv_kernel(const float* __restrict__ src,
                             __nv_bfloat16* __restrict__ dh,
                             __nv_bfloat16* __restrict__ dl,
                             int K, int N, int srcStride, int dstStride)
{
    int l = blockIdx.y;
    int idx = blockIdx.x*256 + threadIdx.x;
    int n = idx / K;
    int k = idx - n*K;
    float v = src[(size_t)l*srcStride + (size_t)k*N + n];
    __nv_bfloat16 h = __float2bfloat16_rn(v);
    dh[(size_t)l*dstStride + idx] = h;
    dl[(size_t)l*dstStride + idx] = __float2bfloat16_rn(v - __bfloat162float(h));
}

// ---- bf16x3 tensor-core GEMM: C = (A@W + bias)*oscale; BM=BN=64 BK=32 -------
__device__ __forceinline__
void mma_body(const __nv_bfloat16* __restrict__ Agh,
              const __nv_bfloat16* __restrict__ Agl,
              const __nv_bfloat16* __restrict__ Bgh,
              const __nv_bfloat16* __restrict__ Bgl,
              const float* __restrict__ bias,
              float* __restrict__ Cf,
              __nv_bfloat16* __restrict__ Ch,
              __nv_bfloat16* __restrict__ Cl,
              int M, int N, int K, int relu, float oscale, int bx, int by)
{
    __shared__ __align__(16) __nv_bfloat16 Ahs[2][64][40], Als[2][64][40];
    __shared__ __align__(16) __nv_bfloat16 Bhs[2][64][40], Bls[2][64][40];

    int tid  = threadIdx.x;        // 0..127
    int lane = tid & 31;
    int wid  = tid >> 5;
    int m0 = bx * 64, n0 = by * 64;
    int g = lane >> 2, t = lane & 3;
    int mw = (wid & 1) * 32;
    int nw = (wid >> 1) * 32;

    int lr = tid >> 1;             // 0..63
    int lc = (tid & 1) * 16;       // 0 or 16 (bf16 offset)

    int gr = m0 + lr;
    int szA = (gr < M) ? 16 : 0;
    int cr  = min(gr, M-1);
    const __nv_bfloat16* pAh = Agh + (size_t)cr*K + lc;
    const __nv_bfloat16* pAl = Agl + (size_t)cr*K + lc;
    const __nv_bfloat16* pBh = Bgh + (size_t)(n0 + lr)*K + lc;
    const __nv_bfloat16* pBl = Bgl + (size_t)(n0 + lr)*K + lc;

    float acc[2][4][4];
    #pragma unroll
    for (int mt = 0; mt < 2; mt++)
        #pragma unroll
        for (int nt = 0; nt < 4; nt++)
            #pragma unroll
            for (int i = 0; i < 4; i++) acc[mt][nt][i] = 0.f;

#define ISSUE_TILE(buf, kt) do { \
    int _k0 = (kt)*32; \
    CPA16(&Ahs[buf][lr][lc],   pAh + _k0,     szA); \
    CPA16(&Ahs[buf][lr][lc+8], pAh + _k0 + 8, szA); \
    CPA16(&Als[buf][lr][lc],   pAl + _k0,     szA); \
    CPA16(&Als[buf][lr][lc+8], pAl + _k0 + 8, szA); \
    CPA16(&Bhs[buf][lr][lc],   pBh + _k0,     16); \
    CPA16(&Bhs[buf][lr][lc+8], pBh + _k0 + 8, 16); \
    CPA16(&Bls[buf][lr][lc],   pBl + _k0,     16); \
    CPA16(&Bls[buf][lr][lc+8], pBl + _k0 + 8, 16); \
    asm volatile("cp.async.commit_group;"); \
} while (0)

    ISSUE_TILE(0, 0);

    int KT = K >> 5;
    for (int kt = 0; kt < KT; kt++) {
        int cur = kt & 1;
        if (kt + 1 < KT) {
            ISSUE_TILE(cur ^ 1, kt + 1);
            asm volatile("cp.async.wait_group 1;");
        } else {
            asm volatile("cp.async.wait_group 0;");
        }
        __syncthreads();

        #pragma unroll
        for (int ks8 = 0; ks8 < 2; ks8++) {
            int ks = ks8 * 16;
            uint32_t ah[2][4], al[2][4], bh[4][2], bl[4][2];
            #pragma unroll
            for (int mt = 0; mt < 2; mt++) {
                int rb = mw + mt*16;
                ah[mt][0] = *(const uint32_t*)&Ahs[cur][rb+g  ][ks+2*t];
                ah[mt][1] = *(const uint32_t*)&Ahs[cur][rb+g+8][ks+2*t];
                ah[mt][2] = *(const uint32_t*)&Ahs[cur][rb+g  ][ks+2*t+8];
                ah[mt][3] = *(const uint32_t*)&Ahs[cur][rb+g+8][ks+2*t+8];
                al[mt][0] = *(const uint32_t*)&Als[cur][rb+g  ][ks+2*t];
                al[mt][1] = *(const uint32_t*)&Als[cur][rb+g+8][ks+2*t];
                al[mt][2] = *(const uint32_t*)&Als[cur][rb+g  ][ks+2*t+8];
                al[mt][3] = *(const uint32_t*)&Als[cur][rb+g+8][ks+2*t+8];
            }
            #pragma unroll
            for (int nt = 0; nt < 4; nt++) {
                int nb = nw + nt*8;
                bh[nt][0] = *(const uint32_t*)&Bhs[cur][nb+g][ks+2*t];
                bh[nt][1] = *(const uint32_t*)&Bhs[cur][nb+g][ks+2*t+8];
                bl[nt][0] = *(const uint32_t*)&Bls[cur][nb+g][ks+2*t];
                bl[nt][1] = *(const uint32_t*)&Bls[cur][nb+g][ks+2*t+8];
            }
            #pragma unroll
            for (int mt = 0; mt < 2; mt++) {
                #pragma unroll
                for (int nt = 0; nt < 4; nt++) {
                    MMA_BF16(acc[mt][nt], ah[mt], bh[nt]);
                    MMA_BF16(acc[mt][nt], ah[mt], bl[nt]);
                    MMA_BF16(acc[mt][nt], al[mt], bh[nt]);
                }
            }
        }
        __syncthreads();
    }
#undef ISSUE_TILE

    // epilogue
    #pragma unroll
    for (int mt = 0; mt < 2; mt++) {
        #pragma unroll
        for (int nt = 0; nt < 4; nt++) {
            int col = n0 + nw + nt*8 + 2*t;
            float b0v = bias[col], b1v = bias[col+1];
            int r0 = m0 + mw + mt*16 + g;
            int r1 = r0 + 8;
            float v00 = (acc[mt][nt][0] + b0v) * oscale;
            float v01 = (acc[mt][nt][1] + b1v) * oscale;
            float v10 = (acc[mt][nt][2] + b0v) * oscale;
            float v11 = (acc[mt][nt][3] + b1v) * oscale;
            if (relu) {
                v00 = fmaxf(v00, 0.f); v01 = fmaxf(v01, 0.f);
                v10 = fmaxf(v10, 0.f); v11 = fmaxf(v11, 0.f);
            }
            if (Cf) {
                if (r0 < M) { float2 o = {v00, v01}; *(float2*)(Cf + (size_t)r0*N + col) = o; }
                if (r1 < M) { float2 o = {v10, v11}; *(float2*)(Cf + (size_t)r1*N + col) = o; }
            } else {
                if (r0 < M) {
                    __nv_bfloat162 lo; __nv_bfloat162 hi = bsplit2(v00, v01, &lo);
                    *(__nv_bfloat162*)(Ch + (size_t)r0*N + col) = hi;
                    *(__nv_bfloat162*)(Cl + (size_t)r0*N + col) = lo;
                }
                if (r1 < M) {
                    __nv_bfloat162 lo; __nv_bfloat162 hi = bsplit2(v10, v11, &lo);
                    *(__nv_bfloat162*)(Ch + (size_t)r1*N + col) = hi;
                    *(__nv_bfloat162*)(Cl + (size_t)r1*N + col) = lo;
                }
            }
        }
    }
}

__global__ __launch_bounds__(128, 4)
void mma_gemm(const __nv_bfloat16* __restrict__ Agh,
              const __nv_bfloat16* __restrict__ Agl,
              const __nv_bfloat16* __restrict__ Bgh,
              const __nv_bfloat16* __restrict__ Bgl,
              const float* __restrict__ bias,
              float* __restrict__ Cf,
              __nv_bfloat16* __restrict__ Ch,
              __nv_bfloat16* __restrict__ Cl,
              int M, int N, int K, int relu)
{
    mma_body(Agh, Agl, Bgh, Bgl, bias, Cf, Ch, Cl, M, N, K, relu, 1.f,
             blockIdx.x, blockIdx.y);
}

// fused QKV: writes bf16-split Q (pre-scaled by 1/sqrt(hd)), K, V
__global__ __launch_bounds__(128, 4)
void qkv_mma(const __nv_bfloat16* __restrict__ xh,
             const __nv_bfloat16* __restrict__ xl,
             const __nv_bfloat16* __restrict__ wth,
             const __nv_bfloat16* __restrict__ wtl,
             const float* __restrict__ bq,
             const float* __restrict__ bk,
             const float* __restrict__ bv,
             __nv_bfloat16* __restrict__ Qh, __nv_bfloat16* __restrict__ Ql,
             __nv_bfloat16* __restrict__ Kh, __nv_bfloat16* __restrict__ Kl,
             __nv_bfloat16* __restrict__ Vh, __nv_bfloat16* __restrict__ Vl)
{
    int z = blockIdx.z;
    const __nv_bfloat16* Wh = wth + (size_t)z*D*D;
    const __nv_bfloat16* Wl = wtl + (size_t)z*D*D;
    const float* bias = (z == 0) ? bq : (z == 1) ? bk : bv;
    __nv_bfloat16* Ch = (z == 0) ? Qh : (z == 1) ? Kh : Vh;
    __nv_bfloat16* Cl = (z == 0) ? Ql : (z == 1) ? Kl : Vl;
    float sc = (z == 0) ? 0.17677669529663687f : 1.f;
    mma_body(xh, xl, Wh, Wl, bias, nullptr, Ch, Cl, MTOK, D, D, 0, sc,
             blockIdx.x, blockIdx.y);
}

// ---------------- tensor-core flash attention (bf16x3) -----------------------
// block = (64-row q-tile, head, batch), 128 threads / 4 warps.
__global__ __launch_bounds__(128)
void attn_mma_kernel()
{
    __shared__ __align__(16) __nv_bfloat16 qsh[64][40], qsl[64][40];
    __shared__ __align__(16) __nv_bfloat16 ksh[64][40], ksl[64][40];
    __shared__ __align__(16) __nv_bfloat16 vsh[64][40], vsl[64][40];

    int qt = blockIdx.x;           // 0..16
    int h  = blockIdx.y;
    int b  = blockIdx.z;
    int tid = threadIdx.x, lane = tid & 31, w = tid >> 5;
    int g = lane >> 2, t = lane & 3;
    int mw = w * 16;

    size_t hoff = ((size_t)b * SLEN) * D + h * HD;
    const __nv_bfloat16* qhg = g_qh + hoff;
    const __nv_bfloat16* qlg = g_ql + hoff;
    const __nv_bfloat16* khg = g_kh + hoff;
    const __nv_bfloat16* klg = g_kl + hoff;
    const __nv_bfloat16* vhg = g_vh + hoff;
    const __nv_bfloat16* vlg = g_vl + hoff;

    int lr = tid >> 1;             // 0..63
    int lc = (tid & 1) * 16;       // 0 / 16 bf16

    // load Q tile (rows clamped; invalid rows never written out)
    {
        int cq = min(qt*64 + lr, SLEN-1);
        const __nv_bfloat16* s0 = qhg + (size_t)cq*D + lc;
        const __nv_bfloat16* s1 = qlg + (size_t)cq*D + lc;
        CPA16(&qsh[lr][lc],   s0,     16);
        CPA16(&qsh[lr][lc+8], s0 + 8, 16);
        CPA16(&qsl[lr][lc],   s1,     16);
        CPA16(&qsl[lr][lc+8], s1 + 8, 16);
        asm volatile("cp.async.commit_group;");
        asm volatile("cp.async.wait_group 0;");
    }
    __syncthreads();

    // Q fragments (A m16k16): per k-chunk kc, per hi/lo
    uint32_t qfh[2][4], qfl[2][4];
    {
        int r = mw + (lane & 15);
        int cb = (lane >> 4) * 8;
        LDSM4(qfh[0][0], qfh[0][1], qfh[0][2], qfh[0][3], sptr(&qsh[r][cb]));
        LDSM4(qfh[1][0], qfh[1][1], qfh[1][2], qfh[1][3], sptr(&qsh[r][16 + cb]));
        LDSM4(qfl[0][0], qfl[0][1], qfl[0][2], qfl[0][3], sptr(&qsl[r][cb]));
        LDSM4(qfl[1][0], qfl[1][1], qfl[1][2], qfl[1][3], sptr(&qsl[r][16 + cb]));
    }

    float m0 = -INFINITY, m1 = -INFINITY, l0 = 0.f, l1 = 0.f;
    float o[4][4];
    #pragma unroll
    for (int nd = 0; nd < 4; nd++)
        #pragma unroll
        for (int i = 0; i < 4; i++) o[nd][i] = 0.f;

    for (int kt = 0; kt < 17; kt++) {
        int k0 = kt * 64;
        __syncthreads();           // prev-tile compute done before overwrite
        {
            int ck = min(k0 + lr, SLEN-1);
            const __nv_bfloat16* a0 = khg + (size_t)ck*D + lc;
            const __nv_bfloat16* a1 = klg + (size_t)ck*D + lc;
            const __nv_bfloat16* a2 = vhg + (size_t)ck*D + lc;
            const __nv_bfloat16* a3 = vlg + (size_t)ck*D + lc;
            CPA16(&ksh[lr][lc],   a0,     16); CPA16(&ksh[lr][lc+8], a0 + 8, 16);
            CPA16(&ksl[lr][lc],   a1,     16); CPA16(&ksl[lr][lc+8], a1 + 8, 16);
            CPA16(&vsh[lr][lc],   a2,     16); CPA16(&vsh[lr][lc+8], a2 + 8, 16);
            CPA16(&vsl[lr][lc],   a3,     16); CPA16(&vsl[lr][lc+8], a3 + 8, 16);
            asm volatile("cp.async.commit_group;");
            asm volatile("cp.async.wait_group 0;");
        }
        __syncthreads();

        // ---- S = Q K^T (3-term bf16x3), 8 n-tiles of 8 tokens ----
        float s[8][4];
        #pragma unroll
        for (int j = 0; j < 8; j++)
            #pragma unroll
            for (int i = 0; i < 4; i++) s[j][i] = 0.f;

        #pragma unroll
        for (int j = 0; j < 8; j++) {
            uint32_t bh[4], bl[4];
            int rr = j*8 + (lane & 7);
            int cc = ((lane >> 3) & 3) * 8;
            LDSM4(bh[0], bh[1], bh[2], bh[3], sptr(&ksh[rr][cc]));
            LDSM4(bl[0], bl[1], bl[2], bl[3], sptr(&ksl[rr][cc]));
            MMA_BF16(s[j], qfh[0], bh);
            MMA_BF16(s[j], qfh[1], bh + 2);
            MMA_BF16(s[j], qfh[0], bl);
            MMA_BF16(s[j], qfh[1], bl + 2);
            MMA_BF16(s[j], qfl[0], bh);
            MMA_BF16(s[j], qfl[1], bh + 2);
        }

        // mask invalid tokens (only last tile)
        if (k0 + 64 > SLEN) {
            #pragma unroll
            for (int j = 0; j < 8; j++) {
                int tok = k0 + j*8 + 2*t;
                if (tok     >= SLEN) { s[j][0] = -1e30f; s[j][2] = -1e30f; }
                if (tok + 1 >= SLEN) { s[j][1] = -1e30f; s[j][3] = -1e30f; }
            }
        }

        // ---- online softmax on fragment layout ----
        float t0v = -INFINITY, t1v = -INFINITY;
        #pragma unroll
        for (int j = 0; j < 8; j++) {
            t0v = fmaxf(t0v, fmaxf(s[j][0], s[j][1]));
            t1v = fmaxf(t1v, fmaxf(s[j][2], s[j][3]));
        }
        t0v = fmaxf(t0v, __shfl_xor_sync(0xffffffffu, t0v, 1));
        t0v = fmaxf(t0v, __shfl_xor_sync(0xffffffffu, t0v, 2));
        t1v = fmaxf(t1v, __shfl_xor_sync(0xffffffffu, t1v, 1));
        t1v = fmaxf(t1v, __shfl_xor_sync(0xffffffffu, t1v, 2));

        float mn0 = fmaxf(m0, t0v), mn1 = fmaxf(m1, t1v);
        float c0 = __expf(m0 - mn0), c1 = __expf(m1 - mn1);
        l0 *= c0; l1 *= c1;
        #pragma unroll
        for (int nd = 0; nd < 4; nd++) {
            o[nd][0] *= c0; o[nd][1] *= c0;
            o[nd][2] *= c1; o[nd][3] *= c1;
        }

        float ls0 = 0.f, ls1 = 0.f;
        #pragma unroll
        for (int j = 0; j < 8; j++) {
            s[j][0] = __expf(s[j][0] - mn0); ls0 += s[j][0];
            s[j][1] = __expf(s[j][1] - mn0); ls0 += s[j][1];
            s[j][2] = __expf(s[j][2] - mn1); ls1 += s[j][2];
            s[j][3] = __expf(s[j][3] - mn1); ls1 += s[j][3];
        }
        l0 += ls0; l1 += ls1;
        m0 = mn0; m1 = mn1;

        // ---- P -> A fragments (hi/lo split, in registers) ----
        uint32_t ph[4][4], pl[4][4];
        #pragma unroll
        for (int c = 0; c < 4; c++) {
            psplit(s[2*c][0],   s[2*c][1],   ph[c][0], pl[c][0]);
            psplit(s[2*c][2],   s[2*c][3],   ph[c][1], pl[c][1]);
            psplit(s[2*c+1][0], s[2*c+1][1], ph[c][2], pl[c][2]);
            psplit(s[2*c+1][2], s[2*c+1][3], ph[c][3], pl[c][3]);
        }

        // ---- O += P V (3-term) ----
        #pragma unroll
        for (int nd = 0; nd < 4; nd++) {
            uint32_t bvh[4][2], bvl[4][2];
            #pragma unroll
            for (int cc = 0; cc < 2; cc++) {
                uint32_t va = sptr(&vsh[cc*32 + lane][nd*8]);
                uint32_t la = sptr(&vsl[cc*32 + lane][nd*8]);
                LDSM4T(bvh[2*cc][0], bvh[2*cc][1], bvh[2*cc+1][0], bvh[2*cc+1][1], va);
                LDSM4T(bvl[2*cc][0], bvl[2*cc][1], bvl[2*cc+1][0], bvl[2*cc+1][1], la);
            }
            #pragma unroll
            for (int c = 0; c < 4; c++) {
                MMA_BF16(o[nd], ph[c], bvh[c]);
                MMA_BF16(o[nd], ph[c], bvl[c]);
                MMA_BF16(o[nd], pl[c], bvh[c]);
            }
        }
    }

    // final: reduce l over quad, normalize, write bf16-split output
    l0 += __shfl_xor_sync(0xffffffffu, l0, 1);
    l0 += __shfl_xor_sync(0xffffffffu, l0, 2);
    l1 += __shfl_xor_sync(0xffffffffu, l1, 1);
    l1 += __shfl_xor_sync(0xffffffffu, l1, 2);
    float i0 = 1.f / l0, i1 = 1.f / l1;

    int q0 = qt*64 + mw + g;
    int q1 = q0 + 8;
    int colb = h*HD + 2*t;
    #pragma unroll
    for (int nd = 0; nd < 4; nd++) {
        if (q0 < SLEN) {
            __nv_bfloat162 lo;
            __nv_bfloat162 hi = bsplit2(o[nd][0]*i0, o[nd][1]*i0, &lo);
            size_t off = ((size_t)b*SLEN + q0)*D + colb + nd*8;
            *(__nv_bfloat162*)(g_ah + off) = hi;
            *(__nv_bfloat162*)(g_al + off) = lo;
        }
        if (q1 < SLEN) {
            __nv_bfloat162 lo;
            __nv_bfloat162 hi = bsplit2(o[nd][2]*i1, o[nd][3]*i1, &lo);
            size_t off = ((size_t)b*SLEN + q1)*D + colb + nd*8;
            *(__nv_bfloat162*)(g_ah + off) = hi;
            *(__nv_bfloat162*)(g_al + off) = lo;
        }
    }
}

// ---------- fused residual + LayerNorm, warp-per-row; f32 + bf16-split out ---
__global__ void ln_kernel(const float* __restrict__ A,
                          const float* __restrict__ Bsrc,
                          const float* __restrict__ g,
                          const float* __restrict__ bta,
                          float* __restrict__ out,
                          __nv_bfloat16* __restrict__ oh,
                          __nv_bfloat16* __restrict__ ol)
{
    int warp = threadIdx.x >> 5;
    int lane = threadIdx.x & 31;
    int row = blockIdx.x * 8 + warp;
    size_t base = (size_t)row * D;

    const float4* ap = (const float4*)(A + base);
    const float4* bp = (const float4*)(Bsrc + base);
    float4 a0 = ap[lane], a1 = ap[lane + 32];
    float4 b0 = bp[lane], b1 = bp[lane + 32];
    float v[8];
    v[0]=a0.x+b0.x; v[1]=a0.y+b0.y; v[2]=a0.z+b0.z; v[3]=a0.w+b0.w;
    v[4]=a1.x+b1.x; v[5]=a1.y+b1.y; v[6]=a1.z+b1.z; v[7]=a1.w+b1.w;

    float s = 0.f, s2 = 0.f;
    #pragma unroll
    for (int i = 0; i < 8; i++) { s += v[i]; s2 = fmaf(v[i], v[i], s2); }
    #pragma unroll
    for (int o = 16; o > 0; o >>= 1) {
        s  += __shfl_xor_sync(0xffffffffu, s,  o);
        s2 += __shfl_xor_sync(0xffffffffu, s2, o);
    }
    float mu = s * (1.f/256.f);
    float var = s2 * (1.f/256.f) - mu*mu;
    float rstd = rsqrtf(var + 1e-5f);

    const float4* gp = (const float4*)g;
    const float4* tp = (const float4*)bta;
    float4 g0 = gp[lane], g1 = gp[lane+32];
    float4 t0 = tp[lane], t1 = tp[lane+32];
    float4 o0, o1;
    o0.x = (v[0]-mu)*rstd*g0.x + t0.x;
    o0.y = (v[1]-mu)*rstd*g0.y + t0.y;
    o0.z = (v[2]-mu)*rstd*g0.z + t0.z;
    o0.w = (v[3]-mu)*rstd*g0.w + t0.w;
    o1.x = (v[4]-mu)*rstd*g1.x + t1.x;
    o1.y = (v[5]-mu)*rstd*g1.y + t1.y;
    o1.z = (v[6]-mu)*rstd*g1.z + t1.z;
    o1.w = (v[7]-mu)*rstd*g1.w + t1.w;
    float4* op = (float4*)(out + base);
    op[lane]      = o0;
    op[lane + 32] = o1;

    size_t e0 = base + (size_t)lane*4;
    size_t e1 = base + (size_t)(lane+32)*4;
    __nv_bfloat162 lo, hi;
    hi = bsplit2(o0.x, o0.y, &lo);
    *(__nv_bfloat162*)(oh + e0)     = hi; *(__nv_bfloat162*)(ol + e0)     = lo;
    hi = bsplit2(o0.z, o0.w, &lo);
    *(__nv_bfloat162*)(oh + e0 + 2) = hi; *(__nv_bfloat162*)(ol + e0 + 2) = lo;
    hi = bsplit2(o1.x, o1.y, &lo);
    *(__nv_bfloat162*)(oh + e1)     = hi; *(__nv_bfloat162*)(ol + e1)     = lo;
    hi = bsplit2(o1.z, o1.w, &lo);
    *(__nv_bfloat162*)(oh + e1 + 2) = hi; *(__nv_bfloat162*)(ol + e1 + 2) = lo;
}

// ---------------- final: LN cls row only + 2-layer head ----------------------
__global__ void head_kernel(const float* __restrict__ g,
                            const float* __restrict__ bta,
                            const float* __restrict__ Wh1,
                            const float* __restrict__ bh1,
                            const float* __restrict__ Wh2,
                            const float* __restrict__ bh2,
                            float* __restrict__ out)
{
    int b = blockIdx.x;
    int d = threadIdx.x;
    float v = g_x[(size_t)b*SLEN*D + d];

    float s = v, s2 = v*v;
    #pragma unroll
    for (int o = 16; o > 0; o >>= 1) {
        s  += __shfl_xor_sync(0xffffffffu, s,  o);
        s2 += __shfl_xor_sync(0xffffffffu, s2, o);
    }
    __shared__ float ws[8], ws2[8];
    __shared__ float mu_s, rstd_s;
    int w = d >> 5;
    if ((d & 31) == 0) { ws[w] = s; ws2[w] = s2; }
    __syncthreads();
    if (d == 0) {
        float S1 = 0.f, S2 = 0.f;
        #pragma unroll
        for (int i = 0; i < 8; i++) { S1 += ws[i]; S2 += ws2[i]; }
        float mu = S1 * (1.f/256.f);
        float var = S2 * (1.f/256.f) - mu*mu;
        mu_s = mu;
        rstd_s = rsqrtf(var + 1e-5f);
    }
    __syncthreads();

    __shared__ float clsr[256];
    __shared__ float hid[256];
    float c = (v - mu_s) * rstd_s * g[d] + bta[d];
    clsr[d] = c;
    out[b*D + d] = c;                       // cls_out
    __syncthreads();

    float hsum = bh1[d];
    #pragma unroll 8
    for (int k = 0; k < 256; k++) hsum = fmaf(clsr[k], Wh1[k*256 + d], hsum);
    hid[d] = fmaxf(hsum, 0.f);
    __syncthreads();

    if (d < 2) {
        float lg = bh2[d];
        for (int k = 0; k < 256; k++) lg = fmaf(hid[k], Wh2[k*2 + d], lg);
        out[BB*D + b*2 + d] = lg;           // logits after cls_out block
    }
}

// ---------------- launcher ---------------------------------------------------
extern "C" void kernel_launch(void* const* d_in, const int* in_sizes, int n_in,
                              void* d_out, int out_size)
{
    (void)in_sizes; (void)n_in; (void)out_size;

    const float* cf   = (const float*)d_in[0];
    const int*   xc   = (const int*)  d_in[1];
    const int*   yc   = (const int*)  d_in[2];
    const float* Wemb = (const float*)d_in[3];
    const float* bemb = (const float*)d_in[4];
    const float* Wct1 = (const float*)d_in[5];
    const float* bct1 = (const float*)d_in[6];
    const float* Wct2 = (const float*)d_in[7];
    const float* bct2 = (const float*)d_in[8];
    const float* cls  = (const float*)d_in[9];
    const float* Wq = (const float*)d_in[10]; const float* bq = (const float*)d_in[11];
    const float* Wk = (const float*)d_in[12]; const float* bk = (const float*)d_in[13];
    const float* Wv = (const float*)d_in[14]; const float* bv = (const float*)d_in[15];
    const float* Wo = (const float*)d_in[16]; const float* bo = (const float*)d_in[17];
    const float* ln1g = (const float*)d_in[18]; const float* ln1b = (const float*)d_in[19];
    const float* ln2g = (const float*)d_in[20]; const float* ln2b = (const float*)d_in[21];
    const float* Wf1 = (const float*)d_in[22]; const float* bf1 = (const float*)d_in[23];
    const float* Wf2 = (const float*)d_in[24]; const float* bf2 = (const float*)d_in[25];
    const float* lnfg = (const float*)d_in[26]; const float* lnfb = (const float*)d_in[27];
    const float* Wh1 = (const float*)d_in[28]; const float* bh1 = (const float*)d_in[29];
    const float* Wh2 = (const float*)d_in[30]; const float* bh2 = (const float*)d_in[31];
    float* out = (float*)d_out;

    void* p;
    cudaGetSymbolAddress(&p, g_x);  float* xb = (float*)p;
    cudaGetSymbolAddress(&p, g_t);  float* tb = (float*)p;
    cudaGetSymbolAddress(&p, g_xh); __nv_bfloat16* xh = (__nv_bfloat16*)p;
    cudaGetSymbolAddress(&p, g_xl); __nv_bfloat16* xl = (__nv_bfloat16*)p;
    cudaGetSymbolAddress(&p, g_ah); __nv_bfloat16* ah = (__nv_bfloat16*)p;
    cudaGetSymbolAddress(&p, g_al); __nv_bfloat16* al = (__nv_bfloat16*)p;
    cudaGetSymbolAddress(&p, g_hh); __nv_bfloat16* hh = (__nv_bfloat16*)p;
    cudaGetSymbolAddress(&p, g_hl); __nv_bfloat16* hl = (__nv_bfloat16*)p;
    cudaGetSymbolAddress(&p, g_qh); __nv_bfloat16* qh = (__nv_bfloat16*)p;
    cudaGetSymbolAddress(&p, g_ql); __nv_bfloat16* ql = (__nv_bfloat16*)p;
    cudaGetSymbolAddress(&p, g_kh); __nv_bfloat16* kh = (__nv_bfloat16*)p;
    cudaGetSymbolAddress(&p, g_kl); __nv_bfloat16* kl = (__nv_bfloat16*)p;
    cudaGetSymbolAddress(&p, g_vh); __nv_bfloat16* vh = (__nv_bfloat16*)p;
    cudaGetSymbolAddress(&p, g_vl); __nv_bfloat16* vl = (__nv_bfloat16*)p;
    cudaGetSymbolAddress(&p, g_wth); __nv_bfloat16* wth = (__nv_bfloat16*)p;
    cudaGetSymbolAddress(&p, g_wtl); __nv_bfloat16* wtl = (__nv_bfloat16*)p;

    // upfront: weight split + transpose (all layers)
    {
        dim3 gdd((D*D)/256, NL);
        wconv_kernel<<<gdd, 256>>>(Wq, wth + 0,       wtl + 0,       D, D, D*D, 3*D*D);
        wconv_kernel<<<gdd, 256>>>(Wk, wth + D*D,     wtl + D*D,     D, D, D*D, 3*D*D);
        wconv_kernel<<<gdd, 256>>>(Wv, wth + 2*D*D,   wtl + 2*D*D,   D, D, D*D, 3*D*D);
        wconv_kernel<<<gdd, 256>>>(Wo, wth + WOFF_WO, wtl + WOFF_WO, D, D, D*D, D*D);
        dim3 gdf((D*DFF)/256, NL);
        wconv_kernel<<<gdf, 256>>>(Wf1, wth + WOFF_F1, wtl + WOFF_F1, D, DFF, D*DFF, D*DFF);
        wconv_kernel<<<gdf, 256>>>(Wf2, wth + WOFF_F2, wtl + WOFF_F2, DFF, D, D*DFF, D*DFF);
    }

    embed_kernel<<<MTOK, 256>>>(cf, xc, yc, Wemb, bemb, Wct1, bct1, Wct2, bct2, cls);

    int MB = (MTOK + 63) / 64;             // 129
    dim3 gqkv(MB, D/64, 3);                // 129 x 4 x 3
    dim3 gdd2(MB, D/64);                   // 129 x 4
    dim3 gff (MB, DFF/64);                 // 129 x 16
    dim3 gattn(17, NH, BB);                // 17 x 8 x 8
    int lngrid = MTOK / 8;                 // 1025

    for (int l = 0; l < NL; l++) {
        qkv_mma<<<gqkv, 128>>>(xh, xl,
                               wth + (size_t)l*3*D*D, wtl + (size_t)l*3*D*D,
                               bq + l*D, bk + l*D, bv + l*D,
                               qh, ql, kh, kl, vh, vl);
        attn_mma_kernel<<<gattn, 128>>>();
        mma_gemm<<<gdd2, 128>>>(ah, al,
                                wth + WOFF_WO + (size_t)l*D*D,
                                wtl + WOFF_WO + (size_t)l*D*D,
                                bo + l*D, tb, nullptr, nullptr, MTOK, D, D, 0);
        ln_kernel<<<lngrid, 256>>>(xb, tb, ln1g + l*D, ln1b + l*D, xb, xh, xl);
        mma_gemm<<<gff, 128>>>(xh, xl,
                               wth + WOFF_F1 + (size_t)l*D*DFF,
                               wtl + WOFF_F1 + (size_t)l*D*DFF,
                               bf1 + l*DFF, nullptr, hh, hl, MTOK, DFF, D, 1);
        mma_gemm<<<gdd2, 128>>>(hh, hl,
                                wth + WOFF_F2 + (size_t)l*D*DFF,
                                wtl + WOFF_F2 + (size_t)l*D*DFF,
                                bf2 + l*D, tb, nullptr, nullptr, MTOK, D, DFF, 0);
        ln_kernel<<<lngrid, 256>>>(xb, tb, ln2g + l*D, ln2b + l*D, xb, xh, xl);
    }

    head_kernel<<<BB, 256>>>(lnfg, lnfb, Wh1, bh1, Wh2, bh2, out);
}

// round 15
// speedup vs baseline: 2.6690x; 1.0453x over previous
#include <cuda_runtime.h>
#include <cuda_bf16.h>
#include <math.h>
#include <stdint.h>

#define BB   8
#define NCELL 1024
#define SLEN 1025
#define D    256
#define NH   8
#define HD   32
#define DFF  1024
#define NL   4
#define MTOK (BB*SLEN)   // 8200

// cp.async helper: 16B global->shared, zero-fill when sz==0
#define CPA16(dst, src, sz) \
    asm volatile("cp.async.cg.shared.global [%0], [%1], 16, %2;" \
        :: "r"((uint32_t)__cvta_generic_to_shared(dst)), "l"(src), "r"(sz))

// bf16 tensor-core mma: C(f32) += A(bf16) * B(bf16), m16n8k16 row.col
#define MMA_BF16(c, a, b) \
    asm volatile("mma.sync.aligned.m16n8k16.row.col.f32.bf16.bf16.f32 " \
        "{%0,%1,%2,%3}, {%4,%5,%6,%7}, {%8,%9}, {%0,%1,%2,%3};" \
        : "+f"((c)[0]), "+f"((c)[1]), "+f"((c)[2]), "+f"((c)[3]) \
        : "r"((a)[0]), "r"((a)[1]), "r"((a)[2]), "r"((a)[3]), \
          "r"((b)[0]), "r"((b)[1]))

#define LDSM4(d0,d1,d2,d3,a) \
    asm volatile("ldmatrix.sync.aligned.m8n8.x4.shared.b16 {%0,%1,%2,%3}, [%4];" \
        : "=r"(d0),"=r"(d1),"=r"(d2),"=r"(d3) : "r"(a))
#define LDSM4T(d0,d1,d2,d3,a) \
    asm volatile("ldmatrix.sync.aligned.m8n8.x4.trans.shared.b16 {%0,%1,%2,%3}, [%4];" \
        : "=r"(d0),"=r"(d1),"=r"(d2),"=r"(d3) : "r"(a))

#define CVTPK(d, hi, lo) \
    asm("cvt.rn.bf16x2.f32 %0, %1, %2;" : "=r"(d) : "f"(hi), "f"(lo))

__device__ __forceinline__ uint32_t sptr(const void* p) {
    return (uint32_t)__cvta_generic_to_shared(p);
}

// pack (p0,p1) -> bf16x2 hi word + bf16x2 residual word
__device__ __forceinline__ void psplit(float p0, float p1, uint32_t& hi, uint32_t& lo)
{
    CVTPK(hi, p1, p0);
    float f0 = __uint_as_float(hi << 16);
    float f1 = __uint_as_float(hi & 0xffff0000u);
    CVTPK(lo, p1 - f1, p0 - f0);
}

// ---------------- scratch (static device globals; no allocs) ----------------
__device__ float g_x[MTOK*D];
__device__ float g_t[MTOK*D];

// bf16 hi/lo split activations
__device__ __nv_bfloat16 g_xh[MTOK*D],  g_xl[MTOK*D];
__device__ __nv_bfloat16 g_ah[MTOK*D],  g_al[MTOK*D];
__device__ __nv_bfloat16 g_hh[(size_t)MTOK*DFF], g_hl[(size_t)MTOK*DFF];
__device__ __nv_bfloat16 g_qh[MTOK*D],  g_ql[MTOK*D];
__device__ __nv_bfloat16 g_kh[MTOK*D],  g_kl[MTOK*D];
__device__ __nv_bfloat16 g_vh[MTOK*D],  g_vl[MTOK*D];

// bf16 hi/lo split transposed weights [N][K]
#define WOFF_WO  (12*D*D)
#define WOFF_F1  (16*D*D)
#define WOFF_F2  (WOFF_F1 + 4*D*DFF)
#define WT_TOTAL (WOFF_F2 + 4*D*DFF)
__device__ __nv_bfloat16 g_wth[WT_TOTAL], g_wtl[WT_TOTAL];

__device__ __forceinline__ __nv_bfloat162 bsplit2(float a, float b, __nv_bfloat162* lo)
{
    __nv_bfloat16 ha = __float2bfloat16_rn(a);
    __nv_bfloat16 hb = __float2bfloat16_rn(b);
    lo->x = __float2bfloat16_rn(a - __bfloat162float(ha));
    lo->y = __float2bfloat16_rn(b - __bfloat162float(hb));
    __nv_bfloat162 hi; hi.x = ha; hi.y = hb;
    return hi;
}

// ---------------- embedding: emb + cell-type MLP + positional + cls ----------
__global__ void embed_kernel(const float* __restrict__ cf,
                             const int* __restrict__ xc,
                             const int* __restrict__ yc,
                             const float* __restrict__ Wemb,
                             const float* __restrict__ bemb,
                             const float* __restrict__ Wct1,
                             const float* __restrict__ bct1,
                             const float* __restrict__ Wct2,
                             const float* __restrict__ bct2,
                             const float* __restrict__ cls)
{
    int blk = blockIdx.x;          // 0..8199
    int b = blk / SLEN;
    int s = blk % SLEN;
    int d = threadIdx.x;           // 0..255
    float* out = g_x + (size_t)blk * D;

    float val;
    if (s == 0) {
        val = cls[d];
    } else {
        int n = s - 1;
        __shared__ float cfs[64];
        __shared__ float hs[128];
        const float* cfp = cf + ((size_t)b*NCELL + n)*64;
        if (d < 64) cfs[d] = cfp[d];
        __syncthreads();

        if (d < 128) {
            float acc = bct1[d];
            #pragma unroll
            for (int k = 0; k < 64; k++) acc = fmaf(cfs[k], Wct1[k*128 + d], acc);
            hs[d] = fmaxf(acc, 0.f);
        }
        __syncthreads();

        float e = bemb[d];
        #pragma unroll
        for (int k = 0; k < 64; k++) e = fmaf(cfs[k], Wemb[k*256 + d], e);
        float c2 = bct2[d];
        #pragma unroll
        for (int j = 0; j < 128; j++) c2 = fmaf(hs[j], Wct2[j*256 + d], c2);

        int dd    = (d < 128) ? d : d - 128;
        int coord = (d < 128) ? xc[b*NCELL + n] : yc[b*NCELL + n];
        coord = min(max(coord, 0), 999);
        int m = dd >> 1;
        const float c1 = -0.07195578739046225f;  // float(-ln(10000)/128)
        float dv  = expf((float)(2*m) * c1);
        float ang = (float)coord * dv;
        float p   = (dd & 1) ? cosf(ang) : sinf(ang);
        val = e + c2 + p;
    }

    out[d] = val;
    __nv_bfloat16 hh = __float2bfloat16_rn(val);
    g_xh[(size_t)blk*D + d] = hh;
    g_xl[(size_t)blk*D + d] = __float2bfloat16_rn(val - __bfloat162float(hh));
}

// ---------------- weight convert: W[K][N] f32 -> Wt[N][K] bf16 hi/lo ---------
__global__ void wconv_kernel(const float* __restrict__ src,
                             __nv_bfloat16* __restrict__ dh,
                             __nv_bfloat16* __restrict__ dl,
                             int K, int N, int srcStride, int dstStride)
{
    int l = blockIdx.y;
    int idx = blockIdx.x*256 + threadIdx.x;
    int n = idx / K;
    int k = idx - n*K;
    float v = src[(size_t)l*srcStride + (size_t)k*N + n];
    __nv_bfloat16 h = __float2bfloat16_rn(v);
    dh[(size_t)l*dstStride + idx] = h;
    dl[(size_t)l*dstStride + idx] = __float2bfloat16_rn(v - __bfloat162float(h));
}

// ---- bf16x3 tensor-core GEMM: C = (A@W + bias)*oscale; BM=BN=64 BK=32 -------
// ldmatrix fragment loads (mappings identical to the proven attention kernel).
__device__ __forceinline__
void mma_body(const __nv_bfloat16* __restrict__ Agh,
              const __nv_bfloat16* __restrict__ Agl,
              const __nv_bfloat16* __restrict__ Bgh,
              const __nv_bfloat16* __restrict__ Bgl,
              const float* __restrict__ bias,
              float* __restrict__ Cf,
              __nv_bfloat16* __restrict__ Ch,
              __nv_bfloat16* __restrict__ Cl,
              int M, int N, int K, int relu, float oscale, int bx, int by)
{
    __shared__ __align__(16) __nv_bfloat16 Ahs[2][64][40], Als[2][64][40];
    __shared__ __align__(16) __nv_bfloat16 Bhs[2][64][40], Bls[2][64][40];

    int tid  = threadIdx.x;        // 0..127
    int lane = tid & 31;
    int wid  = tid >> 5;
    int m0 = bx * 64, n0 = by * 64;
    int g = lane >> 2, t = lane & 3;
    int mw = (wid & 1) * 32;
    int nw = (wid >> 1) * 32;

    int lr = tid >> 1;             // 0..63
    int lc = (tid & 1) * 16;       // 0 or 16 (bf16 offset)

    int gr = m0 + lr;
    int szA = (gr < M) ? 16 : 0;
    int cr  = min(gr, M-1);
    const __nv_bfloat16* pAh = Agh + (size_t)cr*K + lc;
    const __nv_bfloat16* pAl = Agl + (size_t)cr*K + lc;
    const __nv_bfloat16* pBh = Bgh + (size_t)(n0 + lr)*K + lc;
    const __nv_bfloat16* pBl = Bgl + (size_t)(n0 + lr)*K + lc;

    float acc[2][4][4];
    #pragma unroll
    for (int mt = 0; mt < 2; mt++)
        #pragma unroll
        for (int nt = 0; nt < 4; nt++)
            #pragma unroll
            for (int i = 0; i < 4; i++) acc[mt][nt][i] = 0.f;

#define ISSUE_TILE(buf, kt) do { \
    int _k0 = (kt)*32; \
    CPA16(&Ahs[buf][lr][lc],   pAh + _k0,     szA); \
    CPA16(&Ahs[buf][lr][lc+8], pAh + _k0 + 8, szA); \
    CPA16(&Als[buf][lr][lc],   pAl + _k0,     szA); \
    CPA16(&Als[buf][lr][lc+8], pAl + _k0 + 8, szA); \
    CPA16(&Bhs[buf][lr][lc],   pBh + _k0,     16); \
    CPA16(&Bhs[buf][lr][lc+8], pBh + _k0 + 8, 16); \
    CPA16(&Bls[buf][lr][lc],   pBl + _k0,     16); \
    CPA16(&Bls[buf][lr][lc+8], pBl + _k0 + 8, 16); \
    asm volatile("cp.async.commit_group;"); \
} while (0)

    ISSUE_TILE(0, 0);

    int KT = K >> 5;
    for (int kt = 0; kt < KT; kt++) {
        int cur = kt & 1;
        if (kt + 1 < KT) {
            ISSUE_TILE(cur ^ 1, kt + 1);
            asm volatile("cp.async.wait_group 1;");
        } else {
            asm volatile("cp.async.wait_group 0;");
        }
        __syncthreads();

        // A fragments via ldmatrix (m16k16 map: row = base+(lane&15), col = (lane>>4)*8)
        uint32_t ahf[2][2][4], alf[2][2][4];
        #pragma unroll
        for (int mt = 0; mt < 2; mt++) {
            int r = mw + mt*16 + (lane & 15);
            int cb = (lane >> 4) * 8;
            #pragma unroll
            for (int ks = 0; ks < 2; ks++) {
                LDSM4(ahf[mt][ks][0], ahf[mt][ks][1], ahf[mt][ks][2], ahf[mt][ks][3],
                      sptr(&Ahs[cur][r][ks*16 + cb]));
                LDSM4(alf[mt][ks][0], alf[mt][ks][1], alf[mt][ks][2], alf[mt][ks][3],
                      sptr(&Als[cur][r][ks*16 + cb]));
            }
        }

        // B fragments per n-tile via ldmatrix x4 (n8 x k32 map: row = nb+(lane&7), col = (lane>>3)*8)
        #pragma unroll
        for (int nt = 0; nt < 4; nt++) {
            uint32_t bh4[4], bl4[4];
            int rr = nw + nt*8 + (lane & 7);
            int cc = ((lane >> 3) & 3) * 8;
            LDSM4(bh4[0], bh4[1], bh4[2], bh4[3], sptr(&Bhs[cur][rr][cc]));
            LDSM4(bl4[0], bl4[1], bl4[2], bl4[3], sptr(&Bls[cur][rr][cc]));
            #pragma unroll
            for (int ks = 0; ks < 2; ks++) {
                #pragma unroll
                for (int mt = 0; mt < 2; mt++) {
                    MMA_BF16(acc[mt][nt], ahf[mt][ks], bh4 + 2*ks);
                    MMA_BF16(acc[mt][nt], ahf[mt][ks], bl4 + 2*ks);
                    MMA_BF16(acc[mt][nt], alf[mt][ks], bh4 + 2*ks);
                }
            }
        }
        __syncthreads();
    }
#undef ISSUE_TILE

    // epilogue
    #pragma unroll
    for (int mt = 0; mt < 2; mt++) {
        #pragma unroll
        for (int nt = 0; nt < 4; nt++) {
            int col = n0 + nw + nt*8 + 2*t;
            float b0v = bias[col], b1v = bias[col+1];
            int r0 = m0 + mw + mt*16 + g;
            int r1 = r0 + 8;
            float v00 = (acc[mt][nt][0] + b0v) * oscale;
            float v01 = (acc[mt][nt][1] + b1v) * oscale;
            float v10 = (acc[mt][nt][2] + b0v) * oscale;
            float v11 = (acc[mt][nt][3] + b1v) * oscale;
            if (relu) {
                v00 = fmaxf(v00, 0.f); v01 = fmaxf(v01, 0.f);
                v10 = fmaxf(v10, 0.f); v11 = fmaxf(v11, 0.f);
            }
            if (Cf) {
                if (r0 < M) { float2 o = {v00, v01}; *(float2*)(Cf + (size_t)r0*N + col) = o; }
                if (r1 < M) { float2 o = {v10, v11}; *(float2*)(Cf + (size_t)r1*N + col) = o; }
            } else {
                if (r0 < M) {
                    __nv_bfloat162 lo; __nv_bfloat162 hi = bsplit2(v00, v01, &lo);
                    *(__nv_bfloat162*)(Ch + (size_t)r0*N + col) = hi;
                    *(__nv_bfloat162*)(Cl + (size_t)r0*N + col) = lo;
                }
                if (r1 < M) {
                    __nv_bfloat162 lo; __nv_bfloat162 hi = bsplit2(v10, v11, &lo);
                    *(__nv_bfloat162*)(Ch + (size_t)r1*N + col) = hi;
                    *(__nv_bfloat162*)(Cl + (size_t)r1*N + col) = lo;
                }
            }
        }
    }
}

__global__ __launch_bounds__(128, 4)
void mma_gemm(const __nv_bfloat16* __restrict__ Agh,
              const __nv_bfloat16* __restrict__ Agl,
              const __nv_bfloat16* __restrict__ Bgh,
              const __nv_bfloat16* __restrict__ Bgl,
              const float* __restrict__ bias,
              float* __restrict__ Cf,
              __nv_bfloat16* __restrict__ Ch,
              __nv_bfloat16* __restrict__ Cl,
              int M, int N, int K, int relu)
{
    mma_body(Agh, Agl, Bgh, Bgl, bias, Cf, Ch, Cl, M, N, K, relu, 1.f,
             blockIdx.x, blockIdx.y);
}

// fused QKV: writes bf16-split Q (pre-scaled by 1/sqrt(hd)), K, V
__global__ __launch_bounds__(128, 4)
void qkv_mma(const __nv_bfloat16* __restrict__ xh,
             const __nv_bfloat16* __restrict__ xl,
             const __nv_bfloat16* __restrict__ wth,
             const __nv_bfloat16* __restrict__ wtl,
             const float* __restrict__ bq,
             const float* __restrict__ bk,
             const float* __restrict__ bv,
             __nv_bfloat16* __restrict__ Qh, __nv_bfloat16* __restrict__ Ql,
             __nv_bfloat16* __restrict__ Kh, __nv_bfloat16* __restrict__ Kl,
             __nv_bfloat16* __restrict__ Vh, __nv_bfloat16* __restrict__ Vl)
{
    int z = blockIdx.z;
    const __nv_bfloat16* Wh = wth + (size_t)z*D*D;
    const __nv_bfloat16* Wl = wtl + (size_t)z*D*D;
    const float* bias = (z == 0) ? bq : (z == 1) ? bk : bv;
    __nv_bfloat16* Ch = (z == 0) ? Qh : (z == 1) ? Kh : Vh;
    __nv_bfloat16* Cl = (z == 0) ? Ql : (z == 1) ? Kl : Vl;
    float sc = (z == 0) ? 0.17677669529663687f : 1.f;
    mma_body(xh, xl, Wh, Wl, bias, nullptr, Ch, Cl, MTOK, D, D, 0, sc,
             blockIdx.x, blockIdx.y);
}

// ---------------- tensor-core flash attention (bf16x3, K/V double-buffered) --
// smem: one pool [2 buf][4 arrays (kh,kl,vh,vl)][64][40]; Q aliases buf 1
// (Q is consumed into registers before buf 1 is first written at kt=0).
__global__ __launch_bounds__(128)
void attn_mma_kernel()
{
    __shared__ __align__(16) __nv_bfloat16 pool[2][4][64][40];  // 40960 B

    int qt = blockIdx.x;           // 0..16
    int h  = blockIdx.y;
    int b  = blockIdx.z;
    int tid = threadIdx.x, lane = tid & 31, w = tid >> 5;
    int g = lane >> 2, t = lane & 3;
    int mw = w * 16;

    size_t hoff = ((size_t)b * SLEN) * D + h * HD;
    const __nv_bfloat16* qhg = g_qh + hoff;
    const __nv_bfloat16* qlg = g_ql + hoff;
    const __nv_bfloat16* khg = g_kh + hoff;
    const __nv_bfloat16* klg = g_kl + hoff;
    const __nv_bfloat16* vhg = g_vh + hoff;
    const __nv_bfloat16* vlg = g_vl + hoff;

    int lr = tid >> 1;             // 0..63
    int lc = (tid & 1) * 16;       // 0 / 16 bf16

#define KSH(buf) (pool[buf][0])
#define KSL(buf) (pool[buf][1])
#define VSH(buf) (pool[buf][2])
#define VSL(buf) (pool[buf][3])
#define QSH      (pool[1][0])
#define QSL      (pool[1][1])

#define AT_ISSUE(buf, kt) do { \
    int _ck = min((kt)*64 + lr, SLEN-1); \
    const __nv_bfloat16* _a0 = khg + (size_t)_ck*D + lc; \
    const __nv_bfloat16* _a1 = klg + (size_t)_ck*D + lc; \
    const __nv_bfloat16* _a2 = vhg + (size_t)_ck*D + lc; \
    const __nv_bfloat16* _a3 = vlg + (size_t)_ck*D + lc; \
    CPA16(&KSH(buf)[lr][lc],   _a0,     16); CPA16(&KSH(buf)[lr][lc+8], _a0 + 8, 16); \
    CPA16(&KSL(buf)[lr][lc],   _a1,     16); CPA16(&KSL(buf)[lr][lc+8], _a1 + 8, 16); \
    CPA16(&VSH(buf)[lr][lc],   _a2,     16); CPA16(&VSH(buf)[lr][lc+8], _a2 + 8, 16); \
    CPA16(&VSL(buf)[lr][lc],   _a3,     16); CPA16(&VSL(buf)[lr][lc+8], _a3 + 8, 16); \
    asm volatile("cp.async.commit_group;"); \
} while (0)

    // G0: Q tile into buf1 region; G1: first K/V tile into buf0
    {
        int cq = min(qt*64 + lr, SLEN-1);
        const __nv_bfloat16* s0 = qhg + (size_t)cq*D + lc;
        const __nv_bfloat16* s1 = qlg + (size_t)cq*D + lc;
        CPA16(&QSH[lr][lc],   s0,     16);
        CPA16(&QSH[lr][lc+8], s0 + 8, 16);
        CPA16(&QSL[lr][lc],   s1,     16);
        CPA16(&QSL[lr][lc+8], s1 + 8, 16);
        asm volatile("cp.async.commit_group;");
        AT_ISSUE(0, 0);
        asm volatile("cp.async.wait_group 1;");   // Q landed
    }
    __syncthreads();

    // Q fragments (A m16k16) — consume Q from buf1 region into registers
    uint32_t qfh[2][4], qfl[2][4];
    {
        int r = mw + (lane & 15);
        int cb = (lane >> 4) * 8;
        LDSM4(qfh[0][0], qfh[0][1], qfh[0][2], qfh[0][3], sptr(&QSH[r][cb]));
        LDSM4(qfh[1][0], qfh[1][1], qfh[1][2], qfh[1][3], sptr(&QSH[r][16 + cb]));
        LDSM4(qfl[0][0], qfl[0][1], qfl[0][2], qfl[0][3], sptr(&QSL[r][cb]));
        LDSM4(qfl[1][0], qfl[1][1], qfl[1][2], qfl[1][3], sptr(&QSL[r][16 + cb]));
    }
    __syncthreads();               // all Q reads done before buf1 is re-used

    float m0 = -INFINITY, m1 = -INFINITY, l0 = 0.f, l1 = 0.f;
    float o[4][4];
    #pragma unroll
    for (int nd = 0; nd < 4; nd++)
        #pragma unroll
        for (int i = 0; i < 4; i++) o[nd][i] = 0.f;

    for (int kt = 0; kt < 17; kt++) {
        int cur = kt & 1;
        int k0 = kt * 64;
        if (kt + 1 < 17) {
            AT_ISSUE(cur ^ 1, kt + 1);
            asm volatile("cp.async.wait_group 1;");
        } else {
            asm volatile("cp.async.wait_group 0;");
        }
        __syncthreads();

        // ---- S = Q K^T (3-term bf16x3) ----
        float s[8][4];
        #pragma unroll
        for (int j = 0; j < 8; j++)
            #pragma unroll
            for (int i = 0; i < 4; i++) s[j][i] = 0.f;

        #pragma unroll
        for (int j = 0; j < 8; j++) {
            uint32_t bh[4], bl[4];
            int rr = j*8 + (lane & 7);
            int cc = ((lane >> 3) & 3) * 8;
            LDSM4(bh[0], bh[1], bh[2], bh[3], sptr(&KSH(cur)[rr][cc]));
            LDSM4(bl[0], bl[1], bl[2], bl[3], sptr(&KSL(cur)[rr][cc]));
            MMA_BF16(s[j], qfh[0], bh);
            MMA_BF16(s[j], qfh[1], bh + 2);
            MMA_BF16(s[j], qfh[0], bl);
            MMA_BF16(s[j], qfh[1], bl + 2);
            MMA_BF16(s[j], qfl[0], bh);
            MMA_BF16(s[j], qfl[1], bh + 2);
        }

        // mask invalid tokens (only last tile)
        if (k0 + 64 > SLEN) {
            #pragma unroll
            for (int j = 0; j < 8; j++) {
                int tok = k0 + j*8 + 2*t;
                if (tok     >= SLEN) { s[j][0] = -1e30f; s[j][2] = -1e30f; }
                if (tok + 1 >= SLEN) { s[j][1] = -1e30f; s[j][3] = -1e30f; }
            }
        }

        // ---- online softmax ----
        float t0v = -INFINITY, t1v = -INFINITY;
        #pragma unroll
        for (int j = 0; j < 8; j++) {
            t0v = fmaxf(t0v, fmaxf(s[j][0], s[j][1]));
            t1v = fmaxf(t1v, fmaxf(s[j][2], s[j][3]));
        }
        t0v = fmaxf(t0v, __shfl_xor_sync(0xffffffffu, t0v, 1));
        t0v = fmaxf(t0v, __shfl_xor_sync(0xffffffffu, t0v, 2));
        t1v = fmaxf(t1v, __shfl_xor_sync(0xffffffffu, t1v, 1));
        t1v = fmaxf(t1v, __shfl_xor_sync(0xffffffffu, t1v, 2));

        float mn0 = fmaxf(m0, t0v), mn1 = fmaxf(m1, t1v);
        float c0 = __expf(m0 - mn0), c1 = __expf(m1 - mn1);
        l0 *= c0; l1 *= c1;
        #pragma unroll
        for (int nd = 0; nd < 4; nd++) {
            o[nd][0] *= c0; o[nd][1] *= c0;
            o[nd][2] *= c1; o[nd][3] *= c1;
        }

        float ls0 = 0.f, ls1 = 0.f;
        #pragma unroll
        for (int j = 0; j < 8; j++) {
            s[j][0] = __expf(s[j][0] - mn0); ls0 += s[j][0];
            s[j][1] = __expf(s[j][1] - mn0); ls0 += s[j][1];
            s[j][2] = __expf(s[j][2] - mn1); ls1 += s[j][2];
            s[j][3] = __expf(s[j][3] - mn1); ls1 += s[j][3];
        }
        l0 += ls0; l1 += ls1;
        m0 = mn0; m1 = mn1;

        // ---- P -> A fragments (hi/lo split, in registers) ----
        uint32_t ph[4][4], pl[4][4];
        #pragma unroll
        for (int c = 0; c < 4; c++) {
            psplit(s[2*c][0],   s[2*c][1],   ph[c][0], pl[c][0]);
            psplit(s[2*c][2],   s[2*c][3],   ph[c][1], pl[c][1]);
            psplit(s[2*c+1][0], s[2*c+1][1], ph[c][2], pl[c][2]);
            psplit(s[2*c+1][2], s[2*c+1][3], ph[c][3], pl[c][3]);
        }

        // ---- O += P V (3-term) ----
        #pragma unroll
        for (int nd = 0; nd < 4; nd++) {
            uint32_t bvh[4][2], bvl[4][2];
            #pragma unroll
            for (int cc = 0; cc < 2; cc++) {
                uint32_t va = sptr(&VSH(cur)[cc*32 + lane][nd*8]);
                uint32_t la = sptr(&VSL(cur)[cc*32 + lane][nd*8]);
                LDSM4T(bvh[2*cc][0], bvh[2*cc][1], bvh[2*cc+1][0], bvh[2*cc+1][1], va);
                LDSM4T(bvl[2*cc][0], bvl[2*cc][1], bvl[2*cc+1][0], bvl[2*cc+1][1], la);
            }
            #pragma unroll
            for (int c = 0; c < 4; c++) {
                MMA_BF16(o[nd], ph[c], bvh[c]);
                MMA_BF16(o[nd], ph[c], bvl[c]);
                MMA_BF16(o[nd], pl[c], bvh[c]);
            }
        }
        __syncthreads();   // reads of 'cur' done before next issue into it
    }
#undef AT_ISSUE
#undef KSH
#undef KSL
#undef VSH
#undef VSL
#undef QSH
#undef QSL

    // final: reduce l over quad, normalize, write bf16-split output
    l0 += __shfl_xor_sync(0xffffffffu, l0, 1);
    l0 += __shfl_xor_sync(0xffffffffu, l0, 2);
    l1 += __shfl_xor_sync(0xffffffffu, l1, 1);
    l1 += __shfl_xor_sync(0xffffffffu, l1, 2);
    float i0 = 1.f / l0, i1 = 1.f / l1;

    int q0 = qt*64 + mw + g;
    int q1 = q0 + 8;
    int colb = h*HD + 2*t;
    #pragma unroll
    for (int nd = 0; nd < 4; nd++) {
        if (q0 < SLEN) {
            __nv_bfloat162 lo;
            __nv_bfloat162 hi = bsplit2(o[nd][0]*i0, o[nd][1]*i0, &lo);
            size_t off = ((size_t)b*SLEN + q0)*D + colb + nd*8;
            *(__nv_bfloat162*)(g_ah + off) = hi;
            *(__nv_bfloat162*)(g_al + off) = lo;
        }
        if (q1 < SLEN) {
            __nv_bfloat162 lo;
            __nv_bfloat162 hi = bsplit2(o[nd][2]*i1, o[nd][3]*i1, &lo);
            size_t off = ((size_t)b*SLEN + q1)*D + colb + nd*8;
            *(__nv_bfloat162*)(g_ah + off) = hi;
            *(__nv_bfloat162*)(g_al + off) = lo;
        }
    }
}

// ---------- fused residual + LayerNorm, warp-per-row; f32 + bf16-split out ---
__global__ void ln_kernel(const float* __restrict__ A,
                          const float* __restrict__ Bsrc,
                          const float* __restrict__ g,
                          const float* __restrict__ bta,
                          float* __restrict__ out,
                          __nv_bfloat16* __restrict__ oh,
                          __nv_bfloat16* __restrict__ ol)
{
    int warp = threadIdx.x >> 5;
    int lane = threadIdx.x & 31;
    int row = blockIdx.x * 8 + warp;
    size_t base = (size_t)row * D;

    const float4* ap = (const float4*)(A + base);
    const float4* bp = (const float4*)(Bsrc + base);
    float4 a0 = ap[lane], a1 = ap[lane + 32];
    float4 b0 = bp[lane], b1 = bp[lane + 32];
    float v[8];
    v[0]=a0.x+b0.x; v[1]=a0.y+b0.y; v[2]=a0.z+b0.z; v[3]=a0.w+b0.w;
    v[4]=a1.x+b1.x; v[5]=a1.y+b1.y; v[6]=a1.z+b1.z; v[7]=a1.w+b1.w;

    float s = 0.f, s2 = 0.f;
    #pragma unroll
    for (int i = 0; i < 8; i++) { s += v[i]; s2 = fmaf(v[i], v[i], s2); }
    #pragma unroll
    for (int o = 16; o > 0; o >>= 1) {
        s  += __shfl_xor_sync(0xffffffffu, s,  o);
        s2 += __shfl_xor_sync(0xffffffffu, s2, o);
    }
    float mu = s * (1.f/256.f);
    float var = s2 * (1.f/256.f) - mu*mu;
    float rstd = rsqrtf(var + 1e-5f);

    const float4* gp = (const float4*)g;
    const float4* tp = (const float4*)bta;
    float4 g0 = gp[lane], g1 = gp[lane+32];
    float4 t0 = tp[lane], t1 = tp[lane+32];
    float4 o0, o1;
    o0.x = (v[0]-mu)*rstd*g0.x + t0.x;
    o0.y = (v[1]-mu)*rstd*g0.y + t0.y;
    o0.z = (v[2]-mu)*rstd*g0.z + t0.z;
    o0.w = (v[3]-mu)*rstd*g0.w + t0.w;
    o1.x = (v[4]-mu)*rstd*g1.x + t1.x;
    o1.y = (v[5]-mu)*rstd*g1.y + t1.y;
    o1.z = (v[6]-mu)*rstd*g1.z + t1.z;
    o1.w = (v[7]-mu)*rstd*g1.w + t1.w;
    float4* op = (float4*)(out + base);
    op[lane]      = o0;
    op[lane + 32] = o1;

    size_t e0 = base + (size_t)lane*4;
    size_t e1 = base + (size_t)(lane+32)*4;
    __nv_bfloat162 lo, hi;
    hi = bsplit2(o0.x, o0.y, &lo);
    *(__nv_bfloat162*)(oh + e0)     = hi; *(__nv_bfloat162*)(ol + e0)     = lo;
    hi = bsplit2(o0.z, o0.w, &lo);
    *(__nv_bfloat162*)(oh + e0 + 2) = hi; *(__nv_bfloat162*)(ol + e0 + 2) = lo;
    hi = bsplit2(o1.x, o1.y, &lo);
    *(__nv_bfloat162*)(oh + e1)     = hi; *(__nv_bfloat162*)(ol + e1)     = lo;
    hi = bsplit2(o1.z, o1.w, &lo);
    *(__nv_bfloat162*)(oh + e1 + 2) = hi; *(__nv_bfloat162*)(ol + e1 + 2) = lo;
}

// ---------------- final: LN cls row only + 2-layer head ----------------------
__global__ void head_kernel(const float* __restrict__ g,
                            const float* __restrict__ bta,
                            const float* __restrict__ Wh1,
                            const float* __restrict__ bh1,
                            const float* __restrict__ Wh2,
                            const float* __restrict__ bh2,
                            float* __restrict__ out)
{
    int b = blockIdx.x;
    int d = threadIdx.x;
    float v = g_x[(size_t)b*SLEN*D + d];

    float s = v, s2 = v*v;
    #pragma unroll
    for (int o = 16; o > 0; o >>= 1) {
        s  += __shfl_xor_sync(0xffffffffu, s,  o);
        s2 += __shfl_xor_sync(0xffffffffu, s2, o);
    }
    __shared__ float ws[8], ws2[8];
    __shared__ float mu_s, rstd_s;
    int w = d >> 5;
    if ((d & 31) == 0) { ws[w] = s; ws2[w] = s2; }
    __syncthreads();
    if (d == 0) {
        float S1 = 0.f, S2 = 0.f;
        #pragma unroll
        for (int i = 0; i < 8; i++) { S1 += ws[i]; S2 += ws2[i]; }
        float mu = S1 * (1.f/256.f);
        float var = S2 * (1.f/256.f) - mu*mu;
        mu_s = mu;
        rstd_s = rsqrtf(var + 1e-5f);
    }
    __syncthreads();

    __shared__ float clsr[256];
    __shared__ float hid[256];
    float c = (v - mu_s) * rstd_s * g[d] + bta[d];
    clsr[d] = c;
    out[b*D + d] = c;                       // cls_out
    __syncthreads();

    float hsum = bh1[d];
    #pragma unroll 8
    for (int k = 0; k < 256; k++) hsum = fmaf(clsr[k], Wh1[k*256 + d], hsum);
    hid[d] = fmaxf(hsum, 0.f);
    __syncthreads();

    if (d < 2) {
        float lg = bh2[d];
        for (int k = 0; k < 256; k++) lg = fmaf(hid[k], Wh2[k*2 + d], lg);
        out[BB*D + b*2 + d] = lg;           // logits after cls_out block
    }
}

// ---------------- launcher ---------------------------------------------------
extern "C" void kernel_launch(void* const* d_in, const int* in_sizes, int n_in,
                              void* d_out, int out_size)
{
    (void)in_sizes; (void)n_in; (void)out_size;

    const float* cf   = (const float*)d_in[0];
    const int*   xc   = (const int*)  d_in[1];
    const int*   yc   = (const int*)  d_in[2];
    const float* Wemb = (const float*)d_in[3];
    const float* bemb = (const float*)d_in[4];
    const float* Wct1 = (const float*)d_in[5];
    const float* bct1 = (const float*)d_in[6];
    const float* Wct2 = (const float*)d_in[7];
    const float* bct2 = (const float*)d_in[8];
    const float* cls  = (const float*)d_in[9];
    const float* Wq = (const float*)d_in[10]; const float* bq = (const float*)d_in[11];
    const float* Wk = (const float*)d_in[12]; const float* bk = (const float*)d_in[13];
    const float* Wv = (const float*)d_in[14]; const float* bv = (const float*)d_in[15];
    const float* Wo = (const float*)d_in[16]; const float* bo = (const float*)d_in[17];
    const float* ln1g = (const float*)d_in[18]; const float* ln1b = (const float*)d_in[19];
    const float* ln2g = (const float*)d_in[20]; const float* ln2b = (const float*)d_in[21];
    const float* Wf1 = (const float*)d_in[22]; const float* bf1 = (const float*)d_in[23];
    const float* Wf2 = (const float*)d_in[24]; const float* bf2 = (const float*)d_in[25];
    const float* lnfg = (const float*)d_in[26]; const float* lnfb = (const float*)d_in[27];
    const float* Wh1 = (const float*)d_in[28]; const float* bh1 = (const float*)d_in[29];
    const float* Wh2 = (const float*)d_in[30]; const float* bh2 = (const float*)d_in[31];
    float* out = (float*)d_out;

    void* p;
    cudaGetSymbolAddress(&p, g_x);  float* xb = (float*)p;
    cudaGetSymbolAddress(&p, g_t);  float* tb = (float*)p;
    cudaGetSymbolAddress(&p, g_xh); __nv_bfloat16* xh = (__nv_bfloat16*)p;
    cudaGetSymbolAddress(&p, g_xl); __nv_bfloat16* xl = (__nv_bfloat16*)p;
    cudaGetSymbolAddress(&p, g_ah); __nv_bfloat16* ah = (__nv_bfloat16*)p;
    cudaGetSymbolAddress(&p, g_al); __nv_bfloat16* al = (__nv_bfloat16*)p;
    cudaGetSymbolAddress(&p, g_hh); __nv_bfloat16* hh = (__nv_bfloat16*)p;
    cudaGetSymbolAddress(&p, g_hl); __nv_bfloat16* hl = (__nv_bfloat16*)p;
    cudaGetSymbolAddress(&p, g_qh); __nv_bfloat16* qh = (__nv_bfloat16*)p;
    cudaGetSymbolAddress(&p, g_ql); __nv_bfloat16* ql = (__nv_bfloat16*)p;
    cudaGetSymbolAddress(&p, g_kh); __nv_bfloat16* kh = (__nv_bfloat16*)p;
    cudaGetSymbolAddress(&p, g_kl); __nv_bfloat16* kl = (__nv_bfloat16*)p;
    cudaGetSymbolAddress(&p, g_vh); __nv_bfloat16* vh = (__nv_bfloat16*)p;
    cudaGetSymbolAddress(&p, g_vl); __nv_bfloat16* vl = (__nv_bfloat16*)p;
    cudaGetSymbolAddress(&p, g_wth); __nv_bfloat16* wth = (__nv_bfloat16*)p;
    cudaGetSymbolAddress(&p, g_wtl); __nv_bfloat16* wtl = (__nv_bfloat16*)p;

    // upfront: weight split + transpose (all layers)
    {
        dim3 gdd((D*D)/256, NL);
        wconv_kernel<<<gdd, 256>>>(Wq, wth + 0,       wtl + 0,       D, D, D*D, 3*D*D);
        wconv_kernel<<<gdd, 256>>>(Wk, wth + D*D,     wtl + D*D,     D, D, D*D, 3*D*D);
        wconv_kernel<<<gdd, 256>>>(Wv, wth + 2*D*D,   wtl + 2*D*D,   D, D, D*D, 3*D*D);
        wconv_kernel<<<gdd, 256>>>(Wo, wth + WOFF_WO, wtl + WOFF_WO, D, D, D*D, D*D);
        dim3 gdf((D*DFF)/256, NL);
        wconv_kernel<<<gdf, 256>>>(Wf1, wth + WOFF_F1, wtl + WOFF_F1, D, DFF, D*DFF, D*DFF);
        wconv_kernel<<<gdf, 256>>>(Wf2, wth + WOFF_F2, wtl + WOFF_F2, DFF, D, D*DFF, D*DFF);
    }

    embed_kernel<<<MTOK, 256>>>(cf, xc, yc, Wemb, bemb, Wct1, bct1, Wct2, bct2, cls);

    int MB = (MTOK + 63) / 64;             // 129
    dim3 gqkv(MB, D/64, 3);                // 129 x 4 x 3
    dim3 gdd2(MB, D/64);                   // 129 x 4
    dim3 gff (MB, DFF/64);                 // 129 x 16
    dim3 gattn(17, NH, BB);                // 17 x 8 x 8
    int lngrid = MTOK / 8;                 // 1025

    for (int l = 0; l < NL; l++) {
        qkv_mma<<<gqkv, 128>>>(xh, xl,
                               wth + (size_t)l*3*D*D, wtl + (size_t)l*3*D*D,
                               bq + l*D, bk + l*D, bv + l*D,
                               qh, ql, kh, kl, vh, vl);
        attn_mma_kernel<<<gattn, 128>>>();
        mma_gemm<<<gdd2, 128>>>(ah, al,
                                wth + WOFF_WO + (size_t)l*D*D,
                                wtl + WOFF_WO + (size_t)l*D*D,
                                bo + l*D, tb, nullptr, nullptr, MTOK, D, D, 0);
        ln_kernel<<<lngrid, 256>>>(xb, tb, ln1g + l*D, ln1b + l*D, xb, xh, xl);
        mma_gemm<<<gff, 128>>>(xh, xl,
                               wth + WOFF_F1 + (size_t)l*D*DFF,
                               wtl + WOFF_F1 + (size_t)l*D*DFF,
                               bf1 + l*DFF, nullptr, hh, hl, MTOK, DFF, D, 1);
        mma_gemm<<<gdd2, 128>>>(hh, hl,
                                wth + WOFF_F2 + (size_t)l*D*DFF,
                                wtl + WOFF_F2 + (size_t)l*D*DFF,
                                bf2 + l*D, tb, nullptr, nullptr, MTOK, D, DFF, 0);
        ln_kernel<<<lngrid, 256>>>(xb, tb, ln2g + l*D, ln2b + l*D, xb, xh, xl);
    }

    head_kernel<<<BB, 256>>>(lnfg, lnfb, Wh1, bh1, Wh2, bh2, out);
}

// round 16
// speedup vs baseline: 2.8569x; 1.0704x over previous
#include <cuda_runtime.h>
#include <cuda_bf16.h>
#include <math.h>
#include <stdint.h>

#define BB   8
#define NCELL 1024
#define SLEN 1025
#define D    256
#define NH   8
#define HD   32
#define DFF  1024
#define NL   4
#define MTOK (BB*SLEN)   // 8200

// cp.async helper: 16B global->shared, zero-fill when sz==0
#define CPA16(dst, src, sz) \
    asm volatile("cp.async.cg.shared.global [%0], [%1], 16, %2;" \
        :: "r"((uint32_t)__cvta_generic_to_shared(dst)), "l"(src), "r"(sz))

// bf16 tensor-core mma: C(f32) += A(bf16) * B(bf16), m16n8k16 row.col
#define MMA_BF16(c, a, b) \
    asm volatile("mma.sync.aligned.m16n8k16.row.col.f32.bf16.bf16.f32 " \
        "{%0,%1,%2,%3}, {%4,%5,%6,%7}, {%8,%9}, {%0,%1,%2,%3};" \
        : "+f"((c)[0]), "+f"((c)[1]), "+f"((c)[2]), "+f"((c)[3]) \
        : "r"((a)[0]), "r"((a)[1]), "r"((a)[2]), "r"((a)[3]), \
          "r"((b)[0]), "r"((b)[1]))

#define LDSM4(d0,d1,d2,d3,a) \
    asm volatile("ldmatrix.sync.aligned.m8n8.x4.shared.b16 {%0,%1,%2,%3}, [%4];" \
        : "=r"(d0),"=r"(d1),"=r"(d2),"=r"(d3) : "r"(a))
#define LDSM4T(d0,d1,d2,d3,a) \
    asm volatile("ldmatrix.sync.aligned.m8n8.x4.trans.shared.b16 {%0,%1,%2,%3}, [%4];" \
        : "=r"(d0),"=r"(d1),"=r"(d2),"=r"(d3) : "r"(a))

#define CVTPK(d, hi, lo) \
    asm("cvt.rn.bf16x2.f32 %0, %1, %2;" : "=r"(d) : "f"(hi), "f"(lo))

__device__ __forceinline__ uint32_t sptr(const void* p) {
    return (uint32_t)__cvta_generic_to_shared(p);
}

// pack (p0,p1) -> bf16x2 hi word + bf16x2 residual word
__device__ __forceinline__ void psplit(float p0, float p1, uint32_t& hi, uint32_t& lo)
{
    CVTPK(hi, p1, p0);
    float f0 = __uint_as_float(hi << 16);
    float f1 = __uint_as_float(hi & 0xffff0000u);
    CVTPK(lo, p1 - f1, p0 - f0);
}

// ---------------- scratch (static device globals; no allocs) ----------------
__device__ float g_x[MTOK*D];
__device__ float g_t[MTOK*D];

// bf16 hi/lo split activations
__device__ __nv_bfloat16 g_xh[MTOK*D],  g_xl[MTOK*D];
__device__ __nv_bfloat16 g_ah[MTOK*D],  g_al[MTOK*D];
__device__ __nv_bfloat16 g_hh[(size_t)MTOK*DFF], g_hl[(size_t)MTOK*DFF];
__device__ __nv_bfloat16 g_qh[MTOK*D],  g_ql[MTOK*D];
__device__ __nv_bfloat16 g_kh[MTOK*D],  g_kl[MTOK*D];
__device__ __nv_bfloat16 g_vh[MTOK*D],  g_vl[MTOK*D];

// bf16 hi/lo split transposed weights [N][K]
#define WOFF_WO  (12*D*D)
#define WOFF_F1  (16*D*D)
#define WOFF_F2  (WOFF_F1 + 4*D*DFF)
#define WT_TOTAL (WOFF_F2 + 4*D*DFF)
__device__ __nv_bfloat16 g_wth[WT_TOTAL], g_wtl[WT_TOTAL];

__device__ __forceinline__ __nv_bfloat162 bsplit2(float a, float b, __nv_bfloat162* lo)
{
    __nv_bfloat16 ha = __float2bfloat16_rn(a);
    __nv_bfloat16 hb = __float2bfloat16_rn(b);
    lo->x = __float2bfloat16_rn(a - __bfloat162float(ha));
    lo->y = __float2bfloat16_rn(b - __bfloat162float(hb));
    __nv_bfloat162 hi; hi.x = ha; hi.y = hb;
    return hi;
}

// ---------------- embedding: emb + cell-type MLP + positional + cls ----------
__global__ void embed_kernel(const float* __restrict__ cf,
                             const int* __restrict__ xc,
                             const int* __restrict__ yc,
                             const float* __restrict__ Wemb,
                             const float* __restrict__ bemb,
                             const float* __restrict__ Wct1,
                             const float* __restrict__ bct1,
                             const float* __restrict__ Wct2,
                             const float* __restrict__ bct2,
                             const float* __restrict__ cls)
{
    int blk = blockIdx.x;          // 0..8199
    int b = blk / SLEN;
    int s = blk % SLEN;
    int d = threadIdx.x;           // 0..255
    float* out = g_x + (size_t)blk * D;

    float val;
    if (s == 0) {
        val = cls[d];
    } else {
        int n = s - 1;
        __shared__ float cfs[64];
        __shared__ float hs[128];
        const float* cfp = cf + ((size_t)b*NCELL + n)*64;
        if (d < 64) cfs[d] = cfp[d];
        __syncthreads();

        if (d < 128) {
            float acc = bct1[d];
            #pragma unroll
            for (int k = 0; k < 64; k++) acc = fmaf(cfs[k], Wct1[k*128 + d], acc);
            hs[d] = fmaxf(acc, 0.f);
        }
        __syncthreads();

        float e = bemb[d];
        #pragma unroll
        for (int k = 0; k < 64; k++) e = fmaf(cfs[k], Wemb[k*256 + d], e);
        float c2 = bct2[d];
        #pragma unroll
        for (int j = 0; j < 128; j++) c2 = fmaf(hs[j], Wct2[j*256 + d], c2);

        int dd    = (d < 128) ? d : d - 128;
        int coord = (d < 128) ? xc[b*NCELL + n] : yc[b*NCELL + n];
        coord = min(max(coord, 0), 999);
        int m = dd >> 1;
        const float c1 = -0.07195578739046225f;  // float(-ln(10000)/128)
        float dv  = expf((float)(2*m) * c1);
        float ang = (float)coord * dv;
        float p   = (dd & 1) ? cosf(ang) : sinf(ang);
        val = e + c2 + p;
    }

    out[d] = val;
    __nv_bfloat16 hh = __float2bfloat16_rn(val);
    g_xh[(size_t)blk*D + d] = hh;
    g_xl[(size_t)blk*D + d] = __float2bfloat16_rn(val - __bfloat162float(hh));
}

// ---------------- weight convert: W[K][N] f32 -> Wt[N][K] bf16 hi/lo ---------
__global__ void wconv_kernel(const float* __restrict__ src,
                             __nv_bfloat16* __restrict__ dh,
                             __nv_bfloat16* __restrict__ dl,
                             int K, int N, int srcStride, int dstStride)
{
    int l = blockIdx.y;
    int idx = blockIdx.x*256 + threadIdx.x;
    int n = idx / K;
    int k = idx - n*K;
    float v = src[(size_t)l*srcStride + (size_t)k*N + n];
    __nv_bfloat16 h = __float2bfloat16_rn(v);
    dh[(size_t)l*dstStride + idx] = h;
    dl[(size_t)l*dstStride + idx] = __float2bfloat16_rn(v - __bfloat162float(h));
}

// ---- bf16x3 tensor-core GEMM: C = (A@W + bias)*oscale; BM=BN=64 BK=32 -------
// ldmatrix fragment loads (mappings identical to the proven attention kernel).
__device__ __forceinline__
void mma_body(const __nv_bfloat16* __restrict__ Agh,
              const __nv_bfloat16* __restrict__ Agl,
              const __nv_bfloat16* __restrict__ Bgh,
              const __nv_bfloat16* __restrict__ Bgl,
              const float* __restrict__ bias,
              float* __restrict__ Cf,
              __nv_bfloat16* __restrict__ Ch,
              __nv_bfloat16* __restrict__ Cl,
              int M, int N, int K, int relu, float oscale, int bx, int by)
{
    __shared__ __align__(16) __nv_bfloat16 Ahs[2][64][40], Als[2][64][40];
    __shared__ __align__(16) __nv_bfloat16 Bhs[2][64][40], Bls[2][64][40];

    int tid  = threadIdx.x;        // 0..127
    int lane = tid & 31;
    int wid  = tid >> 5;
    int m0 = bx * 64, n0 = by * 64;
    int g = lane >> 2, t = lane & 3;
    int mw = (wid & 1) * 32;
    int nw = (wid >> 1) * 32;

    int lr = tid >> 1;             // 0..63
    int lc = (tid & 1) * 16;       // 0 or 16 (bf16 offset)

    int gr = m0 + lr;
    int szA = (gr < M) ? 16 : 0;
    int cr  = min(gr, M-1);
    const __nv_bfloat16* pAh = Agh + (size_t)cr*K + lc;
    const __nv_bfloat16* pAl = Agl + (size_t)cr*K + lc;
    const __nv_bfloat16* pBh = Bgh + (size_t)(n0 + lr)*K + lc;
    const __nv_bfloat16* pBl = Bgl + (size_t)(n0 + lr)*K + lc;

    float acc[2][4][4];
    #pragma unroll
    for (int mt = 0; mt < 2; mt++)
        #pragma unroll
        for (int nt = 0; nt < 4; nt++)
            #pragma unroll
            for (int i = 0; i < 4; i++) acc[mt][nt][i] = 0.f;

#define ISSUE_TILE(buf, kt) do { \
    int _k0 = (kt)*32; \
    CPA16(&Ahs[buf][lr][lc],   pAh + _k0,     szA); \
    CPA16(&Ahs[buf][lr][lc+8], pAh + _k0 + 8, szA); \
    CPA16(&Als[buf][lr][lc],   pAl + _k0,     szA); \
    CPA16(&Als[buf][lr][lc+8], pAl + _k0 + 8, szA); \
    CPA16(&Bhs[buf][lr][lc],   pBh + _k0,     16); \
    CPA16(&Bhs[buf][lr][lc+8], pBh + _k0 + 8, 16); \
    CPA16(&Bls[buf][lr][lc],   pBl + _k0,     16); \
    CPA16(&Bls[buf][lr][lc+8], pBl + _k0 + 8, 16); \
    asm volatile("cp.async.commit_group;"); \
} while (0)

    ISSUE_TILE(0, 0);

    int KT = K >> 5;
    for (int kt = 0; kt < KT; kt++) {
        int cur = kt & 1;
        if (kt + 1 < KT) {
            ISSUE_TILE(cur ^ 1, kt + 1);
            asm volatile("cp.async.wait_group 1;");
        } else {
            asm volatile("cp.async.wait_group 0;");
        }
        __syncthreads();

        // A fragments via ldmatrix (m16k16 map: row = base+(lane&15), col = (lane>>4)*8)
        uint32_t ahf[2][2][4], alf[2][2][4];
        #pragma unroll
        for (int mt = 0; mt < 2; mt++) {
            int r = mw + mt*16 + (lane & 15);
            int cb = (lane >> 4) * 8;
            #pragma unroll
            for (int ks = 0; ks < 2; ks++) {
                LDSM4(ahf[mt][ks][0], ahf[mt][ks][1], ahf[mt][ks][2], ahf[mt][ks][3],
                      sptr(&Ahs[cur][r][ks*16 + cb]));
                LDSM4(alf[mt][ks][0], alf[mt][ks][1], alf[mt][ks][2], alf[mt][ks][3],
                      sptr(&Als[cur][r][ks*16 + cb]));
            }
        }

        // B fragments per n-tile via ldmatrix x4 (n8 x k32 map: row = nb+(lane&7), col = (lane>>3)*8)
        #pragma unroll
        for (int nt = 0; nt < 4; nt++) {
            uint32_t bh4[4], bl4[4];
            int rr = nw + nt*8 + (lane & 7);
            int cc = ((lane >> 3) & 3) * 8;
            LDSM4(bh4[0], bh4[1], bh4[2], bh4[3], sptr(&Bhs[cur][rr][cc]));
            LDSM4(bl4[0], bl4[1], bl4[2], bl4[3], sptr(&Bls[cur][rr][cc]));
            #pragma unroll
            for (int ks = 0; ks < 2; ks++) {
                #pragma unroll
                for (int mt = 0; mt < 2; mt++) {
                    MMA_BF16(acc[mt][nt], ahf[mt][ks], bh4 + 2*ks);
                    MMA_BF16(acc[mt][nt], ahf[mt][ks], bl4 + 2*ks);
                    MMA_BF16(acc[mt][nt], alf[mt][ks], bh4 + 2*ks);
                }
            }
        }
        __syncthreads();
    }
#undef ISSUE_TILE

    // epilogue
    #pragma unroll
    for (int mt = 0; mt < 2; mt++) {
        #pragma unroll
        for (int nt = 0; nt < 4; nt++) {
            int col = n0 + nw + nt*8 + 2*t;
            float b0v = bias[col], b1v = bias[col+1];
            int r0 = m0 + mw + mt*16 + g;
            int r1 = r0 + 8;
            float v00 = (acc[mt][nt][0] + b0v) * oscale;
            float v01 = (acc[mt][nt][1] + b1v) * oscale;
            float v10 = (acc[mt][nt][2] + b0v) * oscale;
            float v11 = (acc[mt][nt][3] + b1v) * oscale;
            if (relu) {
                v00 = fmaxf(v00, 0.f); v01 = fmaxf(v01, 0.f);
                v10 = fmaxf(v10, 0.f); v11 = fmaxf(v11, 0.f);
            }
            if (Cf) {
                if (r0 < M) { float2 o = {v00, v01}; *(float2*)(Cf + (size_t)r0*N + col) = o; }
                if (r1 < M) { float2 o = {v10, v11}; *(float2*)(Cf + (size_t)r1*N + col) = o; }
            } else {
                if (r0 < M) {
                    __nv_bfloat162 lo; __nv_bfloat162 hi = bsplit2(v00, v01, &lo);
                    *(__nv_bfloat162*)(Ch + (size_t)r0*N + col) = hi;
                    *(__nv_bfloat162*)(Cl + (size_t)r0*N + col) = lo;
                }
                if (r1 < M) {
                    __nv_bfloat162 lo; __nv_bfloat162 hi = bsplit2(v10, v11, &lo);
                    *(__nv_bfloat162*)(Ch + (size_t)r1*N + col) = hi;
                    *(__nv_bfloat162*)(Cl + (size_t)r1*N + col) = lo;
                }
            }
        }
    }
}

__global__ __launch_bounds__(128, 4)
void mma_gemm(const __nv_bfloat16* __restrict__ Agh,
              const __nv_bfloat16* __restrict__ Agl,
              const __nv_bfloat16* __restrict__ Bgh,
              const __nv_bfloat16* __restrict__ Bgl,
              const float* __restrict__ bias,
              float* __restrict__ Cf,
              __nv_bfloat16* __restrict__ Ch,
              __nv_bfloat16* __restrict__ Cl,
              int M, int N, int K, int relu)
{
    mma_body(Agh, Agl, Bgh, Bgl, bias, Cf, Ch, Cl, M, N, K, relu, 1.f,
             blockIdx.x, blockIdx.y);
}

// fused QKV: writes bf16-split Q (pre-scaled by 1/sqrt(hd)), K, V
__global__ __launch_bounds__(128, 4)
void qkv_mma(const __nv_bfloat16* __restrict__ xh,
             const __nv_bfloat16* __restrict__ xl,
             const __nv_bfloat16* __restrict__ wth,
             const __nv_bfloat16* __restrict__ wtl,
             const float* __restrict__ bq,
             const float* __restrict__ bk,
             const float* __restrict__ bv,
             __nv_bfloat16* __restrict__ Qh, __nv_bfloat16* __restrict__ Ql,
             __nv_bfloat16* __restrict__ Kh, __nv_bfloat16* __restrict__ Kl,
             __nv_bfloat16* __restrict__ Vh, __nv_bfloat16* __restrict__ Vl)
{
    int z = blockIdx.z;
    const __nv_bfloat16* Wh = wth + (size_t)z*D*D;
    const __nv_bfloat16* Wl = wtl + (size_t)z*D*D;
    const float* bias = (z == 0) ? bq : (z == 1) ? bk : bv;
    __nv_bfloat16* Ch = (z == 0) ? Qh : (z == 1) ? Kh : Vh;
    __nv_bfloat16* Cl = (z == 0) ? Ql : (z == 1) ? Kl : Vl;
    float sc = (z == 0) ? 0.17677669529663687f : 1.f;
    mma_body(xh, xl, Wh, Wl, bias, nullptr, Ch, Cl, MTOK, D, D, 0, sc,
             blockIdx.x, blockIdx.y);
}

// -------- tensor-core flash attention (bf16x3), q-tile 128, 8 warps ----------
// K/V double-buffered in smem; Q fragments loaded directly from global.
__global__ __launch_bounds__(256, 2)
void attn_mma_kernel()
{
    __shared__ __align__(16) __nv_bfloat16 pool[2][4][64][40];  // 40960 B

    int qt = blockIdx.x;           // 0..8 (128-row q tiles)
    int h  = blockIdx.y;
    int b  = blockIdx.z;
    int tid = threadIdx.x, lane = tid & 31, w = tid >> 5;  // w 0..7
    int g = lane >> 2, t = lane & 3;
    int mw = w * 16;               // 0..112

    size_t hoff = ((size_t)b * SLEN) * D + h * HD;
    const __nv_bfloat16* qhg = g_qh + hoff;
    const __nv_bfloat16* qlg = g_ql + hoff;
    const __nv_bfloat16* khg = g_kh + hoff;
    const __nv_bfloat16* klg = g_kl + hoff;
    const __nv_bfloat16* vhg = g_vh + hoff;
    const __nv_bfloat16* vlg = g_vl + hoff;

    // K/V tile load mapping: 256 threads, 1 16B chunk per array per thread
    int lr = tid >> 2;             // 0..63
    int lc = (tid & 3) * 8;        // 0,8,16,24 (bf16 offset)

#define KSH(buf) (pool[buf][0])
#define KSL(buf) (pool[buf][1])
#define VSH(buf) (pool[buf][2])
#define VSL(buf) (pool[buf][3])

#define AT_ISSUE(buf, kt) do { \
    int _ck = min((kt)*64 + lr, SLEN-1); \
    CPA16(&KSH(buf)[lr][lc], khg + (size_t)_ck*D + lc, 16); \
    CPA16(&KSL(buf)[lr][lc], klg + (size_t)_ck*D + lc, 16); \
    CPA16(&VSH(buf)[lr][lc], vhg + (size_t)_ck*D + lc, 16); \
    CPA16(&VSL(buf)[lr][lc], vlg + (size_t)_ck*D + lc, 16); \
    asm volatile("cp.async.commit_group;"); \
} while (0)

    AT_ISSUE(0, 0);

    // Q fragments (A m16k16) loaded directly from global:
    // frag[ks][0]=(r0, ks*16+2t), [1]=(r0+8, ...), [2]=(r0, +8), [3]=(r0+8, +8)
    uint32_t qfh[2][4], qfl[2][4];
    {
        int r0 = min(qt*128 + mw + g,     SLEN-1);
        int r1 = min(qt*128 + mw + g + 8, SLEN-1);
        const __nv_bfloat16* h0 = qhg + (size_t)r0*D;
        const __nv_bfloat16* h1 = qhg + (size_t)r1*D;
        const __nv_bfloat16* l0 = qlg + (size_t)r0*D;
        const __nv_bfloat16* l1 = qlg + (size_t)r1*D;
        #pragma unroll
        for (int ks = 0; ks < 2; ks++) {
            int c0 = ks*16 + 2*t;
            qfh[ks][0] = *(const uint32_t*)(h0 + c0);
            qfh[ks][1] = *(const uint32_t*)(h1 + c0);
            qfh[ks][2] = *(const uint32_t*)(h0 + c0 + 8);
            qfh[ks][3] = *(const uint32_t*)(h1 + c0 + 8);
            qfl[ks][0] = *(const uint32_t*)(l0 + c0);
            qfl[ks][1] = *(const uint32_t*)(l1 + c0);
            qfl[ks][2] = *(const uint32_t*)(l0 + c0 + 8);
            qfl[ks][3] = *(const uint32_t*)(l1 + c0 + 8);
        }
    }

    float m0 = -INFINITY, m1 = -INFINITY, l0 = 0.f, l1 = 0.f;
    float o[4][4];
    #pragma unroll
    for (int nd = 0; nd < 4; nd++)
        #pragma unroll
        for (int i = 0; i < 4; i++) o[nd][i] = 0.f;

    for (int kt = 0; kt < 17; kt++) {
        int cur = kt & 1;
        int k0 = kt * 64;
        if (kt + 1 < 17) {
            AT_ISSUE(cur ^ 1, kt + 1);
            asm volatile("cp.async.wait_group 1;");
        } else {
            asm volatile("cp.async.wait_group 0;");
        }
        __syncthreads();

        // ---- S = Q K^T (3-term bf16x3) ----
        float s[8][4];
        #pragma unroll
        for (int j = 0; j < 8; j++)
            #pragma unroll
            for (int i = 0; i < 4; i++) s[j][i] = 0.f;

        #pragma unroll
        for (int j = 0; j < 8; j++) {
            uint32_t bh[4], bl[4];
            int rr = j*8 + (lane & 7);
            int cc = ((lane >> 3) & 3) * 8;
            LDSM4(bh[0], bh[1], bh[2], bh[3], sptr(&KSH(cur)[rr][cc]));
            LDSM4(bl[0], bl[1], bl[2], bl[3], sptr(&KSL(cur)[rr][cc]));
            MMA_BF16(s[j], qfh[0], bh);
            MMA_BF16(s[j], qfh[1], bh + 2);
            MMA_BF16(s[j], qfh[0], bl);
            MMA_BF16(s[j], qfh[1], bl + 2);
            MMA_BF16(s[j], qfl[0], bh);
            MMA_BF16(s[j], qfl[1], bh + 2);
        }

        // mask invalid tokens (only last tile)
        if (k0 + 64 > SLEN) {
            #pragma unroll
            for (int j = 0; j < 8; j++) {
                int tok = k0 + j*8 + 2*t;
                if (tok     >= SLEN) { s[j][0] = -1e30f; s[j][2] = -1e30f; }
                if (tok + 1 >= SLEN) { s[j][1] = -1e30f; s[j][3] = -1e30f; }
            }
        }

        // ---- online softmax ----
        float t0v = -INFINITY, t1v = -INFINITY;
        #pragma unroll
        for (int j = 0; j < 8; j++) {
            t0v = fmaxf(t0v, fmaxf(s[j][0], s[j][1]));
            t1v = fmaxf(t1v, fmaxf(s[j][2], s[j][3]));
        }
        t0v = fmaxf(t0v, __shfl_xor_sync(0xffffffffu, t0v, 1));
        t0v = fmaxf(t0v, __shfl_xor_sync(0xffffffffu, t0v, 2));
        t1v = fmaxf(t1v, __shfl_xor_sync(0xffffffffu, t1v, 1));
        t1v = fmaxf(t1v, __shfl_xor_sync(0xffffffffu, t1v, 2));

        float mn0 = fmaxf(m0, t0v), mn1 = fmaxf(m1, t1v);
        float c0 = __expf(m0 - mn0), c1 = __expf(m1 - mn1);
        l0 *= c0; l1 *= c1;
        #pragma unroll
        for (int nd = 0; nd < 4; nd++) {
            o[nd][0] *= c0; o[nd][1] *= c0;
            o[nd][2] *= c1; o[nd][3] *= c1;
        }

        float ls0 = 0.f, ls1 = 0.f;
        #pragma unroll
        for (int j = 0; j < 8; j++) {
            s[j][0] = __expf(s[j][0] - mn0); ls0 += s[j][0];
            s[j][1] = __expf(s[j][1] - mn0); ls0 += s[j][1];
            s[j][2] = __expf(s[j][2] - mn1); ls1 += s[j][2];
            s[j][3] = __expf(s[j][3] - mn1); ls1 += s[j][3];
        }
        l0 += ls0; l1 += ls1;
        m0 = mn0; m1 = mn1;

        // ---- P -> A fragments (hi/lo split, in registers) ----
        uint32_t ph[4][4], pl[4][4];
        #pragma unroll
        for (int c = 0; c < 4; c++) {
            psplit(s[2*c][0],   s[2*c][1],   ph[c][0], pl[c][0]);
            psplit(s[2*c][2],   s[2*c][3],   ph[c][1], pl[c][1]);
            psplit(s[2*c+1][0], s[2*c+1][1], ph[c][2], pl[c][2]);
            psplit(s[2*c+1][2], s[2*c+1][3], ph[c][3], pl[c][3]);
        }

        // ---- O += P V (3-term) ----
        #pragma unroll
        for (int nd = 0; nd < 4; nd++) {
            uint32_t bvh[4][2], bvl[4][2];
            #pragma unroll
            for (int cc = 0; cc < 2; cc++) {
                uint32_t va = sptr(&VSH(cur)[cc*32 + lane][nd*8]);
                uint32_t la = sptr(&VSL(cur)[cc*32 + lane][nd*8]);
                LDSM4T(bvh[2*cc][0], bvh[2*cc][1], bvh[2*cc+1][0], bvh[2*cc+1][1], va);
                LDSM4T(bvl[2*cc][0], bvl[2*cc][1], bvl[2*cc+1][0], bvl[2*cc+1][1], la);
            }
            #pragma unroll
            for (int c = 0; c < 4; c++) {
                MMA_BF16(o[nd], ph[c], bvh[c]);
                MMA_BF16(o[nd], ph[c], bvl[c]);
                MMA_BF16(o[nd], pl[c], bvh[c]);
            }
        }
        __syncthreads();   // reads of 'cur' done before next issue into it
    }
#undef AT_ISSUE
#undef KSH
#undef KSL
#undef VSH
#undef VSL

    // final: reduce l over quad, normalize, write bf16-split output
    l0 += __shfl_xor_sync(0xffffffffu, l0, 1);
    l0 += __shfl_xor_sync(0xffffffffu, l0, 2);
    l1 += __shfl_xor_sync(0xffffffffu, l1, 1);
    l1 += __shfl_xor_sync(0xffffffffu, l1, 2);
    float i0 = 1.f / l0, i1 = 1.f / l1;

    int q0 = qt*128 + mw + g;
    int q1 = q0 + 8;
    int colb = h*HD + 2*t;
    #pragma unroll
    for (int nd = 0; nd < 4; nd++) {
        if (q0 < SLEN) {
            __nv_bfloat162 lo;
            __nv_bfloat162 hi = bsplit2(o[nd][0]*i0, o[nd][1]*i0, &lo);
            size_t off = ((size_t)b*SLEN + q0)*D + colb + nd*8;
            *(__nv_bfloat162*)(g_ah + off) = hi;
            *(__nv_bfloat162*)(g_al + off) = lo;
        }
        if (q1 < SLEN) {
            __nv_bfloat162 lo;
            __nv_bfloat162 hi = bsplit2(o[nd][2]*i1, o[nd][3]*i1, &lo);
            size_t off = ((size_t)b*SLEN + q1)*D + colb + nd*8;
            *(__nv_bfloat162*)(g_ah + off) = hi;
            *(__nv_bfloat162*)(g_al + off) = lo;
        }
    }
}

// ---------- fused residual + LayerNorm, warp-per-row; f32 + bf16-split out ---
__global__ void ln_kernel(const float* __restrict__ A,
                          const float* __restrict__ Bsrc,
                          const float* __restrict__ g,
                          const float* __restrict__ bta,
                          float* __restrict__ out,
                          __nv_bfloat16* __restrict__ oh,
                          __nv_bfloat16* __restrict__ ol)
{
    int warp = threadIdx.x >> 5;
    int lane = threadIdx.x & 31;
    int row = blockIdx.x * 8 + warp;
    size_t base = (size_t)row * D;

    const float4* ap = (const float4*)(A + base);
    const float4* bp = (const float4*)(Bsrc + base);
    float4 a0 = ap[lane], a1 = ap[lane + 32];
    float4 b0 = bp[lane], b1 = bp[lane + 32];
    float v[8];
    v[0]=a0.x+b0.x; v[1]=a0.y+b0.y; v[2]=a0.z+b0.z; v[3]=a0.w+b0.w;
    v[4]=a1.x+b1.x; v[5]=a1.y+b1.y; v[6]=a1.z+b1.z; v[7]=a1.w+b1.w;

    float s = 0.f, s2 = 0.f;
    #pragma unroll
    for (int i = 0; i < 8; i++) { s += v[i]; s2 = fmaf(v[i], v[i], s2); }
    #pragma unroll
    for (int o = 16; o > 0; o >>= 1) {
        s  += __shfl_xor_sync(0xffffffffu, s,  o);
        s2 += __shfl_xor_sync(0xffffffffu, s2, o);
    }
    float mu = s * (1.f/256.f);
    float var = s2 * (1.f/256.f) - mu*mu;
    float rstd = rsqrtf(var + 1e-5f);

    const float4* gp = (const float4*)g;
    const float4* tp = (const float4*)bta;
    float4 g0 = gp[lane], g1 = gp[lane+32];
    float4 t0 = tp[lane], t1 = tp[lane+32];
    float4 o0, o1;
    o0.x = (v[0]-mu)*rstd*g0.x + t0.x;
    o0.y = (v[1]-mu)*rstd*g0.y + t0.y;
    o0.z = (v[2]-mu)*rstd*g0.z + t0.z;
    o0.w = (v[3]-mu)*rstd*g0.w + t0.w;
    o1.x = (v[4]-mu)*rstd*g1.x + t1.x;
    o1.y = (v[5]-mu)*rstd*g1.y + t1.y;
    o1.z = (v[6]-mu)*rstd*g1.z + t1.z;
    o1.w = (v[7]-mu)*rstd*g1.w + t1.w;
    float4* op = (float4*)(out + base);
    op[lane]      = o0;
    op[lane + 32] = o1;

    size_t e0 = base + (size_t)lane*4;
    size_t e1 = base + (size_t)(lane+32)*4;
    __nv_bfloat162 lo, hi;
    hi = bsplit2(o0.x, o0.y, &lo);
    *(__nv_bfloat162*)(oh + e0)     = hi; *(__nv_bfloat162*)(ol + e0)     = lo;
    hi = bsplit2(o0.z, o0.w, &lo);
    *(__nv_bfloat162*)(oh + e0 + 2) = hi; *(__nv_bfloat162*)(ol + e0 + 2) = lo;
    hi = bsplit2(o1.x, o1.y, &lo);
    *(__nv_bfloat162*)(oh + e1)     = hi; *(__nv_bfloat162*)(ol + e1)     = lo;
    hi = bsplit2(o1.z, o1.w, &lo);
    *(__nv_bfloat162*)(oh + e1 + 2) = hi; *(__nv_bfloat162*)(ol + e1 + 2) = lo;
}

// ---------------- final: LN cls row only + 2-layer head ----------------------
__global__ void head_kernel(const float* __restrict__ g,
                            const float* __restrict__ bta,
                            const float* __restrict__ Wh1,
                            const float* __restrict__ bh1,
                            const float* __restrict__ Wh2,
                            const float* __restrict__ bh2,
                            float* __restrict__ out)
{
    int b = blockIdx.x;
    int d = threadIdx.x;
    float v = g_x[(size_t)b*SLEN*D + d];

    float s = v, s2 = v*v;
    #pragma unroll
    for (int o = 16; o > 0; o >>= 1) {
        s  += __shfl_xor_sync(0xffffffffu, s,  o);
        s2 += __shfl_xor_sync(0xffffffffu, s2, o);
    }
    __shared__ float ws[8], ws2[8];
    __shared__ float mu_s, rstd_s;
    int w = d >> 5;
    if ((d & 31) == 0) { ws[w] = s; ws2[w] = s2; }
    __syncthreads();
    if (d == 0) {
        float S1 = 0.f, S2 = 0.f;
        #pragma unroll
        for (int i = 0; i < 8; i++) { S1 += ws[i]; S2 += ws2[i]; }
        float mu = S1 * (1.f/256.f);
        float var = S2 * (1.f/256.f) - mu*mu;
        mu_s = mu;
        rstd_s = rsqrtf(var + 1e-5f);
    }
    __syncthreads();

    __shared__ float clsr[256];
    __shared__ float hid[256];
    float c = (v - mu_s) * rstd_s * g[d] + bta[d];
    clsr[d] = c;
    out[b*D + d] = c;                       // cls_out
    __syncthreads();

    float hsum = bh1[d];
    #pragma unroll 8
    for (int k = 0; k < 256; k++) hsum = fmaf(clsr[k], Wh1[k*256 + d], hsum);
    hid[d] = fmaxf(hsum, 0.f);
    __syncthreads();

    if (d < 2) {
        float lg = bh2[d];
        for (int k = 0; k < 256; k++) lg = fmaf(hid[k], Wh2[k*2 + d], lg);
        out[BB*D + b*2 + d] = lg;           // logits after cls_out block
    }
}

// ---------------- launcher ---------------------------------------------------
extern "C" void kernel_launch(void* const* d_in, const int* in_sizes, int n_in,
                              void* d_out, int out_size)
{
    (void)in_sizes; (void)n_in; (void)out_size;

    const float* cf   = (const float*)d_in[0];
    const int*   xc   = (const int*)  d_in[1];
    const int*   yc   = (const int*)  d_in[2];
    const float* Wemb = (const float*)d_in[3];
    const float* bemb = (const float*)d_in[4];
    const float* Wct1 = (const float*)d_in[5];
    const float* bct1 = (const float*)d_in[6];
    const float* Wct2 = (const float*)d_in[7];
    const float* bct2 = (const float*)d_in[8];
    const float* cls  = (const float*)d_in[9];
    const float* Wq = (const float*)d_in[10]; const float* bq = (const float*)d_in[11];
    const float* Wk = (const float*)d_in[12]; const float* bk = (const float*)d_in[13];
    const float* Wv = (const float*)d_in[14]; const float* bv = (const float*)d_in[15];
    const float* Wo = (const float*)d_in[16]; const float* bo = (const float*)d_in[17];
    const float* ln1g = (const float*)d_in[18]; const float* ln1b = (const float*)d_in[19];
    const float* ln2g = (const float*)d_in[20]; const float* ln2b = (const float*)d_in[21];
    const float* Wf1 = (const float*)d_in[22]; const float* bf1 = (const float*)d_in[23];
    const float* Wf2 = (const float*)d_in[24]; const float* bf2 = (const float*)d_in[25];
    const float* lnfg = (const float*)d_in[26]; const float* lnfb = (const float*)d_in[27];
    const float* Wh1 = (const float*)d_in[28]; const float* bh1 = (const float*)d_in[29];
    const float* Wh2 = (const float*)d_in[30]; const float* bh2 = (const float*)d_in[31];
    float* out = (float*)d_out;

    void* p;
    cudaGetSymbolAddress(&p, g_x);  float* xb = (float*)p;
    cudaGetSymbolAddress(&p, g_t);  float* tb = (float*)p;
    cudaGetSymbolAddress(&p, g_xh); __nv_bfloat16* xh = (__nv_bfloat16*)p;
    cudaGetSymbolAddress(&p, g_xl); __nv_bfloat16* xl = (__nv_bfloat16*)p;
    cudaGetSymbolAddress(&p, g_ah); __nv_bfloat16* ah = (__nv_bfloat16*)p;
    cudaGetSymbolAddress(&p, g_al); __nv_bfloat16* al = (__nv_bfloat16*)p;
    cudaGetSymbolAddress(&p, g_hh); __nv_bfloat16* hh = (__nv_bfloat16*)p;
    cudaGetSymbolAddress(&p, g_hl); __nv_bfloat16* hl = (__nv_bfloat16*)p;
    cudaGetSymbolAddress(&p, g_qh); __nv_bfloat16* qh = (__nv_bfloat16*)p;
    cudaGetSymbolAddress(&p, g_ql); __nv_bfloat16* ql = (__nv_bfloat16*)p;
    cudaGetSymbolAddress(&p, g_kh); __nv_bfloat16* kh = (__nv_bfloat16*)p;
    cudaGetSymbolAddress(&p, g_kl); __nv_bfloat16* kl = (__nv_bfloat16*)p;
    cudaGetSymbolAddress(&p, g_vh); __nv_bfloat16* vh = (__nv_bfloat16*)p;
    cudaGetSymbolAddress(&p, g_vl); __nv_bfloat16* vl = (__nv_bfloat16*)p;
    cudaGetSymbolAddress(&p, g_wth); __nv_bfloat16* wth = (__nv_bfloat16*)p;
    cudaGetSymbolAddress(&p, g_wtl); __nv_bfloat16* wtl = (__nv_bfloat16*)p;

    // upfront: weight split + transpose (all layers)
    {
        dim3 gdd((D*D)/256, NL);
        wconv_kernel<<<gdd, 256>>>(Wq, wth + 0,       wtl + 0,       D, D, D*D, 3*D*D);
        wconv_kernel<<<gdd, 256>>>(Wk, wth + D*D,     wtl + D*D,     D, D, D*D, 3*D*D);
        wconv_kernel<<<gdd, 256>>>(Wv, wth + 2*D*D,   wtl + 2*D*D,   D, D, D*D, 3*D*D);
        wconv_kernel<<<gdd, 256>>>(Wo, wth + WOFF_WO, wtl + WOFF_WO, D, D, D*D, D*D);
        dim3 gdf((D*DFF)/256, NL);
        wconv_kernel<<<gdf, 256>>>(Wf1, wth + WOFF_F1, wtl + WOFF_F1, D, DFF, D*DFF, D*DFF);
        wconv_kernel<<<gdf, 256>>>(Wf2, wth + WOFF_F2, wtl + WOFF_F2, DFF, D, D*DFF, D*DFF);
    }

    embed_kernel<<<MTOK, 256>>>(cf, xc, yc, Wemb, bemb, Wct1, bct1, Wct2, bct2, cls);

    int MB = (MTOK + 63) / 64;             // 129
    dim3 gqkv(MB, D/64, 3);                // 129 x 4 x 3
    dim3 gdd2(MB, D/64);                   // 129 x 4
    dim3 gff (MB, DFF/64);                 // 129 x 16
    dim3 gattn((SLEN + 127)/128, NH, BB);  // 9 x 8 x 8
    int lngrid = MTOK / 8;                 // 1025

    for (int l = 0; l < NL; l++) {
        qkv_mma<<<gqkv, 128>>>(xh, xl,
                               wth + (size_t)l*3*D*D, wtl + (size_t)l*3*D*D,
                               bq + l*D, bk + l*D, bv + l*D,
                               qh, ql, kh, kl, vh, vl);
        attn_mma_kernel<<<gattn, 256>>>();
        mma_gemm<<<gdd2, 128>>>(ah, al,
                                wth + WOFF_WO + (size_t)l*D*D,
                                wtl + WOFF_WO + (size_t)l*D*D,
                                bo + l*D, tb, nullptr, nullptr, MTOK, D, D, 0);
        ln_kernel<<<lngrid, 256>>>(xb, tb, ln1g + l*D, ln1b + l*D, xb, xh, xl);
        mma_gemm<<<gff, 128>>>(xh, xl,
                               wth + WOFF_F1 + (size_t)l*D*DFF,
                               wtl + WOFF_F1 + (size_t)l*D*DFF,
                               bf1 + l*DFF, nullptr, hh, hl, MTOK, DFF, D, 1);
        mma_gemm<<<gdd2, 128>>>(hh, hl,
                                wth + WOFF_F2 + (size_t)l*D*DFF,
                                wtl + WOFF_F2 + (size_t)l*D*DFF,
                                bf2 + l*D, tb, nullptr, nullptr, MTOK, D, DFF, 0);
        ln_kernel<<<lngrid, 256>>>(xb, tb, ln2g + l*D, ln2b + l*D, xb, xh, xl);
    }

    head_kernel<<<BB, 256>>>(lnfg, lnfb, Wh1, bh1, Wh2, bh2, out);
}